// round 4
// baseline (speedup 1.0000x reference)
#include <cuda_runtime.h>
#include <cuda_bf16.h>
#include <cstdint>
#include <cstddef>

// Problem constants
#define Bb 8
#define Ss 1024
#define Hh 256
#define LL 7
#define BSR (Bb*Ss)        // 8192 rows
#define H7 (7*Hh)          // 1792
#define H3 (3*Hh)          // 768
#define NCH 16
#define SCH (Ss/NCH)

// ---------------- scratch (device globals; no allocations allowed) ----------
__device__ float d_hbuf0[BSR*Hh];
__device__ float d_hbuf1[BSR*Hh];
__device__ float d_cbuf0[BSR*Hh];
__device__ float d_cbuf1[BSR*Hh];
__device__ float d_proj[(size_t)BSR*H7];
__device__ float d_zbuf[(size_t)BSR*H7];
__device__ float d_ph[BSR*Hh];
__device__ float d_pihg[Bb*Hh];
__device__ float d_igb[Bb*Hh];
__device__ float d_ogb[Bb*Hh];
__device__ float d_gh[Bb*Hh];
__device__ float d_gcv[Bb*Hh];
__device__ float d_havg[Bb*Hh];
__device__ float d_gWg[Bb*H7];
__device__ float d_pnum[Bb*NCH*Hh];
__device__ float d_pden[Bb*NCH*Hh];
__device__ float d_invms[Bb];
// split-bf16 activations / weights (16B aligned for uint4 / cp.async)
__device__ __align__(16) __nv_bfloat16 d_h_hi0[BSR*Hh];
__device__ __align__(16) __nv_bfloat16 d_h_lo0[BSR*Hh];
__device__ __align__(16) __nv_bfloat16 d_h_hi1[BSR*Hh];
__device__ __align__(16) __nv_bfloat16 d_h_lo1[BSR*Hh];
__device__ __align__(16) __nv_bfloat16 d_in_hi[BSR*Hh];
__device__ __align__(16) __nv_bfloat16 d_in_lo[BSR*Hh];
__device__ __align__(16) __nv_bfloat16 d_W3T_hi[H7*H3];
__device__ __align__(16) __nv_bfloat16 d_W3T_lo[H7*H3];
__device__ __align__(16) __nv_bfloat16 d_GhT_hi[Hh*Hh];
__device__ __align__(16) __nv_bfloat16 d_GhT_lo[Hh*Hh];
__device__ __align__(16) __nv_bfloat16 d_WiT_hi[H7*Hh];
__device__ __align__(16) __nv_bfloat16 d_WiT_lo[H7*Hh];

// ---------------- PTX helpers -----------------------------------------------
__device__ __forceinline__ uint32_t smem_u32(const void* p) {
    uint32_t a;
    asm("{ .reg .u64 t; cvta.to.shared.u64 t, %1; cvt.u32.u64 %0, t; }"
        : "=r"(a) : "l"(p));
    return a;
}
__device__ __forceinline__ void cpasync16(uint32_t dst, const void* src) {
    asm volatile("cp.async.cg.shared.global [%0], [%1], 16;" :: "r"(dst), "l"(src));
}
__device__ __forceinline__ void cpasync16z(uint32_t dst, const void* src, int nbytes) {
    asm volatile("cp.async.cg.shared.global [%0], [%1], 16, %2;"
                 :: "r"(dst), "l"(src), "r"(nbytes));
}
#define CP_COMMIT() asm volatile("cp.async.commit_group;" ::: "memory")
#define CP_WAIT1()  asm volatile("cp.async.wait_group 1;" ::: "memory")
#define CP_WAIT0()  asm volatile("cp.async.wait_group 0;" ::: "memory")

__device__ __forceinline__ void mma16816(float* c, const uint32_t* a, const uint32_t* b) {
    asm volatile(
        "mma.sync.aligned.m16n8k16.row.col.f32.bf16.bf16.f32 "
        "{%0,%1,%2,%3}, {%4,%5,%6,%7}, {%8,%9}, {%0,%1,%2,%3};"
        : "+f"(c[0]), "+f"(c[1]), "+f"(c[2]), "+f"(c[3])
        : "r"(a[0]), "r"(a[1]), "r"(a[2]), "r"(a[3]), "r"(b[0]), "r"(b[1]));
}
__device__ __forceinline__ void ldsm4(uint32_t& r0, uint32_t& r1, uint32_t& r2,
                                      uint32_t& r3, uint32_t addr) {
    asm volatile("ldmatrix.sync.aligned.m8n8.x4.shared.b16 {%0,%1,%2,%3}, [%4];"
                 : "=r"(r0), "=r"(r1), "=r"(r2), "=r"(r3) : "r"(addr));
}

// ---------------- bf16x3 HMMA GEMM -------------------------------------------
// C[M,N] = (Ahi+Alo)[M,K] @ (Bhi+Blo)^T  with B stored [N,K] K-major.
// ctxmode: A operands are hidden [BSR x Hh]; logical A row bs, K index k maps to
// hidden[bs + k/256 - 1] (zero at sequence boundaries). K must be 768 then.
#define KB 32
#define SA 40                      // padded smem row stride (halves)
#define MTILE (128*SA)
#define STAGE (4*MTILE)            // Ahi, Alo, Bhi, Blo
#define HSMEM (2*STAGE*2)          // 81920 bytes

__device__ __forceinline__ void load_tiles(
    uint32_t smbase, int st, int k0, int tid, int K, int ctxmode, int arow0,
    const __nv_bfloat16* __restrict__ Ahi, const __nv_bfloat16* __restrict__ Alo,
    const __nv_bfloat16* __restrict__ Bhi_off, const __nv_bfloat16* __restrict__ Blo_off)
{
    #pragma unroll
    for (int t = 0; t < 4; t++) {
        uint32_t dstbase = smbase + (st * STAGE + t * MTILE) * 2;
        #pragma unroll
        for (int s = 0; s < 2; s++) {
            int slot = tid + s * 256;
            int row = slot >> 2, cg = (slot & 3) * 8;
            uint32_t dst = dstbase + (row * SA + cg) * 2;
            if (t >= 2) {
                const __nv_bfloat16* src = (t == 2) ? Bhi_off : Blo_off;
                cpasync16(dst, src + (size_t)row * K + k0 + cg);
            } else if (!ctxmode) {
                const __nv_bfloat16* src = (t == 0) ? Ahi : Alo;
                cpasync16(dst, src + (size_t)(arow0 + row) * K + k0 + cg);
            } else {
                int bs = arow0 + row;
                int sq = bs & (Ss - 1);
                int k = k0 + cg;
                int seg = k >> 8, off = k & 255;
                int srcrow = bs + seg - 1;
                bool pred = (seg == 1) || ((seg == 0) ? (sq > 0) : (sq < Ss - 1));
                if (!pred) srcrow = bs;
                const __nv_bfloat16* src = (t == 0) ? Ahi : Alo;
                cpasync16z(dst, src + (size_t)srcrow * Hh + off, pred ? 16 : 0);
            }
        }
    }
}

__global__ void __launch_bounds__(256, 1) k_hmma(
    int M, int N, int K, int ctxmode,
    const __nv_bfloat16* __restrict__ Ahi, const __nv_bfloat16* __restrict__ Alo,
    const __nv_bfloat16* __restrict__ Bhi, const __nv_bfloat16* __restrict__ Blo,
    const float* __restrict__ bias, const float* __restrict__ add,
    const float* __restrict__ addrow, float* __restrict__ C)
{
    extern __shared__ __nv_bfloat16 sm[];
    int tid = threadIdx.x, wid = tid >> 5, lane = tid & 31;
    int gID = lane >> 2, tg = lane & 3;
    int warp_m = wid >> 2, warp_n = wid & 3;
    int arow0 = blockIdx.y * 128, bcol0 = blockIdx.x * 128;
    const __nv_bfloat16* Bhi_off = Bhi + (size_t)bcol0 * K;
    const __nv_bfloat16* Blo_off = Blo + (size_t)bcol0 * K;

    float acc[4][4][4];
    #pragma unroll
    for (int mi = 0; mi < 4; mi++)
        #pragma unroll
        for (int ni = 0; ni < 4; ni++)
            #pragma unroll
            for (int q = 0; q < 4; q++) acc[mi][ni][q] = 0.f;

    uint32_t smbase = smem_u32(sm);
    int niter = K / KB;

    // ldmatrix per-lane address deltas (bytes)
    int mat = lane >> 3, lr = lane & 7;
    int a_off = (((mat & 1) * 8 + lr) * SA + (mat >> 1) * 8) * 2;
    int b_off = (((mat >> 1) * 8 + lr) * SA + (mat & 1) * 8) * 2;

    load_tiles(smbase, 0, 0, tid, K, ctxmode, arow0, Ahi, Alo, Bhi_off, Blo_off);
    CP_COMMIT();

    for (int it = 0; it < niter; it++) {
        if (it + 1 < niter) {
            load_tiles(smbase, (it + 1) & 1, (it + 1) * KB, tid, K, ctxmode, arow0,
                       Ahi, Alo, Bhi_off, Blo_off);
            CP_COMMIT();
            CP_WAIT1();
        } else {
            CP_WAIT0();
        }
        __syncthreads();

        uint32_t Ab = smbase + ((it & 1) * STAGE) * 2;
        uint32_t Al = Ab + MTILE * 2;
        uint32_t Bh = Ab + 2 * MTILE * 2;
        uint32_t Bl = Ab + 3 * MTILE * 2;

        #pragma unroll
        for (int kk = 0; kk < KB; kk += 16) {
            uint32_t bh[4][2], bl[4][2];
            #pragma unroll
            for (int np = 0; np < 2; np++) {
                int n0 = warp_n * 32 + np * 16;
                uint32_t base = (n0 * SA + kk) * 2 + b_off;
                ldsm4(bh[np*2][0], bh[np*2][1], bh[np*2+1][0], bh[np*2+1][1], Bh + base);
                ldsm4(bl[np*2][0], bl[np*2][1], bl[np*2+1][0], bl[np*2+1][1], Bl + base);
            }
            #pragma unroll
            for (int mi = 0; mi < 4; mi++) {
                int r0 = warp_m * 64 + mi * 16;
                uint32_t abase = (r0 * SA + kk) * 2 + a_off;
                uint32_t ah[4], al[4];
                ldsm4(ah[0], ah[1], ah[2], ah[3], Ab + abase);
                ldsm4(al[0], al[1], al[2], al[3], Al + abase);
                #pragma unroll
                for (int ni = 0; ni < 4; ni++) {
                    mma16816(acc[mi][ni], ah, bh[ni]);
                    mma16816(acc[mi][ni], ah, bl[ni]);
                    mma16816(acc[mi][ni], al, bh[ni]);
                }
            }
        }
        __syncthreads();
    }

    // epilogue: C = acc (+bias) (+add[r,c]) (+addrow[b,c])
    #pragma unroll
    for (int mi = 0; mi < 4; mi++) {
        #pragma unroll
        for (int ni = 0; ni < 4; ni++) {
            int r = arow0 + warp_m * 64 + mi * 16 + gID;
            int c = bcol0 + warp_n * 32 + ni * 8 + tg * 2;
            float b0 = 0.f, b1 = 0.f;
            if (bias) { b0 = bias[c]; b1 = bias[c + 1]; }
            if (addrow) {
                size_t ro = (size_t)(r >> 10) * N + c;
                b0 += addrow[ro]; b1 += addrow[ro + 1];
            }
            float2 v0 = make_float2(acc[mi][ni][0] + b0, acc[mi][ni][1] + b1);
            float2 v1 = make_float2(acc[mi][ni][2] + b0, acc[mi][ni][3] + b1);
            if (add) {
                float2 a0 = *(const float2*)(add + (size_t)r * N + c);
                float2 a1 = *(const float2*)(add + (size_t)(r + 8) * N + c);
                v0.x += a0.x; v0.y += a0.y; v1.x += a1.x; v1.y += a1.y;
            }
            *(float2*)(C + (size_t)r * N + c) = v0;
            *(float2*)(C + (size_t)(r + 8) * N + c) = v1;
        }
    }
}

// ---------------- helpers ----------------------------------------------------
__device__ __forceinline__ float2 blockSum2(float a, float b, float* sh) {
    #pragma unroll
    for (int o = 16; o > 0; o >>= 1) {
        a += __shfl_down_sync(0xffffffffu, a, o);
        b += __shfl_down_sync(0xffffffffu, b, o);
    }
    int w = threadIdx.x >> 5, l = threadIdx.x & 31;
    if (l == 0) { sh[w] = a; sh[8 + w] = b; }
    __syncthreads();
    if (threadIdx.x == 0) {
        float sa = 0.f, sb2 = 0.f;
        #pragma unroll
        for (int i = 0; i < 8; i++) { sa += sh[i]; sb2 += sh[8 + i]; }
        sh[16] = sa; sh[17] = sb2;
    }
    __syncthreads();
    float2 r = make_float2(sh[16], sh[17]);
    __syncthreads();
    return r;
}
__device__ __forceinline__ float sigmoidf_(float x) { return 1.f / (1.f + expf(-x)); }
__device__ __forceinline__ void splitbf(float v, __nv_bfloat16& hi, __nv_bfloat16& lo) {
    hi = __float2bfloat16(v);
    lo = __float2bfloat16(v - __bfloat162float(hi));
}

// ---------------- split / transpose kernels ----------------------------------
__global__ void k_split(const float* __restrict__ x, __nv_bfloat16* __restrict__ hi,
                        __nv_bfloat16* __restrict__ lo, int n)
{
    int i = blockIdx.x * blockDim.x + threadIdx.x;
    if (i >= n) return;
    splitbf(x[i], hi[i], lo[i]);
}

__global__ void k_w3t(const float* __restrict__ Wc, const float* __restrict__ Wh,
                      __nv_bfloat16* __restrict__ hi, __nv_bfloat16* __restrict__ lo)
{
    int i = blockIdx.x * blockDim.x + threadIdx.x;   // [H7 x H3]
    if (i >= H7 * H3) return;
    int n = i / H3, k = i % H3;
    float v = (k < Hh) ? Wc[(size_t)k * H7 + n]
            : (k < 2 * Hh) ? Wh[(size_t)(k - Hh) * H7 + n]
            : Wc[(size_t)(k - Hh) * H7 + n];
    splitbf(v, hi[i], lo[i]);
}

__global__ void k_wt(const float* __restrict__ W, int K, int N,
                     __nv_bfloat16* __restrict__ hi, __nv_bfloat16* __restrict__ lo)
{
    int i = blockIdx.x * blockDim.x + threadIdx.x;   // [N x K]
    if (i >= N * K) return;
    int n = i / K, k = i % K;
    splitbf(W[(size_t)k * N + n], hi[i], lo[i]);
}

// ---------------- small kernels ----------------------------------------------
__global__ void k_invms(const float* __restrict__ mask, float* __restrict__ invms)
{
    __shared__ float sh[8];
    int b = blockIdx.x, t = threadIdx.x;
    float a = 0.f;
    for (int s = t; s < Ss; s += 256) a += mask[b * Ss + s];
    #pragma unroll
    for (int o = 16; o > 0; o >>= 1) a += __shfl_down_sync(0xffffffffu, a, o);
    if ((t & 31) == 0) sh[t >> 5] = a;
    __syncthreads();
    if (t == 0) {
        float s2 = 0.f;
        #pragma unroll
        for (int i = 0; i < 8; i++) s2 += sh[i];
        invms[b] = 1.f / s2;
    }
}

__global__ void k_meanp(const float* __restrict__ x, const float* __restrict__ mask,
                        float* __restrict__ pnum)
{
    int ch = blockIdx.x, b = blockIdx.y, h = threadIdx.x;
    float acc = 0.f;
    int s0 = ch * SCH;
    #pragma unroll 8
    for (int i = 0; i < SCH; i++) {
        int s = s0 + i;
        acc += x[((size_t)(b * Ss + s)) * Hh + h] * mask[b * Ss + s];
    }
    pnum[(b * NCH + ch) * Hh + h] = acc;
}

__global__ void k_meanf(const float* __restrict__ pnum, const float* __restrict__ invms,
                        float* __restrict__ out)
{
    int b = blockIdx.x, h = threadIdx.x;
    float a = 0.f;
    #pragma unroll
    for (int c = 0; c < NCH; c++) a += pnum[(b * NCH + c) * Hh + h];
    out[b * Hh + h] = a * invms[b];
}

// fused: pi = gh@Gi + gb, pa = havg@Ga, then ig/og LayerNorm+sigmoid; writes pihg
__global__ void k_globalA(const float* __restrict__ gh, const float* __restrict__ havg,
                          const float* __restrict__ Gi, const float* __restrict__ gb,
                          const float* __restrict__ Ga,
                          const float* __restrict__ lns, const float* __restrict__ lnb,
                          float* __restrict__ ig, float* __restrict__ og,
                          float* __restrict__ pihg)
{
    __shared__ float sgh[Hh], sha[Hh], sh[18];
    int b = blockIdx.x, h = threadIdx.x;
    sgh[h] = gh[b * Hh + h];
    sha[h] = havg[b * Hh + h];
    __syncthreads();
    float a0 = 0.f, a1 = 0.f, a2 = 0.f, a3 = 0.f, a4 = 0.f;
    #pragma unroll 4
    for (int k = 0; k < Hh; k++) {
        float g = sgh[k], a = sha[k];
        a0 += g * Gi[(size_t)k * H3 + h];
        a1 += g * Gi[(size_t)k * H3 + Hh + h];
        a2 += g * Gi[(size_t)k * H3 + 2 * Hh + h];
        a3 += a * Ga[(size_t)k * 2 * Hh + h];
        a4 += a * Ga[(size_t)k * 2 * Hh + Hh + h];
    }
    float pi0 = a0 + gb[h];
    float pi1 = a1 + gb[Hh + h];
    float pi2 = a2 + gb[2 * Hh + h];
    pihg[b * Hh + h] = pi1;
    float v = pi0 + a3;
    float2 s2 = blockSum2(v, v * v, sh);
    float m = s2.x * (1.f / 256.f);
    float var = (s2.y - 256.f * m * m) * (1.f / 255.f);
    ig[b * Hh + h] = sigmoidf_(lns[h] * (v - m) * rsqrtf(var + 1e-6f) + lnb[h]);
    v = pi2 + a4;
    s2 = blockSum2(v, v * v, sh);
    m = s2.x * (1.f / 256.f);
    var = (s2.y - 256.f * m * m) * (1.f / 255.f);
    og[b * Hh + h] = sigmoidf_(lns[2 * Hh + h] * (v - m) * rsqrtf(var + 1e-6f) + lnb[2 * Hh + h]);
}

__global__ void k_hg(const float* __restrict__ ph, const float* __restrict__ pihg,
                     const float* __restrict__ mask,
                     const float* __restrict__ lns, const float* __restrict__ lnb,
                     float* __restrict__ hg)
{
    __shared__ float sh[18];
    int bs = blockIdx.x; int b = bs >> 10;
    int h = threadIdx.x;
    float v = ph[(size_t)bs * Hh + h] + pihg[b * Hh + h];
    float2 ssum = blockSum2(v, v * v, sh);
    float m = ssum.x * (1.f / 256.f);
    float var = (ssum.y - 256.f * m * m) * (1.f / 255.f);
    float zn = lns[Hh + h] * (v - m) * rsqrtf(var + 1e-6f) + lnb[Hh + h];
    hg[(size_t)bs * Hh + h] = sigmoidf_(zn) + (mask[bs] * 1e25f - 1e25f);
}

__global__ void k_gcp(const float* __restrict__ hg, const float* __restrict__ cell,
                      float* __restrict__ pnum, float* __restrict__ pden)
{
    int ch = blockIdx.x, b = blockIdx.y, h = threadIdx.x;
    float num = 0.f, den = 0.f;
    int s0 = ch * SCH;
    #pragma unroll 4
    for (int i = 0; i < SCH; i++) {
        size_t idx = ((size_t)(b * Ss + s0 + i)) * Hh + h;
        float e = expf(hg[idx]);
        num += e * cell[idx];
        den += e;
    }
    pnum[(b * NCH + ch) * Hh + h] = num;
    pden[(b * NCH + ch) * Hh + h] = den;
}

// fused: finish g_c/g_h softmax combine, then gWg = gh @ Wg
__global__ void k_gcfWg(const float* __restrict__ pnum, const float* __restrict__ pden,
                        const float* __restrict__ ig, const float* __restrict__ og,
                        const float* __restrict__ Wg,
                        float* __restrict__ gc, float* __restrict__ gh,
                        float* __restrict__ gWg)
{
    __shared__ float sgh[Hh];
    int b = blockIdx.x, h = threadIdx.x;
    float num = 0.f, den = 0.f;
    #pragma unroll
    for (int c = 0; c < NCH; c++) {
        num += pnum[(b * NCH + c) * Hh + h];
        den += pden[(b * NCH + c) * Hh + h];
    }
    float ei = expf(ig[b * Hh + h]);
    float g = (gc[b * Hh + h] * ei + num) / (ei + den);
    gc[b * Hh + h] = g;
    float ghv = og[b * Hh + h] * tanhf(g);
    gh[b * Hh + h] = ghv;
    sgh[h] = ghv;
    __syncthreads();
    #pragma unroll
    for (int j = 0; j < 7; j++) {
        float acc = 0.f;
        #pragma unroll 4
        for (int k = 0; k < Hh; k++)
            acc += sgh[k] * Wg[(size_t)k * H7 + j * Hh + h];
        gWg[(size_t)b * H7 + j * Hh + h] = acc;
    }
}

__global__ __launch_bounds__(256) void k_update(
    const float* __restrict__ z, const float* __restrict__ gc,
    const float* __restrict__ mask,
    const float* __restrict__ lns, const float* __restrict__ lnb,
    const float* __restrict__ c_old,
    float* __restrict__ h_new, float* __restrict__ c_new,
    __nv_bfloat16* __restrict__ hhi, __nv_bfloat16* __restrict__ hlo)
{
    __shared__ float sh[18];
    int bs = blockIdx.x; int b = bs >> 10; int s = bs & (Ss - 1);
    int h = threadIdx.x;
    size_t rz = (size_t)bs * H7;
    float zn[7];
    #pragma unroll
    for (int k = 0; k < 7; k++) {
        float v = z[rz + k * Hh + h];
        float2 ssum = blockSum2(v, v * v, sh);
        float m = ssum.x * (1.f / 256.f);
        float var = (ssum.y - 256.f * m * m) * (1.f / 255.f);
        zn[k] = lns[(3 + k) * Hh + h] * (v - m) * rsqrtf(var + 1e-6f) + lnb[(3 + k) * Hh + h];
    }
    float e[6], den = 0.f;
    #pragma unroll
    for (int k = 0; k < 6; k++) {
        e[k] = expf(sigmoidf_(zn[k]));
        den += e[k];
    }
    float inv = 1.f / den;
    float mem = tanhf(zn[6]);
    size_t idx = (size_t)bs * Hh + h;
    float c  = c_old[idx];
    float cl = (s > 0)      ? c_old[idx - Hh] : 0.f;
    float cr = (s < Ss - 1) ? c_old[idx + Hh] : 0.f;
    float cn = (e[1] * cl + e[2] * cr + e[3] * c + e[0] * mem + e[4] * gc[b * Hh + h]) * inv;
    float mk = mask[bs];
    float hv = e[5] * inv * tanhf(cn) * mk;
    h_new[idx] = hv;
    c_new[idx] = cn * mk;
    splitbf(hv, hhi[idx], hlo[idx]);
}

// ---------------- orchestration ----------------------------------------------
extern "C" void kernel_launch(void* const* d_in, const int* in_sizes, int n_in,
                              void* d_out, int out_size)
{
    (void)in_sizes; (void)n_in; (void)out_size;
    const float* inputs = (const float*)d_in[0];
    const float* mask   = (const float*)d_in[1];
    const float* ih     = (const float*)d_in[2];
    const float* ic     = (const float*)d_in[3];
    const float* Wc     = (const float*)d_in[4];
    const float* Wh     = (const float*)d_in[5];
    const float* Wi     = (const float*)d_in[6];
    const float* bi     = (const float*)d_in[7];
    const float* Wg     = (const float*)d_in[8];
    const float* Gi     = (const float*)d_in[9];
    const float* gb     = (const float*)d_in[10];
    const float* Gh     = (const float*)d_in[11];
    const float* Ga     = (const float*)d_in[12];
    const float* lns    = (const float*)d_in[13];
    const float* lnb    = (const float*)d_in[14];
    float* out = (float*)d_out;

    float *hb0, *hb1, *cb0, *cb1, *proj, *zb, *ph;
    float *pihg, *ig, *og, *gh, *gc, *havg, *gWg, *pnum, *pden, *invms;
    __nv_bfloat16 *hh0, *hl0, *hh1, *hl1, *inh, *inl;
    __nv_bfloat16 *w3h, *w3l, *ghh, *ghl, *wih, *wil;
    cudaGetSymbolAddress((void**)&hb0,  d_hbuf0);
    cudaGetSymbolAddress((void**)&hb1,  d_hbuf1);
    cudaGetSymbolAddress((void**)&cb0,  d_cbuf0);
    cudaGetSymbolAddress((void**)&cb1,  d_cbuf1);
    cudaGetSymbolAddress((void**)&proj, d_proj);
    cudaGetSymbolAddress((void**)&zb,   d_zbuf);
    cudaGetSymbolAddress((void**)&ph,   d_ph);
    cudaGetSymbolAddress((void**)&pihg, d_pihg);
    cudaGetSymbolAddress((void**)&ig,   d_igb);
    cudaGetSymbolAddress((void**)&og,   d_ogb);
    cudaGetSymbolAddress((void**)&gh,   d_gh);
    cudaGetSymbolAddress((void**)&gc,   d_gcv);
    cudaGetSymbolAddress((void**)&havg, d_havg);
    cudaGetSymbolAddress((void**)&gWg,  d_gWg);
    cudaGetSymbolAddress((void**)&pnum, d_pnum);
    cudaGetSymbolAddress((void**)&pden, d_pden);
    cudaGetSymbolAddress((void**)&invms, d_invms);
    cudaGetSymbolAddress((void**)&hh0, d_h_hi0);
    cudaGetSymbolAddress((void**)&hl0, d_h_lo0);
    cudaGetSymbolAddress((void**)&hh1, d_h_hi1);
    cudaGetSymbolAddress((void**)&hl1, d_h_lo1);
    cudaGetSymbolAddress((void**)&inh, d_in_hi);
    cudaGetSymbolAddress((void**)&inl, d_in_lo);
    cudaGetSymbolAddress((void**)&w3h, d_W3T_hi);
    cudaGetSymbolAddress((void**)&w3l, d_W3T_lo);
    cudaGetSymbolAddress((void**)&ghh, d_GhT_hi);
    cudaGetSymbolAddress((void**)&ghl, d_GhT_lo);
    cudaGetSymbolAddress((void**)&wih, d_WiT_hi);
    cudaGetSymbolAddress((void**)&wil, d_WiT_lo);

    cudaFuncSetAttribute(k_hmma, cudaFuncAttributeMaxDynamicSharedMemorySize, HSMEM);

    // layer-invariant precompute
    k_invms<<<Bb, 256>>>(mask, invms);
    k_meanp<<<dim3(NCH, Bb), 256>>>(ih, mask, pnum);
    k_meanf<<<Bb, 256>>>(pnum, invms, gh);
    k_meanp<<<dim3(NCH, Bb), 256>>>(ic, mask, pnum);
    k_meanf<<<Bb, 256>>>(pnum, invms, gc);
    k_w3t<<<(H7 * H3 + 255) / 256, 256>>>(Wc, Wh, w3h, w3l);
    k_wt<<<(Hh * Hh + 255) / 256, 256>>>(Gh, Hh, Hh, ghh, ghl);
    k_wt<<<(H7 * Hh + 255) / 256, 256>>>(Wi, Hh, H7, wih, wil);
    k_split<<<(BSR * Hh + 255) / 256, 256>>>(ih, hh0, hl0, BSR * Hh);
    k_split<<<(BSR * Hh + 255) / 256, 256>>>(inputs, inh, inl, BSR * Hh);
    k_hmma<<<dim3(H7 / 128, BSR / 128), 256, HSMEM>>>(
        BSR, H7, Hh, 0, inh, inl, wih, wil, bi,
        (const float*)nullptr, (const float*)nullptr, proj);

    float* hbufs[2] = { hb0, hb1 };
    float* cbufs[2] = { cb0, cb1 };
    __nv_bfloat16* hhis[2] = { hh0, hh1 };
    __nv_bfloat16* hlos[2] = { hl0, hl1 };

    for (int l = 0; l < LL; l++) {
        const float* hid = (l == 0) ? ih : hbufs[l & 1];
        const float* cel = (l == 0) ? ic : cbufs[l & 1];
        const __nv_bfloat16* hhi = hhis[l & 1];
        const __nv_bfloat16* hlo = hlos[l & 1];
        float* hout = (l == LL - 1) ? out : hbufs[(l + 1) & 1];
        float* cout = cbufs[(l + 1) & 1];

        // ---- global state ----
        k_meanp<<<dim3(NCH, Bb), 256>>>(hid, mask, pnum);
        k_meanf<<<Bb, 256>>>(pnum, invms, havg);
        k_globalA<<<Bb, 256>>>(gh, havg, Gi, gb, Ga, lns, lnb, ig, og, pihg);
        k_hmma<<<dim3(Hh / 128, BSR / 128), 256, HSMEM>>>(
            BSR, Hh, Hh, 0, hhi, hlo, ghh, ghl,
            (const float*)nullptr, (const float*)nullptr, (const float*)nullptr, ph);
        k_hg<<<BSR, 256>>>(ph, pihg, mask, lns, lnb, ph);
        k_gcp<<<dim3(NCH, Bb), 256>>>(ph, cel, pnum, pden);
        k_gcfWg<<<Bb, 256>>>(pnum, pden, ig, og, Wg, gc, gh, gWg);

        // ---- per-word state: z = ctx@W3 (+proj +gWg), then update ----
        k_hmma<<<dim3(H7 / 128, BSR / 128), 256, HSMEM>>>(
            BSR, H7, H3, 1, hhi, hlo, w3h, w3l,
            (const float*)nullptr, proj, gWg, zb);
        k_update<<<BSR, 256>>>(zb, gc, mask, lns, lnb, cel, hout, cout,
                               hhis[(l + 1) & 1], hlos[(l + 1) & 1]);
    }
}

// round 5
// speedup vs baseline: 1.0046x; 1.0046x over previous
#include <cuda_runtime.h>
#include <cuda_bf16.h>
#include <cstdint>
#include <cstddef>

// Problem constants
#define Bb 8
#define Ss 1024
#define Hh 256
#define LL 7
#define BSR (Bb*Ss)        // 8192 rows
#define H7 (7*Hh)          // 1792
#define H3 (3*Hh)          // 768
#define NCH 16
#define SCH (Ss/NCH)

// ---------------- scratch (device globals; no allocations allowed) ----------
__device__ float d_hbuf0[BSR*Hh];
__device__ float d_hbuf1[BSR*Hh];
__device__ float d_cbuf0[BSR*Hh];
__device__ float d_cbuf1[BSR*Hh];
__device__ float d_proj[(size_t)BSR*H7];
__device__ float d_zbuf[(size_t)BSR*H7];
__device__ float d_ph[BSR*Hh];
__device__ float d_pihg[Bb*Hh];
__device__ float d_igb[Bb*Hh];
__device__ float d_ogb[Bb*Hh];
__device__ float d_gh[Bb*Hh];
__device__ float d_gcv[Bb*Hh];
__device__ float d_havg[Bb*Hh];
__device__ float d_gWg[Bb*H7];
__device__ float d_pnum[Bb*NCH*Hh];
__device__ float d_pden[Bb*NCH*Hh];
__device__ float d_invms[Bb];
// split-bf16 activations / weights (16B aligned for uint4 / cp.async)
__device__ __align__(16) __nv_bfloat16 d_ctx_hi[(size_t)BSR*H3];
__device__ __align__(16) __nv_bfloat16 d_ctx_lo[(size_t)BSR*H3];
__device__ __align__(16) __nv_bfloat16 d_h_hi0[BSR*Hh];
__device__ __align__(16) __nv_bfloat16 d_h_lo0[BSR*Hh];
__device__ __align__(16) __nv_bfloat16 d_h_hi1[BSR*Hh];
__device__ __align__(16) __nv_bfloat16 d_h_lo1[BSR*Hh];
__device__ __align__(16) __nv_bfloat16 d_in_hi[BSR*Hh];
__device__ __align__(16) __nv_bfloat16 d_in_lo[BSR*Hh];
__device__ __align__(16) __nv_bfloat16 d_W3T_hi[H7*H3];
__device__ __align__(16) __nv_bfloat16 d_W3T_lo[H7*H3];
__device__ __align__(16) __nv_bfloat16 d_GhT_hi[Hh*Hh];
__device__ __align__(16) __nv_bfloat16 d_GhT_lo[Hh*Hh];
__device__ __align__(16) __nv_bfloat16 d_WiT_hi[H7*Hh];
__device__ __align__(16) __nv_bfloat16 d_WiT_lo[H7*Hh];

// ---------------- PTX helpers -----------------------------------------------
__device__ __forceinline__ uint32_t smem_u32(const void* p) {
    uint32_t a;
    asm("{ .reg .u64 t; cvta.to.shared.u64 t, %1; cvt.u32.u64 %0, t; }"
        : "=r"(a) : "l"(p));
    return a;
}
__device__ __forceinline__ void cpasync16(uint32_t dst, const void* src) {
    asm volatile("cp.async.cg.shared.global [%0], [%1], 16;" :: "r"(dst), "l"(src));
}
#define CP_COMMIT() asm volatile("cp.async.commit_group;" ::: "memory")
#define CP_WAIT1()  asm volatile("cp.async.wait_group 1;" ::: "memory")
#define CP_WAIT0()  asm volatile("cp.async.wait_group 0;" ::: "memory")

__device__ __forceinline__ void mma16816(float* c, const uint32_t* a, const uint32_t* b) {
    asm volatile(
        "mma.sync.aligned.m16n8k16.row.col.f32.bf16.bf16.f32 "
        "{%0,%1,%2,%3}, {%4,%5,%6,%7}, {%8,%9}, {%0,%1,%2,%3};"
        : "+f"(c[0]), "+f"(c[1]), "+f"(c[2]), "+f"(c[3])
        : "r"(a[0]), "r"(a[1]), "r"(a[2]), "r"(a[3]), "r"(b[0]), "r"(b[1]));
}
__device__ __forceinline__ void ldsm4(uint32_t& r0, uint32_t& r1, uint32_t& r2,
                                      uint32_t& r3, uint32_t addr) {
    asm volatile("ldmatrix.sync.aligned.m8n8.x4.shared.b16 {%0,%1,%2,%3}, [%4];"
                 : "=r"(r0), "=r"(r1), "=r"(r2), "=r"(r3) : "r"(addr));
}

// ---------------- bf16x3 HMMA GEMM -------------------------------------------
// C[M,N] = (Ahi+Alo)[M,K] @ (Bhi+Blo)^T  with B stored [N,K] K-major.
// M%128==0, N%128==0, K%32==0.
#define KB 32
#define SA 40                      // padded smem row stride (halves)
#define MTILE (128*SA)
#define STAGE (4*MTILE)            // Ahi, Alo, Bhi, Blo
#define HSMEM (2*STAGE*2)          // 81920 bytes

__global__ void __launch_bounds__(256, 1) k_hmma(
    int M, int N, int K,
    const __nv_bfloat16* __restrict__ Ahi, const __nv_bfloat16* __restrict__ Alo,
    const __nv_bfloat16* __restrict__ Bhi, const __nv_bfloat16* __restrict__ Blo,
    const float* __restrict__ bias, float* __restrict__ C)
{
    extern __shared__ __nv_bfloat16 sm[];
    int tid = threadIdx.x, wid = tid >> 5, lane = tid & 31;
    int gID = lane >> 2, tg = lane & 3;
    int warp_m = wid >> 2, warp_n = wid & 3;
    int arow0 = blockIdx.y * 128, bcol0 = blockIdx.x * 128;

    const __nv_bfloat16* srcs[4] = {
        Ahi + (size_t)arow0 * K, Alo + (size_t)arow0 * K,
        Bhi + (size_t)bcol0 * K, Blo + (size_t)bcol0 * K };

    float acc[4][4][4];
    #pragma unroll
    for (int mi = 0; mi < 4; mi++)
        #pragma unroll
        for (int ni = 0; ni < 4; ni++)
            #pragma unroll
            for (int q = 0; q < 4; q++) acc[mi][ni][q] = 0.f;

    uint32_t smbase = smem_u32(sm);
    int niter = K / KB;

    // ldmatrix per-lane address deltas (bytes)
    int mat = lane >> 3, lr = lane & 7;
    int a_off = (((mat & 1) * 8 + lr) * SA + (mat >> 1) * 8) * 2;
    int b_off = (((mat >> 1) * 8 + lr) * SA + (mat & 1) * 8) * 2;

    // prologue: stage 0
    #pragma unroll
    for (int t = 0; t < 4; t++) {
        const __nv_bfloat16* src = srcs[t];
        uint32_t dst = smbase + (0 * STAGE + t * MTILE) * 2;
        #pragma unroll
        for (int s = 0; s < 2; s++) {
            int slot = tid + s * 256;
            int row = slot >> 2, cg = (slot & 3) * 8;
            cpasync16(dst + (row * SA + cg) * 2, src + (size_t)row * K + cg);
        }
    }
    CP_COMMIT();

    for (int it = 0; it < niter; it++) {
        if (it + 1 < niter) {
            int st = (it + 1) & 1;
            int k0 = (it + 1) * KB;
            #pragma unroll
            for (int t = 0; t < 4; t++) {
                const __nv_bfloat16* src = srcs[t] + k0;
                uint32_t dst = smbase + (st * STAGE + t * MTILE) * 2;
                #pragma unroll
                for (int s = 0; s < 2; s++) {
                    int slot = tid + s * 256;
                    int row = slot >> 2, cg = (slot & 3) * 8;
                    cpasync16(dst + (row * SA + cg) * 2, src + (size_t)row * K + cg);
                }
            }
            CP_COMMIT();
            CP_WAIT1();
        } else {
            CP_WAIT0();
        }
        __syncthreads();

        uint32_t Ab = smbase + ((it & 1) * STAGE) * 2;
        uint32_t Al = Ab + MTILE * 2;
        uint32_t Bh = Ab + 2 * MTILE * 2;
        uint32_t Bl = Ab + 3 * MTILE * 2;

        #pragma unroll
        for (int kk = 0; kk < KB; kk += 16) {
            uint32_t bh[4][2], bl[4][2];
            #pragma unroll
            for (int np = 0; np < 2; np++) {
                int n0 = warp_n * 32 + np * 16;
                uint32_t base = (n0 * SA + kk) * 2 + b_off;
                ldsm4(bh[np*2][0], bh[np*2][1], bh[np*2+1][0], bh[np*2+1][1], Bh + base);
                ldsm4(bl[np*2][0], bl[np*2][1], bl[np*2+1][0], bl[np*2+1][1], Bl + base);
            }
            #pragma unroll
            for (int mi = 0; mi < 4; mi++) {
                int r0 = warp_m * 64 + mi * 16;
                uint32_t abase = (r0 * SA + kk) * 2 + a_off;
                uint32_t ah[4], al[4];
                ldsm4(ah[0], ah[1], ah[2], ah[3], Ab + abase);
                ldsm4(al[0], al[1], al[2], al[3], Al + abase);
                #pragma unroll
                for (int ni = 0; ni < 4; ni++) {
                    mma16816(acc[mi][ni], ah, bh[ni]);
                    mma16816(acc[mi][ni], ah, bl[ni]);
                    mma16816(acc[mi][ni], al, bh[ni]);
                }
            }
        }
        __syncthreads();
    }

    // epilogue
    #pragma unroll
    for (int mi = 0; mi < 4; mi++) {
        #pragma unroll
        for (int ni = 0; ni < 4; ni++) {
            int r = arow0 + warp_m * 64 + mi * 16 + gID;
            int c = bcol0 + warp_n * 32 + ni * 8 + tg * 2;
            float b0 = bias ? bias[c] : 0.f;
            float b1 = bias ? bias[c + 1] : 0.f;
            float2 v0 = make_float2(acc[mi][ni][0] + b0, acc[mi][ni][1] + b1);
            float2 v1 = make_float2(acc[mi][ni][2] + b0, acc[mi][ni][3] + b1);
            *(float2*)(C + (size_t)r * N + c) = v0;
            *(float2*)(C + (size_t)(r + 8) * N + c) = v1;
        }
    }
}

// ---------------- helpers ----------------------------------------------------
__device__ __forceinline__ float2 blockSum2(float a, float b, float* sh) {
    #pragma unroll
    for (int o = 16; o > 0; o >>= 1) {
        a += __shfl_down_sync(0xffffffffu, a, o);
        b += __shfl_down_sync(0xffffffffu, b, o);
    }
    int w = threadIdx.x >> 5, l = threadIdx.x & 31;
    if (l == 0) { sh[w] = a; sh[8 + w] = b; }
    __syncthreads();
    if (threadIdx.x == 0) {
        float sa = 0.f, sb2 = 0.f;
        #pragma unroll
        for (int i = 0; i < 8; i++) { sa += sh[i]; sb2 += sh[8 + i]; }
        sh[16] = sa; sh[17] = sb2;
    }
    __syncthreads();
    float2 r = make_float2(sh[16], sh[17]);
    __syncthreads();
    return r;
}
__device__ __forceinline__ float sigmoidf_(float x) { return 1.f / (1.f + expf(-x)); }
__device__ __forceinline__ void splitbf(float v, __nv_bfloat16& hi, __nv_bfloat16& lo) {
    hi = __float2bfloat16(v);
    lo = __float2bfloat16(v - __bfloat162float(hi));
}

// ---------------- split / transpose kernels ----------------------------------
__global__ void k_split(const float* __restrict__ x, __nv_bfloat16* __restrict__ hi,
                        __nv_bfloat16* __restrict__ lo, int n)
{
    int i = blockIdx.x * blockDim.x + threadIdx.x;
    if (i >= n) return;
    splitbf(x[i], hi[i], lo[i]);
}

__global__ void k_w3t(const float* __restrict__ Wc, const float* __restrict__ Wh,
                      __nv_bfloat16* __restrict__ hi, __nv_bfloat16* __restrict__ lo)
{
    int i = blockIdx.x * blockDim.x + threadIdx.x;   // [H7 x H3]
    if (i >= H7 * H3) return;
    int n = i / H3, k = i % H3;
    float v = (k < Hh) ? Wc[(size_t)k * H7 + n]
            : (k < 2 * Hh) ? Wh[(size_t)(k - Hh) * H7 + n]
            : Wc[(size_t)(k - Hh) * H7 + n];
    splitbf(v, hi[i], lo[i]);
}

__global__ void k_wt(const float* __restrict__ W, int K, int N,
                     __nv_bfloat16* __restrict__ hi, __nv_bfloat16* __restrict__ lo)
{
    int i = blockIdx.x * blockDim.x + threadIdx.x;   // [N x K]
    if (i >= N * K) return;
    int n = i / K, k = i % K;
    splitbf(W[(size_t)k * N + n], hi[i], lo[i]);
}

// ---------------- small kernels ----------------------------------------------
__global__ void k_invms(const float* __restrict__ mask, float* __restrict__ invms)
{
    __shared__ float sh[8];
    int b = blockIdx.x, t = threadIdx.x;
    float a = 0.f;
    for (int s = t; s < Ss; s += 256) a += mask[b * Ss + s];
    #pragma unroll
    for (int o = 16; o > 0; o >>= 1) a += __shfl_down_sync(0xffffffffu, a, o);
    if ((t & 31) == 0) sh[t >> 5] = a;
    __syncthreads();
    if (t == 0) {
        float s2 = 0.f;
        #pragma unroll
        for (int i = 0; i < 8; i++) s2 += sh[i];
        invms[b] = 1.f / s2;
    }
}

__global__ void k_meanp(const float* __restrict__ x, const float* __restrict__ mask,
                        float* __restrict__ pnum)
{
    int ch = blockIdx.x, b = blockIdx.y, h = threadIdx.x;
    float acc = 0.f;
    int s0 = ch * SCH;
    #pragma unroll 8
    for (int i = 0; i < SCH; i++) {
        int s = s0 + i;
        acc += x[((size_t)(b * Ss + s)) * Hh + h] * mask[b * Ss + s];
    }
    pnum[(b * NCH + ch) * Hh + h] = acc;
}

__global__ void k_meanf(const float* __restrict__ pnum, const float* __restrict__ invms,
                        float* __restrict__ out)
{
    int b = blockIdx.x, h = threadIdx.x;
    float a = 0.f;
    #pragma unroll
    for (int c = 0; c < NCH; c++) a += pnum[(b * NCH + c) * Hh + h];
    out[b * Hh + h] = a * invms[b];
}

// fused: pi = gh@Gi + gb, pa = havg@Ga, then ig/og LayerNorm+sigmoid; writes pihg
__global__ void k_globalA(const float* __restrict__ gh, const float* __restrict__ havg,
                          const float* __restrict__ Gi, const float* __restrict__ gb,
                          const float* __restrict__ Ga,
                          const float* __restrict__ lns, const float* __restrict__ lnb,
                          float* __restrict__ ig, float* __restrict__ og,
                          float* __restrict__ pihg)
{
    __shared__ float sgh[Hh], sha[Hh], sh[18];
    int b = blockIdx.x, h = threadIdx.x;
    sgh[h] = gh[b * Hh + h];
    sha[h] = havg[b * Hh + h];
    __syncthreads();
    float a0 = 0.f, a1 = 0.f, a2 = 0.f, a3 = 0.f, a4 = 0.f;
    #pragma unroll 4
    for (int k = 0; k < Hh; k++) {
        float g = sgh[k], a = sha[k];
        a0 += g * Gi[(size_t)k * H3 + h];
        a1 += g * Gi[(size_t)k * H3 + Hh + h];
        a2 += g * Gi[(size_t)k * H3 + 2 * Hh + h];
        a3 += a * Ga[(size_t)k * 2 * Hh + h];
        a4 += a * Ga[(size_t)k * 2 * Hh + Hh + h];
    }
    float pi0 = a0 + gb[h];
    float pi1 = a1 + gb[Hh + h];
    float pi2 = a2 + gb[2 * Hh + h];
    pihg[b * Hh + h] = pi1;
    float v = pi0 + a3;
    float2 s2 = blockSum2(v, v * v, sh);
    float m = s2.x * (1.f / 256.f);
    float var = (s2.y - 256.f * m * m) * (1.f / 255.f);
    ig[b * Hh + h] = sigmoidf_(lns[h] * (v - m) * rsqrtf(var + 1e-6f) + lnb[h]);
    v = pi2 + a4;
    s2 = blockSum2(v, v * v, sh);
    m = s2.x * (1.f / 256.f);
    var = (s2.y - 256.f * m * m) * (1.f / 255.f);
    og[b * Hh + h] = sigmoidf_(lns[2 * Hh + h] * (v - m) * rsqrtf(var + 1e-6f) + lnb[2 * Hh + h]);
}

__global__ void k_hg(const float* __restrict__ ph, const float* __restrict__ pihg,
                     const float* __restrict__ mask,
                     const float* __restrict__ lns, const float* __restrict__ lnb,
                     float* __restrict__ hg)
{
    __shared__ float sh[18];
    int bs = blockIdx.x; int b = bs >> 10;
    int h = threadIdx.x;
    float v = ph[(size_t)bs * Hh + h] + pihg[b * Hh + h];
    float2 ssum = blockSum2(v, v * v, sh);
    float m = ssum.x * (1.f / 256.f);
    float var = (ssum.y - 256.f * m * m) * (1.f / 255.f);
    float zn = lns[Hh + h] * (v - m) * rsqrtf(var + 1e-6f) + lnb[Hh + h];
    hg[(size_t)bs * Hh + h] = sigmoidf_(zn) + (mask[bs] * 1e25f - 1e25f);
}

__global__ void k_gcp(const float* __restrict__ hg, const float* __restrict__ cell,
                      float* __restrict__ pnum, float* __restrict__ pden)
{
    int ch = blockIdx.x, b = blockIdx.y, h = threadIdx.x;
    float num = 0.f, den = 0.f;
    int s0 = ch * SCH;
    #pragma unroll 4
    for (int i = 0; i < SCH; i++) {
        size_t idx = ((size_t)(b * Ss + s0 + i)) * Hh + h;
        float e = expf(hg[idx]);
        num += e * cell[idx];
        den += e;
    }
    pnum[(b * NCH + ch) * Hh + h] = num;
    pden[(b * NCH + ch) * Hh + h] = den;
}

// fused: finish g_c/g_h softmax combine, then gWg = gh @ Wg
__global__ void k_gcfWg(const float* __restrict__ pnum, const float* __restrict__ pden,
                        const float* __restrict__ ig, const float* __restrict__ og,
                        const float* __restrict__ Wg,
                        float* __restrict__ gc, float* __restrict__ gh,
                        float* __restrict__ gWg)
{
    __shared__ float sgh[Hh];
    int b = blockIdx.x, h = threadIdx.x;
    float num = 0.f, den = 0.f;
    #pragma unroll
    for (int c = 0; c < NCH; c++) {
        num += pnum[(b * NCH + c) * Hh + h];
        den += pden[(b * NCH + c) * Hh + h];
    }
    float ei = expf(ig[b * Hh + h]);
    float g = (gc[b * Hh + h] * ei + num) / (ei + den);
    gc[b * Hh + h] = g;
    float ghv = og[b * Hh + h] * tanhf(g);
    gh[b * Hh + h] = ghv;
    sgh[h] = ghv;
    __syncthreads();
    #pragma unroll
    for (int j = 0; j < 7; j++) {
        float acc = 0.f;
        #pragma unroll 4
        for (int k = 0; k < Hh; k++)
            acc += sgh[k] * Wg[(size_t)k * H7 + j * Hh + h];
        gWg[(size_t)b * H7 + j * Hh + h] = acc;
    }
}

// build split-bf16 ctx = [h_l, h, h_r] directly from split-bf16 hidden
__global__ void k_ctx_bf(const __nv_bfloat16* __restrict__ hhi,
                         const __nv_bfloat16* __restrict__ hlo,
                         __nv_bfloat16* __restrict__ chi,
                         __nv_bfloat16* __restrict__ clo)
{
    int i = blockIdx.x * blockDim.x + threadIdx.x;  // 8-elem chunk
    if (i >= BSR * (H3 / 8)) return;
    int bs = i / (H3 / 8);
    int j = (i % (H3 / 8)) * 8;
    int s = bs & (Ss - 1);
    uint4 vh = make_uint4(0, 0, 0, 0), vl = make_uint4(0, 0, 0, 0);
    long off = -1;
    if (j < Hh)           { if (s > 0)      off = ((long)bs - 1) * Hh + j; }
    else if (j < 2 * Hh)  {                 off = (long)bs * Hh + (j - Hh); }
    else                  { if (s < Ss - 1) off = ((long)bs + 1) * Hh + (j - 2 * Hh); }
    if (off >= 0) {
        vh = *(const uint4*)(hhi + off);
        vl = *(const uint4*)(hlo + off);
    }
    *(uint4*)(chi + (size_t)bs * H3 + j) = vh;
    *(uint4*)(clo + (size_t)bs * H3 + j) = vl;
}

__global__ __launch_bounds__(256) void k_update(
    const float* __restrict__ z, const float* __restrict__ proj,
    const float* __restrict__ gWg, const float* __restrict__ gc,
    const float* __restrict__ mask,
    const float* __restrict__ lns, const float* __restrict__ lnb,
    const float* __restrict__ c_old,
    float* __restrict__ h_new, float* __restrict__ c_new,
    __nv_bfloat16* __restrict__ hhi, __nv_bfloat16* __restrict__ hlo)
{
    __shared__ float sh[18];
    int bs = blockIdx.x; int b = bs >> 10; int s = bs & (Ss - 1);
    int h = threadIdx.x;
    size_t rz = (size_t)bs * H7;
    float zn[7];
    #pragma unroll
    for (int k = 0; k < 7; k++) {
        float v = z[rz + k * Hh + h] + proj[rz + k * Hh + h] + gWg[b * H7 + k * Hh + h];
        float2 ssum = blockSum2(v, v * v, sh);
        float m = ssum.x * (1.f / 256.f);
        float var = (ssum.y - 256.f * m * m) * (1.f / 255.f);
        zn[k] = lns[(3 + k) * Hh + h] * (v - m) * rsqrtf(var + 1e-6f) + lnb[(3 + k) * Hh + h];
    }
    float e[6], den = 0.f;
    #pragma unroll
    for (int k = 0; k < 6; k++) {
        e[k] = expf(sigmoidf_(zn[k]));
        den += e[k];
    }
    float inv = 1.f / den;
    float mem = tanhf(zn[6]);
    size_t idx = (size_t)bs * Hh + h;
    float c  = c_old[idx];
    float cl = (s > 0)      ? c_old[idx - Hh] : 0.f;
    float cr = (s < Ss - 1) ? c_old[idx + Hh] : 0.f;
    float cn = (e[1] * cl + e[2] * cr + e[3] * c + e[0] * mem + e[4] * gc[b * Hh + h]) * inv;
    float mk = mask[bs];
    float hv = e[5] * inv * tanhf(cn) * mk;
    h_new[idx] = hv;
    c_new[idx] = cn * mk;
    splitbf(hv, hhi[idx], hlo[idx]);
}

// ---------------- orchestration ----------------------------------------------
extern "C" void kernel_launch(void* const* d_in, const int* in_sizes, int n_in,
                              void* d_out, int out_size)
{
    (void)in_sizes; (void)n_in; (void)out_size;
    const float* inputs = (const float*)d_in[0];
    const float* mask   = (const float*)d_in[1];
    const float* ih     = (const float*)d_in[2];
    const float* ic     = (const float*)d_in[3];
    const float* Wc     = (const float*)d_in[4];
    const float* Wh     = (const float*)d_in[5];
    const float* Wi     = (const float*)d_in[6];
    const float* bi     = (const float*)d_in[7];
    const float* Wg     = (const float*)d_in[8];
    const float* Gi     = (const float*)d_in[9];
    const float* gb     = (const float*)d_in[10];
    const float* Gh     = (const float*)d_in[11];
    const float* Ga     = (const float*)d_in[12];
    const float* lns    = (const float*)d_in[13];
    const float* lnb    = (const float*)d_in[14];
    float* out = (float*)d_out;

    float *hb0, *hb1, *cb0, *cb1, *proj, *zb, *ph;
    float *pihg, *ig, *og, *gh, *gc, *havg, *gWg, *pnum, *pden, *invms;
    __nv_bfloat16 *chi, *clo, *hh0, *hl0, *hh1, *hl1, *inh, *inl;
    __nv_bfloat16 *w3h, *w3l, *ghh, *ghl, *wih, *wil;
    cudaGetSymbolAddress((void**)&hb0,  d_hbuf0);
    cudaGetSymbolAddress((void**)&hb1,  d_hbuf1);
    cudaGetSymbolAddress((void**)&cb0,  d_cbuf0);
    cudaGetSymbolAddress((void**)&cb1,  d_cbuf1);
    cudaGetSymbolAddress((void**)&proj, d_proj);
    cudaGetSymbolAddress((void**)&zb,   d_zbuf);
    cudaGetSymbolAddress((void**)&ph,   d_ph);
    cudaGetSymbolAddress((void**)&pihg, d_pihg);
    cudaGetSymbolAddress((void**)&ig,   d_igb);
    cudaGetSymbolAddress((void**)&og,   d_ogb);
    cudaGetSymbolAddress((void**)&gh,   d_gh);
    cudaGetSymbolAddress((void**)&gc,   d_gcv);
    cudaGetSymbolAddress((void**)&havg, d_havg);
    cudaGetSymbolAddress((void**)&gWg,  d_gWg);
    cudaGetSymbolAddress((void**)&pnum, d_pnum);
    cudaGetSymbolAddress((void**)&pden, d_pden);
    cudaGetSymbolAddress((void**)&invms, d_invms);
    cudaGetSymbolAddress((void**)&chi, d_ctx_hi);
    cudaGetSymbolAddress((void**)&clo, d_ctx_lo);
    cudaGetSymbolAddress((void**)&hh0, d_h_hi0);
    cudaGetSymbolAddress((void**)&hl0, d_h_lo0);
    cudaGetSymbolAddress((void**)&hh1, d_h_hi1);
    cudaGetSymbolAddress((void**)&hl1, d_h_lo1);
    cudaGetSymbolAddress((void**)&inh, d_in_hi);
    cudaGetSymbolAddress((void**)&inl, d_in_lo);
    cudaGetSymbolAddress((void**)&w3h, d_W3T_hi);
    cudaGetSymbolAddress((void**)&w3l, d_W3T_lo);
    cudaGetSymbolAddress((void**)&ghh, d_GhT_hi);
    cudaGetSymbolAddress((void**)&ghl, d_GhT_lo);
    cudaGetSymbolAddress((void**)&wih, d_WiT_hi);
    cudaGetSymbolAddress((void**)&wil, d_WiT_lo);

    cudaFuncSetAttribute(k_hmma, cudaFuncAttributeMaxDynamicSharedMemorySize, HSMEM);

    // layer-invariant precompute
    k_invms<<<Bb, 256>>>(mask, invms);
    k_meanp<<<dim3(NCH, Bb), 256>>>(ih, mask, pnum);
    k_meanf<<<Bb, 256>>>(pnum, invms, gh);
    k_meanp<<<dim3(NCH, Bb), 256>>>(ic, mask, pnum);
    k_meanf<<<Bb, 256>>>(pnum, invms, gc);
    k_w3t<<<(H7 * H3 + 255) / 256, 256>>>(Wc, Wh, w3h, w3l);
    k_wt<<<(Hh * Hh + 255) / 256, 256>>>(Gh, Hh, Hh, ghh, ghl);
    k_wt<<<(H7 * Hh + 255) / 256, 256>>>(Wi, Hh, H7, wih, wil);
    k_split<<<(BSR * Hh + 255) / 256, 256>>>(ih, hh0, hl0, BSR * Hh);
    k_split<<<(BSR * Hh + 255) / 256, 256>>>(inputs, inh, inl, BSR * Hh);
    k_hmma<<<dim3(H7 / 128, BSR / 128), 256, HSMEM>>>(
        BSR, H7, Hh, inh, inl, wih, wil, bi, proj);

    float* hbufs[2] = { hb0, hb1 };
    float* cbufs[2] = { cb0, cb1 };
    __nv_bfloat16* hhis[2] = { hh0, hh1 };
    __nv_bfloat16* hlos[2] = { hl0, hl1 };

    for (int l = 0; l < LL; l++) {
        const float* hid = (l == 0) ? ih : hbufs[l & 1];
        const float* cel = (l == 0) ? ic : cbufs[l & 1];
        const __nv_bfloat16* hhi = hhis[l & 1];
        const __nv_bfloat16* hlo = hlos[l & 1];
        float* hout = (l == LL - 1) ? out : hbufs[(l + 1) & 1];
        float* cout = cbufs[(l + 1) & 1];

        // ---- global state ----
        k_meanp<<<dim3(NCH, Bb), 256>>>(hid, mask, pnum);
        k_meanf<<<Bb, 256>>>(pnum, invms, havg);
        k_globalA<<<Bb, 256>>>(gh, havg, Gi, gb, Ga, lns, lnb, ig, og, pihg);
        k_hmma<<<dim3(Hh / 128, BSR / 128), 256, HSMEM>>>(
            BSR, Hh, Hh, hhi, hlo, ghh, ghl, (const float*)nullptr, ph);
        k_hg<<<BSR, 256>>>(ph, pihg, mask, lns, lnb, ph);
        k_gcp<<<dim3(NCH, Bb), 256>>>(ph, cel, pnum, pden);
        k_gcfWg<<<Bb, 256>>>(pnum, pden, ig, og, Wg, gc, gh, gWg);

        // ---- per-word state ----
        k_ctx_bf<<<(BSR * (H3 / 8) + 255) / 256, 256>>>(hhi, hlo, chi, clo);
        k_hmma<<<dim3(H7 / 128, BSR / 128), 256, HSMEM>>>(
            BSR, H7, H3, chi, clo, w3h, w3l, (const float*)nullptr, zb);
        k_update<<<BSR, 256>>>(zb, proj, gWg, gc, mask, lns, lnb, cel, hout, cout,
                               hhis[(l + 1) & 1], hlos[(l + 1) & 1]);
    }
}

// round 6
// speedup vs baseline: 1.5210x; 1.5140x over previous
#include <cuda_runtime.h>
#include <cuda_bf16.h>
#include <cstdint>
#include <cstddef>

// Problem constants
#define Bb 8
#define Ss 1024
#define Hh 256
#define LL 7
#define BSR (Bb*Ss)        // 8192 rows
#define H7 (7*Hh)          // 1792
#define H3 (3*Hh)          // 768
#define NCH 64
#define SCH (Ss/NCH)       // 16

// ---------------- scratch (device globals; no allocations allowed) ----------
__device__ float d_hbuf0[BSR*Hh];
__device__ float d_hbuf1[BSR*Hh];
__device__ float d_cbuf0[BSR*Hh];
__device__ float d_cbuf1[BSR*Hh];
__device__ float d_proj[(size_t)BSR*H7];
__device__ float d_zbuf[(size_t)BSR*H7];
__device__ float d_ph[BSR*Hh];
__device__ float d_pi[Bb*H3];
__device__ float d_pa[Bb*2*Hh];
__device__ float d_igb[Bb*Hh];
__device__ float d_ogb[Bb*Hh];
__device__ float d_gh[Bb*Hh];
__device__ float d_gcv[Bb*Hh];
__device__ float d_havg[Bb*Hh];
__device__ float d_gWg[Bb*H7];
__device__ float d_pnum[Bb*NCH*Hh];
__device__ float d_pden[Bb*NCH*Hh];
__device__ float d_invms[Bb];
// split-bf16 activations / weights (16B aligned for uint4 / cp.async)
__device__ __align__(16) __nv_bfloat16 d_ctx_hi[(size_t)BSR*H3];
__device__ __align__(16) __nv_bfloat16 d_ctx_lo[(size_t)BSR*H3];
__device__ __align__(16) __nv_bfloat16 d_h_hi0[BSR*Hh];
__device__ __align__(16) __nv_bfloat16 d_h_lo0[BSR*Hh];
__device__ __align__(16) __nv_bfloat16 d_h_hi1[BSR*Hh];
__device__ __align__(16) __nv_bfloat16 d_h_lo1[BSR*Hh];
__device__ __align__(16) __nv_bfloat16 d_in_hi[BSR*Hh];
__device__ __align__(16) __nv_bfloat16 d_in_lo[BSR*Hh];
__device__ __align__(16) __nv_bfloat16 d_W3T_hi[H7*H3];
__device__ __align__(16) __nv_bfloat16 d_W3T_lo[H7*H3];
__device__ __align__(16) __nv_bfloat16 d_GhT_hi[Hh*Hh];
__device__ __align__(16) __nv_bfloat16 d_GhT_lo[Hh*Hh];
__device__ __align__(16) __nv_bfloat16 d_WiT_hi[H7*Hh];
__device__ __align__(16) __nv_bfloat16 d_WiT_lo[H7*Hh];

// ---------------- PTX helpers -----------------------------------------------
__device__ __forceinline__ uint32_t smem_u32(const void* p) {
    uint32_t a;
    asm("{ .reg .u64 t; cvta.to.shared.u64 t, %1; cvt.u32.u64 %0, t; }"
        : "=r"(a) : "l"(p));
    return a;
}
__device__ __forceinline__ void cpasync16(uint32_t dst, const void* src) {
    asm volatile("cp.async.cg.shared.global [%0], [%1], 16;" :: "r"(dst), "l"(src));
}
#define CP_COMMIT() asm volatile("cp.async.commit_group;" ::: "memory")
#define CP_WAIT1()  asm volatile("cp.async.wait_group 1;" ::: "memory")
#define CP_WAIT0()  asm volatile("cp.async.wait_group 0;" ::: "memory")

__device__ __forceinline__ void mma16816(float* c, const uint32_t* a, const uint32_t* b) {
    asm volatile(
        "mma.sync.aligned.m16n8k16.row.col.f32.bf16.bf16.f32 "
        "{%0,%1,%2,%3}, {%4,%5,%6,%7}, {%8,%9}, {%0,%1,%2,%3};"
        : "+f"(c[0]), "+f"(c[1]), "+f"(c[2]), "+f"(c[3])
        : "r"(a[0]), "r"(a[1]), "r"(a[2]), "r"(a[3]), "r"(b[0]), "r"(b[1]));
}

// ---------------- bf16x3 HMMA GEMM (R3 proven version, scalar LDS) -----------
#define KB 32
#define SA 40                      // padded smem row stride (halves)
#define MTILE (128*SA)
#define STAGE (4*MTILE)            // Ahi, Alo, Bhi, Blo
#define HSMEM (2*STAGE*2)          // 81920 bytes

__global__ void __launch_bounds__(256, 1) k_hmma(
    int M, int N, int K,
    const __nv_bfloat16* __restrict__ Ahi, const __nv_bfloat16* __restrict__ Alo,
    const __nv_bfloat16* __restrict__ Bhi, const __nv_bfloat16* __restrict__ Blo,
    const float* __restrict__ bias, float* __restrict__ C)
{
    extern __shared__ __nv_bfloat16 sm[];
    int tid = threadIdx.x, wid = tid >> 5, lane = tid & 31;
    int gID = lane >> 2, tg = lane & 3;
    int warp_m = wid >> 2, warp_n = wid & 3;
    int arow0 = blockIdx.y * 128, bcol0 = blockIdx.x * 128;

    const __nv_bfloat16* srcs[4] = {
        Ahi + (size_t)arow0 * K, Alo + (size_t)arow0 * K,
        Bhi + (size_t)bcol0 * K, Blo + (size_t)bcol0 * K };

    float acc[4][4][4];
    #pragma unroll
    for (int mi = 0; mi < 4; mi++)
        #pragma unroll
        for (int ni = 0; ni < 4; ni++)
            #pragma unroll
            for (int q = 0; q < 4; q++) acc[mi][ni][q] = 0.f;

    uint32_t smbase = smem_u32(sm);
    int niter = K / KB;

    // prologue: stage 0
    #pragma unroll
    for (int t = 0; t < 4; t++) {
        const __nv_bfloat16* src = srcs[t];
        uint32_t dst = smbase + (0 * STAGE + t * MTILE) * 2;
        #pragma unroll
        for (int s = 0; s < 2; s++) {
            int slot = tid + s * 256;
            int row = slot >> 2, cg = (slot & 3) * 8;
            cpasync16(dst + (row * SA + cg) * 2, src + (size_t)row * K + cg);
        }
    }
    CP_COMMIT();

    for (int it = 0; it < niter; it++) {
        if (it + 1 < niter) {
            int st = (it + 1) & 1;
            int k0 = (it + 1) * KB;
            #pragma unroll
            for (int t = 0; t < 4; t++) {
                const __nv_bfloat16* src = srcs[t] + k0;
                uint32_t dst = smbase + (st * STAGE + t * MTILE) * 2;
                #pragma unroll
                for (int s = 0; s < 2; s++) {
                    int slot = tid + s * 256;
                    int row = slot >> 2, cg = (slot & 3) * 8;
                    cpasync16(dst + (row * SA + cg) * 2, src + (size_t)row * K + cg);
                }
            }
            CP_COMMIT();
            CP_WAIT1();
        } else {
            CP_WAIT0();
        }
        __syncthreads();

        const __nv_bfloat16* As_h = sm + (it & 1) * STAGE;
        const __nv_bfloat16* As_l = As_h + MTILE;
        const __nv_bfloat16* Bs_h = As_h + 2 * MTILE;
        const __nv_bfloat16* Bs_l = As_h + 3 * MTILE;

        #pragma unroll
        for (int kk = 0; kk < KB; kk += 16) {
            uint32_t bh[4][2], bl[4][2];
            #pragma unroll
            for (int ni = 0; ni < 4; ni++) {
                int n = warp_n * 32 + ni * 8 + gID;
                const __nv_bfloat16* ph_ = Bs_h + n * SA + kk + tg * 2;
                const __nv_bfloat16* pl_ = Bs_l + n * SA + kk + tg * 2;
                bh[ni][0] = *(const uint32_t*)ph_;
                bh[ni][1] = *(const uint32_t*)(ph_ + 8);
                bl[ni][0] = *(const uint32_t*)pl_;
                bl[ni][1] = *(const uint32_t*)(pl_ + 8);
            }
            #pragma unroll
            for (int mi = 0; mi < 4; mi++) {
                int r0 = warp_m * 64 + mi * 16 + gID;
                const __nv_bfloat16* ah_ = As_h + r0 * SA + kk + tg * 2;
                const __nv_bfloat16* al_ = As_l + r0 * SA + kk + tg * 2;
                uint32_t ah[4], al[4];
                ah[0] = *(const uint32_t*)ah_;
                ah[1] = *(const uint32_t*)(ah_ + 8 * SA);
                ah[2] = *(const uint32_t*)(ah_ + 8);
                ah[3] = *(const uint32_t*)(ah_ + 8 * SA + 8);
                al[0] = *(const uint32_t*)al_;
                al[1] = *(const uint32_t*)(al_ + 8 * SA);
                al[2] = *(const uint32_t*)(al_ + 8);
                al[3] = *(const uint32_t*)(al_ + 8 * SA + 8);
                #pragma unroll
                for (int ni = 0; ni < 4; ni++) {
                    mma16816(acc[mi][ni], ah, bh[ni]);
                    mma16816(acc[mi][ni], ah, bl[ni]);
                    mma16816(acc[mi][ni], al, bh[ni]);
                }
            }
        }
        __syncthreads();
    }

    // epilogue
    #pragma unroll
    for (int mi = 0; mi < 4; mi++) {
        #pragma unroll
        for (int ni = 0; ni < 4; ni++) {
            int r = arow0 + warp_m * 64 + mi * 16 + gID;
            int c = bcol0 + warp_n * 32 + ni * 8 + tg * 2;
            float b0 = bias ? bias[c] : 0.f;
            float b1 = bias ? bias[c + 1] : 0.f;
            float2 v0 = make_float2(acc[mi][ni][0] + b0, acc[mi][ni][1] + b1);
            float2 v1 = make_float2(acc[mi][ni][2] + b0, acc[mi][ni][3] + b1);
            *(float2*)(C + (size_t)r * N + c) = v0;
            *(float2*)(C + (size_t)(r + 8) * N + c) = v1;
        }
    }
}

// ---------------- helpers ----------------------------------------------------
__device__ __forceinline__ float2 blockSum2(float a, float b, float* sh) {
    #pragma unroll
    for (int o = 16; o > 0; o >>= 1) {
        a += __shfl_down_sync(0xffffffffu, a, o);
        b += __shfl_down_sync(0xffffffffu, b, o);
    }
    int w = threadIdx.x >> 5, l = threadIdx.x & 31;
    if (l == 0) { sh[w] = a; sh[8 + w] = b; }
    __syncthreads();
    if (threadIdx.x == 0) {
        float sa = 0.f, sb2 = 0.f;
        #pragma unroll
        for (int i = 0; i < 8; i++) { sa += sh[i]; sb2 += sh[8 + i]; }
        sh[16] = sa; sh[17] = sb2;
    }
    __syncthreads();
    float2 r = make_float2(sh[16], sh[17]);
    __syncthreads();
    return r;
}
__device__ __forceinline__ float sigmoidf_(float x) { return 1.f / (1.f + expf(-x)); }
__device__ __forceinline__ void splitbf(float v, __nv_bfloat16& hi, __nv_bfloat16& lo) {
    hi = __float2bfloat16(v);
    lo = __float2bfloat16(v - __bfloat162float(hi));
}

// ---------------- split / transpose kernels ----------------------------------
__global__ void k_split(const float* __restrict__ x, __nv_bfloat16* __restrict__ hi,
                        __nv_bfloat16* __restrict__ lo, int n)
{
    int i = blockIdx.x * blockDim.x + threadIdx.x;
    if (i >= n) return;
    splitbf(x[i], hi[i], lo[i]);
}

__global__ void k_w3t(const float* __restrict__ Wc, const float* __restrict__ Wh,
                      __nv_bfloat16* __restrict__ hi, __nv_bfloat16* __restrict__ lo)
{
    int i = blockIdx.x * blockDim.x + threadIdx.x;   // [H7 x H3]
    if (i >= H7 * H3) return;
    int n = i / H3, k = i % H3;
    float v = (k < Hh) ? Wc[(size_t)k * H7 + n]
            : (k < 2 * Hh) ? Wh[(size_t)(k - Hh) * H7 + n]
            : Wc[(size_t)(k - Hh) * H7 + n];
    splitbf(v, hi[i], lo[i]);
}

__global__ void k_wt(const float* __restrict__ W, int K, int N,
                     __nv_bfloat16* __restrict__ hi, __nv_bfloat16* __restrict__ lo)
{
    int i = blockIdx.x * blockDim.x + threadIdx.x;   // [N x K]
    if (i >= N * K) return;
    int n = i / K, k = i % K;
    splitbf(W[(size_t)k * N + n], hi[i], lo[i]);
}

// ---------------- tiny GEMM for M=8 rows -------------------------------------
__global__ void k_smallgemm(int M, int N, int K,
                            const float* __restrict__ A, const float* __restrict__ W,
                            const float* __restrict__ bias, float* __restrict__ C)
{
    int idx = blockIdx.x * blockDim.x + threadIdx.x;
    if (idx >= M * N) return;
    int m = idx / N, n = idx % N;
    float acc = bias ? bias[n] : 0.f;
    const float* a = A + (size_t)m * K;
    for (int k = 0; k < K; k++) acc += a[k] * W[(size_t)k * N + n];
    C[idx] = acc;
}

// ---------------- small kernels ----------------------------------------------
__global__ void k_invms(const float* __restrict__ mask, float* __restrict__ invms)
{
    __shared__ float sh[8];
    int b = blockIdx.x, t = threadIdx.x;
    float a = 0.f;
    for (int s = t; s < Ss; s += 256) a += mask[b * Ss + s];
    #pragma unroll
    for (int o = 16; o > 0; o >>= 1) a += __shfl_down_sync(0xffffffffu, a, o);
    if ((t & 31) == 0) sh[t >> 5] = a;
    __syncthreads();
    if (t == 0) {
        float s2 = 0.f;
        #pragma unroll
        for (int i = 0; i < 8; i++) s2 += sh[i];
        invms[b] = 1.f / s2;
    }
}

__global__ void k_meanp(const float* __restrict__ x, const float* __restrict__ mask,
                        float* __restrict__ pnum)
{
    int ch = blockIdx.x, b = blockIdx.y, h = threadIdx.x;
    float acc = 0.f;
    int s0 = ch * SCH;
    #pragma unroll
    for (int i = 0; i < SCH; i++) {
        int s = s0 + i;
        acc += x[((size_t)(b * Ss + s)) * Hh + h] * mask[b * Ss + s];
    }
    pnum[(b * NCH + ch) * Hh + h] = acc;
}

__global__ void k_meanf(const float* __restrict__ pnum, const float* __restrict__ invms,
                        float* __restrict__ out)
{
    int b = blockIdx.x, h = threadIdx.x;
    float a = 0.f;
    #pragma unroll
    for (int c = 0; c < NCH; c++) a += pnum[(b * NCH + c) * Hh + h];
    out[b * Hh + h] = a * invms[b];
}

__global__ void k_igog(const float* __restrict__ pi, const float* __restrict__ pa,
                       const float* __restrict__ lns, const float* __restrict__ lnb,
                       float* __restrict__ ig, float* __restrict__ og)
{
    __shared__ float sh[18];
    int b = blockIdx.x, h = threadIdx.x;
    float v = pi[b * H3 + h] + pa[b * 2 * Hh + h];
    float2 ssum = blockSum2(v, v * v, sh);
    float m = ssum.x * (1.f / 256.f);
    float var = (ssum.y - 256.f * m * m) * (1.f / 255.f);
    float zn = lns[h] * (v - m) * rsqrtf(var + 1e-6f) + lnb[h];
    ig[b * Hh + h] = sigmoidf_(zn);
    v = pi[b * H3 + 2 * Hh + h] + pa[b * 2 * Hh + Hh + h];
    ssum = blockSum2(v, v * v, sh);
    m = ssum.x * (1.f / 256.f);
    var = (ssum.y - 256.f * m * m) * (1.f / 255.f);
    zn = lns[2 * Hh + h] * (v - m) * rsqrtf(var + 1e-6f) + lnb[2 * Hh + h];
    og[b * Hh + h] = sigmoidf_(zn);
}

__global__ void k_hg(const float* __restrict__ ph, const float* __restrict__ pi,
                     const float* __restrict__ mask,
                     const float* __restrict__ lns, const float* __restrict__ lnb,
                     float* __restrict__ hg)
{
    __shared__ float sh[18];
    int bs = blockIdx.x; int b = bs >> 10;
    int h = threadIdx.x;
    float v = ph[(size_t)bs * Hh + h] + pi[b * H3 + Hh + h];
    float2 ssum = blockSum2(v, v * v, sh);
    float m = ssum.x * (1.f / 256.f);
    float var = (ssum.y - 256.f * m * m) * (1.f / 255.f);
    float zn = lns[Hh + h] * (v - m) * rsqrtf(var + 1e-6f) + lnb[Hh + h];
    hg[(size_t)bs * Hh + h] = sigmoidf_(zn) + (mask[bs] * 1e25f - 1e25f);
}

__global__ void k_gcp(const float* __restrict__ hg, const float* __restrict__ cell,
                      float* __restrict__ pnum, float* __restrict__ pden)
{
    int ch = blockIdx.x, b = blockIdx.y, h = threadIdx.x;
    float num = 0.f, den = 0.f;
    int s0 = ch * SCH;
    #pragma unroll
    for (int i = 0; i < SCH; i++) {
        size_t idx = ((size_t)(b * Ss + s0 + i)) * Hh + h;
        float e = expf(hg[idx]);
        num += e * cell[idx];
        den += e;
    }
    pnum[(b * NCH + ch) * Hh + h] = num;
    pden[(b * NCH + ch) * Hh + h] = den;
}

__global__ void k_gcf(const float* __restrict__ pnum, const float* __restrict__ pden,
                      const float* __restrict__ ig, const float* __restrict__ og,
                      float* __restrict__ gc, float* __restrict__ gh)
{
    int b = blockIdx.x, h = threadIdx.x;
    float num = 0.f, den = 0.f;
    #pragma unroll
    for (int c = 0; c < NCH; c++) {
        num += pnum[(b * NCH + c) * Hh + h];
        den += pden[(b * NCH + c) * Hh + h];
    }
    float ei = expf(ig[b * Hh + h]);
    float g = (gc[b * Hh + h] * ei + num) / (ei + den);
    gc[b * Hh + h] = g;
    gh[b * Hh + h] = og[b * Hh + h] * tanhf(g);
}

// build split-bf16 ctx = [h_l, h, h_r] directly from split-bf16 hidden
__global__ void k_ctx_bf(const __nv_bfloat16* __restrict__ hhi,
                         const __nv_bfloat16* __restrict__ hlo,
                         __nv_bfloat16* __restrict__ chi,
                         __nv_bfloat16* __restrict__ clo)
{
    int i = blockIdx.x * blockDim.x + threadIdx.x;  // 8-elem chunk
    if (i >= BSR * (H3 / 8)) return;
    int bs = i / (H3 / 8);
    int j = (i % (H3 / 8)) * 8;
    int s = bs & (Ss - 1);
    uint4 vh = make_uint4(0, 0, 0, 0), vl = make_uint4(0, 0, 0, 0);
    long off = -1;
    if (j < Hh)           { if (s > 0)      off = ((long)bs - 1) * Hh + j; }
    else if (j < 2 * Hh)  {                 off = (long)bs * Hh + (j - Hh); }
    else                  { if (s < Ss - 1) off = ((long)bs + 1) * Hh + (j - 2 * Hh); }
    if (off >= 0) {
        vh = *(const uint4*)(hhi + off);
        vl = *(const uint4*)(hlo + off);
    }
    *(uint4*)(chi + (size_t)bs * H3 + j) = vh;
    *(uint4*)(clo + (size_t)bs * H3 + j) = vl;
}

// one-pass LN for all 7 groups: 2 barriers instead of 21
__global__ __launch_bounds__(256) void k_update(
    const float* __restrict__ z, const float* __restrict__ proj,
    const float* __restrict__ gWg, const float* __restrict__ gc,
    const float* __restrict__ mask,
    const float* __restrict__ lns, const float* __restrict__ lnb,
    const float* __restrict__ c_old,
    float* __restrict__ h_new, float* __restrict__ c_new,
    __nv_bfloat16* __restrict__ hhi, __nv_bfloat16* __restrict__ hlo)
{
    __shared__ float wsum[8][14];
    __shared__ float fin[14];
    int bs = blockIdx.x; int b = bs >> 10; int s = bs & (Ss - 1);
    int h = threadIdx.x;
    int w = h >> 5, lane = h & 31;
    size_t rz = (size_t)bs * H7;
    float v[7];
    #pragma unroll
    for (int k = 0; k < 7; k++)
        v[k] = z[rz + k * Hh + h] + proj[rz + k * Hh + h] + gWg[b * H7 + k * Hh + h];

    float p[14];
    #pragma unroll
    for (int k = 0; k < 7; k++) { p[2 * k] = v[k]; p[2 * k + 1] = v[k] * v[k]; }
    #pragma unroll
    for (int o = 16; o > 0; o >>= 1)
        #pragma unroll
        for (int j = 0; j < 14; j++)
            p[j] += __shfl_down_sync(0xffffffffu, p[j], o);
    if (lane == 0)
        #pragma unroll
        for (int j = 0; j < 14; j++) wsum[w][j] = p[j];
    __syncthreads();
    if (h < 14) {
        float a = 0.f;
        #pragma unroll
        for (int i = 0; i < 8; i++) a += wsum[i][h];
        fin[h] = a;
    }
    __syncthreads();

    float zn[7];
    #pragma unroll
    for (int k = 0; k < 7; k++) {
        float m = fin[2 * k] * (1.f / 256.f);
        float var = (fin[2 * k + 1] - 256.f * m * m) * (1.f / 255.f);
        zn[k] = lns[(3 + k) * Hh + h] * (v[k] - m) * rsqrtf(var + 1e-6f) + lnb[(3 + k) * Hh + h];
    }
    float e[6], den = 0.f;
    #pragma unroll
    for (int k = 0; k < 6; k++) {
        e[k] = expf(sigmoidf_(zn[k]));
        den += e[k];
    }
    float inv = 1.f / den;
    float mem = tanhf(zn[6]);
    size_t idx = (size_t)bs * Hh + h;
    float c  = c_old[idx];
    float cl = (s > 0)      ? c_old[idx - Hh] : 0.f;
    float cr = (s < Ss - 1) ? c_old[idx + Hh] : 0.f;
    float cn = (e[1] * cl + e[2] * cr + e[3] * c + e[0] * mem + e[4] * gc[b * Hh + h]) * inv;
    float mk = mask[bs];
    float hv = e[5] * inv * tanhf(cn) * mk;
    h_new[idx] = hv;
    c_new[idx] = cn * mk;
    splitbf(hv, hhi[idx], hlo[idx]);
}

// ---------------- orchestration ----------------------------------------------
extern "C" void kernel_launch(void* const* d_in, const int* in_sizes, int n_in,
                              void* d_out, int out_size)
{
    (void)in_sizes; (void)n_in; (void)out_size;
    const float* inputs = (const float*)d_in[0];
    const float* mask   = (const float*)d_in[1];
    const float* ih     = (const float*)d_in[2];
    const float* ic     = (const float*)d_in[3];
    const float* Wc     = (const float*)d_in[4];
    const float* Wh     = (const float*)d_in[5];
    const float* Wi     = (const float*)d_in[6];
    const float* bi     = (const float*)d_in[7];
    const float* Wg     = (const float*)d_in[8];
    const float* Gi     = (const float*)d_in[9];
    const float* gb     = (const float*)d_in[10];
    const float* Gh     = (const float*)d_in[11];
    const float* Ga     = (const float*)d_in[12];
    const float* lns    = (const float*)d_in[13];
    const float* lnb    = (const float*)d_in[14];
    float* out = (float*)d_out;

    float *hb0, *hb1, *cb0, *cb1, *proj, *zb, *ph;
    float *pi, *pa, *ig, *og, *gh, *gc, *havg, *gWg, *pnum, *pden, *invms;
    __nv_bfloat16 *chi, *clo, *hh0, *hl0, *hh1, *hl1, *inh, *inl;
    __nv_bfloat16 *w3h, *w3l, *ghh, *ghl, *wih, *wil;
    cudaGetSymbolAddress((void**)&hb0,  d_hbuf0);
    cudaGetSymbolAddress((void**)&hb1,  d_hbuf1);
    cudaGetSymbolAddress((void**)&cb0,  d_cbuf0);
    cudaGetSymbolAddress((void**)&cb1,  d_cbuf1);
    cudaGetSymbolAddress((void**)&proj, d_proj);
    cudaGetSymbolAddress((void**)&zb,   d_zbuf);
    cudaGetSymbolAddress((void**)&ph,   d_ph);
    cudaGetSymbolAddress((void**)&pi,   d_pi);
    cudaGetSymbolAddress((void**)&pa,   d_pa);
    cudaGetSymbolAddress((void**)&ig,   d_igb);
    cudaGetSymbolAddress((void**)&og,   d_ogb);
    cudaGetSymbolAddress((void**)&gh,   d_gh);
    cudaGetSymbolAddress((void**)&gc,   d_gcv);
    cudaGetSymbolAddress((void**)&havg, d_havg);
    cudaGetSymbolAddress((void**)&gWg,  d_gWg);
    cudaGetSymbolAddress((void**)&pnum, d_pnum);
    cudaGetSymbolAddress((void**)&pden, d_pden);
    cudaGetSymbolAddress((void**)&invms, d_invms);
    cudaGetSymbolAddress((void**)&chi, d_ctx_hi);
    cudaGetSymbolAddress((void**)&clo, d_ctx_lo);
    cudaGetSymbolAddress((void**)&hh0, d_h_hi0);
    cudaGetSymbolAddress((void**)&hl0, d_h_lo0);
    cudaGetSymbolAddress((void**)&hh1, d_h_hi1);
    cudaGetSymbolAddress((void**)&hl1, d_h_lo1);
    cudaGetSymbolAddress((void**)&inh, d_in_hi);
    cudaGetSymbolAddress((void**)&inl, d_in_lo);
    cudaGetSymbolAddress((void**)&w3h, d_W3T_hi);
    cudaGetSymbolAddress((void**)&w3l, d_W3T_lo);
    cudaGetSymbolAddress((void**)&ghh, d_GhT_hi);
    cudaGetSymbolAddress((void**)&ghl, d_GhT_lo);
    cudaGetSymbolAddress((void**)&wih, d_WiT_hi);
    cudaGetSymbolAddress((void**)&wil, d_WiT_lo);

    cudaFuncSetAttribute(k_hmma, cudaFuncAttributeMaxDynamicSharedMemorySize, HSMEM);

    // layer-invariant precompute
    k_invms<<<Bb, 256>>>(mask, invms);
    k_meanp<<<dim3(NCH, Bb), 256>>>(ih, mask, pnum);
    k_meanf<<<Bb, 256>>>(pnum, invms, gh);
    k_meanp<<<dim3(NCH, Bb), 256>>>(ic, mask, pnum);
    k_meanf<<<Bb, 256>>>(pnum, invms, gc);
    k_w3t<<<(H7 * H3 + 255) / 256, 256>>>(Wc, Wh, w3h, w3l);
    k_wt<<<(Hh * Hh + 255) / 256, 256>>>(Gh, Hh, Hh, ghh, ghl);
    k_wt<<<(H7 * Hh + 255) / 256, 256>>>(Wi, Hh, H7, wih, wil);
    k_split<<<(BSR * Hh + 255) / 256, 256>>>(ih, hh0, hl0, BSR * Hh);
    k_split<<<(BSR * Hh + 255) / 256, 256>>>(inputs, inh, inl, BSR * Hh);
    k_hmma<<<dim3(H7 / 128, BSR / 128), 256, HSMEM>>>(
        BSR, H7, Hh, inh, inl, wih, wil, bi, proj);

    float* hbufs[2] = { hb0, hb1 };
    float* cbufs[2] = { cb0, cb1 };
    __nv_bfloat16* hhis[2] = { hh0, hh1 };
    __nv_bfloat16* hlos[2] = { hl0, hl1 };

    for (int l = 0; l < LL; l++) {
        const float* hid = (l == 0) ? ih : hbufs[l & 1];
        const float* cel = (l == 0) ? ic : cbufs[l & 1];
        const __nv_bfloat16* hhi = hhis[l & 1];
        const __nv_bfloat16* hlo = hlos[l & 1];
        float* hout = (l == LL - 1) ? out : hbufs[(l + 1) & 1];
        float* cout = cbufs[(l + 1) & 1];

        // ---- global state ----
        k_meanp<<<dim3(NCH, Bb), 256>>>(hid, mask, pnum);
        k_meanf<<<Bb, 256>>>(pnum, invms, havg);
        k_smallgemm<<<(Bb * H3 + 255) / 256, 256>>>(Bb, H3, Hh, gh, Gi, gb, pi);
        k_smallgemm<<<(Bb * 2 * Hh + 255) / 256, 256>>>(Bb, 2 * Hh, Hh, havg, Ga,
                                                        (const float*)nullptr, pa);
        k_igog<<<Bb, 256>>>(pi, pa, lns, lnb, ig, og);
        k_hmma<<<dim3(Hh / 128, BSR / 128), 256, HSMEM>>>(
            BSR, Hh, Hh, hhi, hlo, ghh, ghl, (const float*)nullptr, ph);
        k_hg<<<BSR, 256>>>(ph, pi, mask, lns, lnb, ph);
        k_gcp<<<dim3(NCH, Bb), 256>>>(ph, cel, pnum, pden);
        k_gcf<<<Bb, 256>>>(pnum, pden, ig, og, gc, gh);
        k_smallgemm<<<(Bb * H7 + 255) / 256, 256>>>(Bb, H7, Hh, gh, Wg,
                                                    (const float*)nullptr, gWg);

        // ---- per-word state ----
        k_ctx_bf<<<(BSR * (H3 / 8) + 255) / 256, 256>>>(hhi, hlo, chi, clo);
        k_hmma<<<dim3(H7 / 128, BSR / 128), 256, HSMEM>>>(
            BSR, H7, H3, chi, clo, w3h, w3l, (const float*)nullptr, zb);
        k_update<<<BSR, 256>>>(zb, proj, gWg, gc, mask, lns, lnb, cel, hout, cout,
                               hhis[(l + 1) & 1], hlos[(l + 1) & 1]);
    }
}

// round 7
// speedup vs baseline: 1.6500x; 1.0848x over previous
#include <cuda_runtime.h>
#include <cuda_bf16.h>
#include <cstdint>
#include <cstddef>

// Problem constants
#define Bb 8
#define Ss 1024
#define Hh 256
#define LL 7
#define BSR (Bb*Ss)        // 8192 rows
#define H7 (7*Hh)          // 1792
#define H3 (3*Hh)          // 768
#define NCH 64
#define SCH (Ss/NCH)       // 16

// ---------------- scratch (device globals; no allocations allowed) ----------
__device__ float d_hbuf0[BSR*Hh];
__device__ float d_hbuf1[BSR*Hh];
__device__ float d_cbuf0[BSR*Hh];
__device__ float d_cbuf1[BSR*Hh];
__device__ float d_proj[(size_t)BSR*H7];
__device__ float d_zbuf[(size_t)BSR*H7];
__device__ float d_ph[BSR*Hh];
__device__ float d_pi[Bb*H3];
__device__ float d_pa[Bb*2*Hh];
__device__ float d_igb[Bb*Hh];
__device__ float d_ogb[Bb*Hh];
__device__ float d_gh[Bb*Hh];
__device__ float d_gcv[Bb*Hh];
__device__ float d_havg[Bb*Hh];
__device__ float d_gWg[Bb*H7];
__device__ float d_pnum[Bb*NCH*Hh];
__device__ float d_pden[Bb*NCH*Hh];
__device__ float d_invms[Bb];
// split-bf16 activations / weights (16B aligned for uint4 / cp.async)
__device__ __align__(16) __nv_bfloat16 d_ctx_hi[(size_t)BSR*H3];
__device__ __align__(16) __nv_bfloat16 d_ctx_lo[(size_t)BSR*H3];
__device__ __align__(16) __nv_bfloat16 d_h_hi0[BSR*Hh];
__device__ __align__(16) __nv_bfloat16 d_h_lo0[BSR*Hh];
__device__ __align__(16) __nv_bfloat16 d_h_hi1[BSR*Hh];
__device__ __align__(16) __nv_bfloat16 d_h_lo1[BSR*Hh];
__device__ __align__(16) __nv_bfloat16 d_in_hi[BSR*Hh];
__device__ __align__(16) __nv_bfloat16 d_in_lo[BSR*Hh];
__device__ __align__(16) __nv_bfloat16 d_W3T_hi[H7*H3];
__device__ __align__(16) __nv_bfloat16 d_W3T_lo[H7*H3];
__device__ __align__(16) __nv_bfloat16 d_GhT_hi[Hh*Hh];
__device__ __align__(16) __nv_bfloat16 d_GhT_lo[Hh*Hh];
__device__ __align__(16) __nv_bfloat16 d_WiT_hi[H7*Hh];
__device__ __align__(16) __nv_bfloat16 d_WiT_lo[H7*Hh];

// ---------------- PTX helpers -----------------------------------------------
__device__ __forceinline__ uint32_t smem_u32(const void* p) {
    uint32_t a;
    asm("{ .reg .u64 t; cvta.to.shared.u64 t, %1; cvt.u32.u64 %0, t; }"
        : "=r"(a) : "l"(p));
    return a;
}
__device__ __forceinline__ void cpasync16(uint32_t dst, const void* src) {
    asm volatile("cp.async.cg.shared.global [%0], [%1], 16;" :: "r"(dst), "l"(src));
}
#define CP_COMMIT() asm volatile("cp.async.commit_group;" ::: "memory")
#define CP_WAIT1()  asm volatile("cp.async.wait_group 1;" ::: "memory")
#define CP_WAIT0()  asm volatile("cp.async.wait_group 0;" ::: "memory")

__device__ __forceinline__ void mma16816(float* c, const uint32_t* a, const uint32_t* b) {
    asm volatile(
        "mma.sync.aligned.m16n8k16.row.col.f32.bf16.bf16.f32 "
        "{%0,%1,%2,%3}, {%4,%5,%6,%7}, {%8,%9}, {%0,%1,%2,%3};"
        : "+f"(c[0]), "+f"(c[1]), "+f"(c[2]), "+f"(c[3])
        : "r"(a[0]), "r"(a[1]), "r"(a[2]), "r"(a[3]), "r"(b[0]), "r"(b[1]));
}

// ---------------- bf16x3 HMMA GEMM (proven version, scalar LDS) --------------
#define KB 32
#define SA 40                      // padded smem row stride (halves)
#define MTILE (128*SA)
#define STAGE (4*MTILE)            // Ahi, Alo, Bhi, Blo
#define HSMEM (2*STAGE*2)          // 81920 bytes

__global__ void __launch_bounds__(256, 1) k_hmma(
    int M, int N, int K,
    const __nv_bfloat16* __restrict__ Ahi, const __nv_bfloat16* __restrict__ Alo,
    const __nv_bfloat16* __restrict__ Bhi, const __nv_bfloat16* __restrict__ Blo,
    const float* __restrict__ bias, float* __restrict__ C)
{
    extern __shared__ __nv_bfloat16 sm[];
    int tid = threadIdx.x, wid = tid >> 5, lane = tid & 31;
    int gID = lane >> 2, tg = lane & 3;
    int warp_m = wid >> 2, warp_n = wid & 3;
    int arow0 = blockIdx.y * 128, bcol0 = blockIdx.x * 128;

    const __nv_bfloat16* srcs[4] = {
        Ahi + (size_t)arow0 * K, Alo + (size_t)arow0 * K,
        Bhi + (size_t)bcol0 * K, Blo + (size_t)bcol0 * K };

    float acc[4][4][4];
    #pragma unroll
    for (int mi = 0; mi < 4; mi++)
        #pragma unroll
        for (int ni = 0; ni < 4; ni++)
            #pragma unroll
            for (int q = 0; q < 4; q++) acc[mi][ni][q] = 0.f;

    uint32_t smbase = smem_u32(sm);
    int niter = K / KB;

    // prologue: stage 0
    #pragma unroll
    for (int t = 0; t < 4; t++) {
        const __nv_bfloat16* src = srcs[t];
        uint32_t dst = smbase + (0 * STAGE + t * MTILE) * 2;
        #pragma unroll
        for (int s = 0; s < 2; s++) {
            int slot = tid + s * 256;
            int row = slot >> 2, cg = (slot & 3) * 8;
            cpasync16(dst + (row * SA + cg) * 2, src + (size_t)row * K + cg);
        }
    }
    CP_COMMIT();

    for (int it = 0; it < niter; it++) {
        if (it + 1 < niter) {
            int st = (it + 1) & 1;
            int k0 = (it + 1) * KB;
            #pragma unroll
            for (int t = 0; t < 4; t++) {
                const __nv_bfloat16* src = srcs[t] + k0;
                uint32_t dst = smbase + (st * STAGE + t * MTILE) * 2;
                #pragma unroll
                for (int s = 0; s < 2; s++) {
                    int slot = tid + s * 256;
                    int row = slot >> 2, cg = (slot & 3) * 8;
                    cpasync16(dst + (row * SA + cg) * 2, src + (size_t)row * K + cg);
                }
            }
            CP_COMMIT();
            CP_WAIT1();
        } else {
            CP_WAIT0();
        }
        __syncthreads();

        const __nv_bfloat16* As_h = sm + (it & 1) * STAGE;
        const __nv_bfloat16* As_l = As_h + MTILE;
        const __nv_bfloat16* Bs_h = As_h + 2 * MTILE;
        const __nv_bfloat16* Bs_l = As_h + 3 * MTILE;

        #pragma unroll
        for (int kk = 0; kk < KB; kk += 16) {
            uint32_t bh[4][2], bl[4][2];
            #pragma unroll
            for (int ni = 0; ni < 4; ni++) {
                int n = warp_n * 32 + ni * 8 + gID;
                const __nv_bfloat16* ph_ = Bs_h + n * SA + kk + tg * 2;
                const __nv_bfloat16* pl_ = Bs_l + n * SA + kk + tg * 2;
                bh[ni][0] = *(const uint32_t*)ph_;
                bh[ni][1] = *(const uint32_t*)(ph_ + 8);
                bl[ni][0] = *(const uint32_t*)pl_;
                bl[ni][1] = *(const uint32_t*)(pl_ + 8);
            }
            #pragma unroll
            for (int mi = 0; mi < 4; mi++) {
                int r0 = warp_m * 64 + mi * 16 + gID;
                const __nv_bfloat16* ah_ = As_h + r0 * SA + kk + tg * 2;
                const __nv_bfloat16* al_ = As_l + r0 * SA + kk + tg * 2;
                uint32_t ah[4], al[4];
                ah[0] = *(const uint32_t*)ah_;
                ah[1] = *(const uint32_t*)(ah_ + 8 * SA);
                ah[2] = *(const uint32_t*)(ah_ + 8);
                ah[3] = *(const uint32_t*)(ah_ + 8 * SA + 8);
                al[0] = *(const uint32_t*)al_;
                al[1] = *(const uint32_t*)(al_ + 8 * SA);
                al[2] = *(const uint32_t*)(al_ + 8);
                al[3] = *(const uint32_t*)(al_ + 8 * SA + 8);
                #pragma unroll
                for (int ni = 0; ni < 4; ni++) {
                    mma16816(acc[mi][ni], ah, bh[ni]);
                    mma16816(acc[mi][ni], ah, bl[ni]);
                    mma16816(acc[mi][ni], al, bh[ni]);
                }
            }
        }
        __syncthreads();
    }

    // epilogue
    #pragma unroll
    for (int mi = 0; mi < 4; mi++) {
        #pragma unroll
        for (int ni = 0; ni < 4; ni++) {
            int r = arow0 + warp_m * 64 + mi * 16 + gID;
            int c = bcol0 + warp_n * 32 + ni * 8 + tg * 2;
            float b0 = bias ? bias[c] : 0.f;
            float b1 = bias ? bias[c + 1] : 0.f;
            float2 v0 = make_float2(acc[mi][ni][0] + b0, acc[mi][ni][1] + b1);
            float2 v1 = make_float2(acc[mi][ni][2] + b0, acc[mi][ni][3] + b1);
            *(float2*)(C + (size_t)r * N + c) = v0;
            *(float2*)(C + (size_t)(r + 8) * N + c) = v1;
        }
    }
}

// ---------------- helpers ----------------------------------------------------
__device__ __forceinline__ float2 blockSum2(float a, float b, float* sh) {
    #pragma unroll
    for (int o = 16; o > 0; o >>= 1) {
        a += __shfl_down_sync(0xffffffffu, a, o);
        b += __shfl_down_sync(0xffffffffu, b, o);
    }
    int w = threadIdx.x >> 5, l = threadIdx.x & 31;
    if (l == 0) { sh[w] = a; sh[8 + w] = b; }
    __syncthreads();
    if (threadIdx.x == 0) {
        float sa = 0.f, sb2 = 0.f;
        #pragma unroll
        for (int i = 0; i < 8; i++) { sa += sh[i]; sb2 += sh[8 + i]; }
        sh[16] = sa; sh[17] = sb2;
    }
    __syncthreads();
    float2 r = make_float2(sh[16], sh[17]);
    __syncthreads();
    return r;
}
__device__ __forceinline__ float sigmoidf_(float x) { return 1.f / (1.f + expf(-x)); }
__device__ __forceinline__ void splitbf(float v, __nv_bfloat16& hi, __nv_bfloat16& lo) {
    hi = __float2bfloat16(v);
    lo = __float2bfloat16(v - __bfloat162float(hi));
}

// ---------------- split / transpose kernels ----------------------------------
__global__ void k_split(const float* __restrict__ x, __nv_bfloat16* __restrict__ hi,
                        __nv_bfloat16* __restrict__ lo, int n)
{
    int i = blockIdx.x * blockDim.x + threadIdx.x;
    if (i >= n) return;
    splitbf(x[i], hi[i], lo[i]);
}

__global__ void k_w3t(const float* __restrict__ Wc, const float* __restrict__ Wh,
                      __nv_bfloat16* __restrict__ hi, __nv_bfloat16* __restrict__ lo)
{
    int i = blockIdx.x * blockDim.x + threadIdx.x;   // [H7 x H3]
    if (i >= H7 * H3) return;
    int n = i / H3, k = i % H3;
    float v = (k < Hh) ? Wc[(size_t)k * H7 + n]
            : (k < 2 * Hh) ? Wh[(size_t)(k - Hh) * H7 + n]
            : Wc[(size_t)(k - Hh) * H7 + n];
    splitbf(v, hi[i], lo[i]);
}

__global__ void k_wt(const float* __restrict__ W, int K, int N,
                     __nv_bfloat16* __restrict__ hi, __nv_bfloat16* __restrict__ lo)
{
    int i = blockIdx.x * blockDim.x + threadIdx.x;   // [N x K]
    if (i >= N * K) return;
    int n = i / K, k = i % K;
    splitbf(W[(size_t)k * N + n], hi[i], lo[i]);
}

// ---------------- tiny GEMM for M=8 rows -------------------------------------
__global__ void k_smallgemm(int M, int N, int K,
                            const float* __restrict__ A, const float* __restrict__ W,
                            const float* __restrict__ bias, float* __restrict__ C)
{
    int idx = blockIdx.x * blockDim.x + threadIdx.x;
    if (idx >= M * N) return;
    int m = idx / N, n = idx % N;
    float acc = bias ? bias[n] : 0.f;
    const float* a = A + (size_t)m * K;
    for (int k = 0; k < K; k++) acc += a[k] * W[(size_t)k * N + n];
    C[idx] = acc;
}

// ---------------- small kernels ----------------------------------------------
__global__ void k_invms(const float* __restrict__ mask, float* __restrict__ invms)
{
    __shared__ float sh[8];
    int b = blockIdx.x, t = threadIdx.x;
    float a = 0.f;
    for (int s = t; s < Ss; s += 256) a += mask[b * Ss + s];
    #pragma unroll
    for (int o = 16; o > 0; o >>= 1) a += __shfl_down_sync(0xffffffffu, a, o);
    if ((t & 31) == 0) sh[t >> 5] = a;
    __syncthreads();
    if (t == 0) {
        float s2 = 0.f;
        #pragma unroll
        for (int i = 0; i < 8; i++) s2 += sh[i];
        invms[b] = 1.f / s2;
    }
}

__global__ void k_meanp(const float* __restrict__ x, const float* __restrict__ mask,
                        float* __restrict__ pnum)
{
    int ch = blockIdx.x, b = blockIdx.y, h = threadIdx.x;
    float acc = 0.f;
    int s0 = ch * SCH;
    #pragma unroll
    for (int i = 0; i < SCH; i++) {
        int s = s0 + i;
        acc += x[((size_t)(b * Ss + s)) * Hh + h] * mask[b * Ss + s];
    }
    pnum[(b * NCH + ch) * Hh + h] = acc;
}

__global__ void k_meanf(const float* __restrict__ pnum, const float* __restrict__ invms,
                        float* __restrict__ out)
{
    int b = blockIdx.x, h = threadIdx.x;
    float a = 0.f;
    #pragma unroll
    for (int c = 0; c < NCH; c++) a += pnum[(b * NCH + c) * Hh + h];
    out[b * Hh + h] = a * invms[b];
}

__global__ void k_igog(const float* __restrict__ pi, const float* __restrict__ pa,
                       const float* __restrict__ lns, const float* __restrict__ lnb,
                       float* __restrict__ ig, float* __restrict__ og)
{
    __shared__ float sh[18];
    int b = blockIdx.x, h = threadIdx.x;
    float v = pi[b * H3 + h] + pa[b * 2 * Hh + h];
    float2 ssum = blockSum2(v, v * v, sh);
    float m = ssum.x * (1.f / 256.f);
    float var = (ssum.y - 256.f * m * m) * (1.f / 255.f);
    float zn = lns[h] * (v - m) * rsqrtf(var + 1e-6f) + lnb[h];
    ig[b * Hh + h] = sigmoidf_(zn);
    v = pi[b * H3 + 2 * Hh + h] + pa[b * 2 * Hh + Hh + h];
    ssum = blockSum2(v, v * v, sh);
    m = ssum.x * (1.f / 256.f);
    var = (ssum.y - 256.f * m * m) * (1.f / 255.f);
    zn = lns[2 * Hh + h] * (v - m) * rsqrtf(var + 1e-6f) + lnb[2 * Hh + h];
    og[b * Hh + h] = sigmoidf_(zn);
}

__global__ void k_hg(const float* __restrict__ ph, const float* __restrict__ pi,
                     const float* __restrict__ mask,
                     const float* __restrict__ lns, const float* __restrict__ lnb,
                     float* __restrict__ hg)
{
    __shared__ float sh[18];
    int bs = blockIdx.x; int b = bs >> 10;
    int h = threadIdx.x;
    float v = ph[(size_t)bs * Hh + h] + pi[b * H3 + Hh + h];
    float2 ssum = blockSum2(v, v * v, sh);
    float m = ssum.x * (1.f / 256.f);
    float var = (ssum.y - 256.f * m * m) * (1.f / 255.f);
    float zn = lns[Hh + h] * (v - m) * rsqrtf(var + 1e-6f) + lnb[Hh + h];
    hg[(size_t)bs * Hh + h] = sigmoidf_(zn) + (mask[bs] * 1e25f - 1e25f);
}

__global__ void k_gcp(const float* __restrict__ hg, const float* __restrict__ cell,
                      float* __restrict__ pnum, float* __restrict__ pden)
{
    int ch = blockIdx.x, b = blockIdx.y, h = threadIdx.x;
    float num = 0.f, den = 0.f;
    int s0 = ch * SCH;
    #pragma unroll
    for (int i = 0; i < SCH; i++) {
        size_t idx = ((size_t)(b * Ss + s0 + i)) * Hh + h;
        float e = expf(hg[idx]);
        num += e * cell[idx];
        den += e;
    }
    pnum[(b * NCH + ch) * Hh + h] = num;
    pden[(b * NCH + ch) * Hh + h] = den;
}

__global__ void k_gcf(const float* __restrict__ pnum, const float* __restrict__ pden,
                      const float* __restrict__ ig, const float* __restrict__ og,
                      float* __restrict__ gc, float* __restrict__ gh)
{
    int b = blockIdx.x, h = threadIdx.x;
    float num = 0.f, den = 0.f;
    #pragma unroll
    for (int c = 0; c < NCH; c++) {
        num += pnum[(b * NCH + c) * Hh + h];
        den += pden[(b * NCH + c) * Hh + h];
    }
    float ei = expf(ig[b * Hh + h]);
    float g = (gc[b * Hh + h] * ei + num) / (ei + den);
    gc[b * Hh + h] = g;
    gh[b * Hh + h] = og[b * Hh + h] * tanhf(g);
}

// build split-bf16 ctx = [h_l, h, h_r] directly from split-bf16 hidden
__global__ void k_ctx_bf(const __nv_bfloat16* __restrict__ hhi,
                         const __nv_bfloat16* __restrict__ hlo,
                         __nv_bfloat16* __restrict__ chi,
                         __nv_bfloat16* __restrict__ clo)
{
    int i = blockIdx.x * blockDim.x + threadIdx.x;  // 8-elem chunk
    if (i >= BSR * (H3 / 8)) return;
    int bs = i / (H3 / 8);
    int j = (i % (H3 / 8)) * 8;
    int s = bs & (Ss - 1);
    uint4 vh = make_uint4(0, 0, 0, 0), vl = make_uint4(0, 0, 0, 0);
    long off = -1;
    if (j < Hh)           { if (s > 0)      off = ((long)bs - 1) * Hh + j; }
    else if (j < 2 * Hh)  {                 off = (long)bs * Hh + (j - Hh); }
    else                  { if (s < Ss - 1) off = ((long)bs + 1) * Hh + (j - 2 * Hh); }
    if (off >= 0) {
        vh = *(const uint4*)(hhi + off);
        vl = *(const uint4*)(hlo + off);
    }
    *(uint4*)(chi + (size_t)bs * H3 + j) = vh;
    *(uint4*)(clo + (size_t)bs * H3 + j) = vl;
}

// one-pass LN for all 7 groups: 2 barriers instead of 21
__global__ __launch_bounds__(256) void k_update(
    const float* __restrict__ z, const float* __restrict__ proj,
    const float* __restrict__ gWg, const float* __restrict__ gc,
    const float* __restrict__ mask,
    const float* __restrict__ lns, const float* __restrict__ lnb,
    const float* __restrict__ c_old,
    float* __restrict__ h_new, float* __restrict__ c_new,
    __nv_bfloat16* __restrict__ hhi, __nv_bfloat16* __restrict__ hlo)
{
    __shared__ float wsum[8][14];
    __shared__ float fin[14];
    int bs = blockIdx.x; int b = bs >> 10; int s = bs & (Ss - 1);
    int h = threadIdx.x;
    int w = h >> 5, lane = h & 31;
    size_t rz = (size_t)bs * H7;
    float v[7];
    #pragma unroll
    for (int k = 0; k < 7; k++)
        v[k] = z[rz + k * Hh + h] + proj[rz + k * Hh + h] + gWg[b * H7 + k * Hh + h];

    float p[14];
    #pragma unroll
    for (int k = 0; k < 7; k++) { p[2 * k] = v[k]; p[2 * k + 1] = v[k] * v[k]; }
    #pragma unroll
    for (int o = 16; o > 0; o >>= 1)
        #pragma unroll
        for (int j = 0; j < 14; j++)
            p[j] += __shfl_down_sync(0xffffffffu, p[j], o);
    if (lane == 0)
        #pragma unroll
        for (int j = 0; j < 14; j++) wsum[w][j] = p[j];
    __syncthreads();
    if (h < 14) {
        float a = 0.f;
        #pragma unroll
        for (int i = 0; i < 8; i++) a += wsum[i][h];
        fin[h] = a;
    }
    __syncthreads();

    float zn[7];
    #pragma unroll
    for (int k = 0; k < 7; k++) {
        float m = fin[2 * k] * (1.f / 256.f);
        float var = (fin[2 * k + 1] - 256.f * m * m) * (1.f / 255.f);
        zn[k] = lns[(3 + k) * Hh + h] * (v[k] - m) * rsqrtf(var + 1e-6f) + lnb[(3 + k) * Hh + h];
    }
    float e[6], den = 0.f;
    #pragma unroll
    for (int k = 0; k < 6; k++) {
        e[k] = expf(sigmoidf_(zn[k]));
        den += e[k];
    }
    float inv = 1.f / den;
    float mem = tanhf(zn[6]);
    size_t idx = (size_t)bs * Hh + h;
    float c  = c_old[idx];
    float cl = (s > 0)      ? c_old[idx - Hh] : 0.f;
    float cr = (s < Ss - 1) ? c_old[idx + Hh] : 0.f;
    float cn = (e[1] * cl + e[2] * cr + e[3] * c + e[0] * mem + e[4] * gc[b * Hh + h]) * inv;
    float mk = mask[bs];
    float hv = e[5] * inv * tanhf(cn) * mk;
    h_new[idx] = hv;
    c_new[idx] = cn * mk;
    splitbf(hv, hhi[idx], hlo[idx]);
}

// ---------------- orchestration ----------------------------------------------
extern "C" void kernel_launch(void* const* d_in, const int* in_sizes, int n_in,
                              void* d_out, int out_size)
{
    (void)in_sizes; (void)n_in; (void)out_size;
    const float* inputs = (const float*)d_in[0];
    const float* mask   = (const float*)d_in[1];
    const float* ih     = (const float*)d_in[2];
    const float* ic     = (const float*)d_in[3];
    const float* Wc     = (const float*)d_in[4];
    const float* Wh     = (const float*)d_in[5];
    const float* Wi     = (const float*)d_in[6];
    const float* bi     = (const float*)d_in[7];
    const float* Wg     = (const float*)d_in[8];
    const float* Gi     = (const float*)d_in[9];
    const float* gb     = (const float*)d_in[10];
    const float* Gh     = (const float*)d_in[11];
    const float* Ga     = (const float*)d_in[12];
    const float* lns    = (const float*)d_in[13];
    const float* lnb    = (const float*)d_in[14];
    float* out = (float*)d_out;

    float *hb0, *hb1, *cb0, *cb1, *proj, *zb, *ph;
    float *pi, *pa, *ig, *og, *gh, *gc, *havg, *gWg, *pnum, *pden, *invms;
    __nv_bfloat16 *chi, *clo, *hh0, *hl0, *hh1, *hl1, *inh, *inl;
    __nv_bfloat16 *w3h, *w3l, *ghh, *ghl, *wih, *wil;
    cudaGetSymbolAddress((void**)&hb0,  d_hbuf0);
    cudaGetSymbolAddress((void**)&hb1,  d_hbuf1);
    cudaGetSymbolAddress((void**)&cb0,  d_cbuf0);
    cudaGetSymbolAddress((void**)&cb1,  d_cbuf1);
    cudaGetSymbolAddress((void**)&proj, d_proj);
    cudaGetSymbolAddress((void**)&zb,   d_zbuf);
    cudaGetSymbolAddress((void**)&ph,   d_ph);
    cudaGetSymbolAddress((void**)&pi,   d_pi);
    cudaGetSymbolAddress((void**)&pa,   d_pa);
    cudaGetSymbolAddress((void**)&ig,   d_igb);
    cudaGetSymbolAddress((void**)&og,   d_ogb);
    cudaGetSymbolAddress((void**)&gh,   d_gh);
    cudaGetSymbolAddress((void**)&gc,   d_gcv);
    cudaGetSymbolAddress((void**)&havg, d_havg);
    cudaGetSymbolAddress((void**)&gWg,  d_gWg);
    cudaGetSymbolAddress((void**)&pnum, d_pnum);
    cudaGetSymbolAddress((void**)&pden, d_pden);
    cudaGetSymbolAddress((void**)&invms, d_invms);
    cudaGetSymbolAddress((void**)&chi, d_ctx_hi);
    cudaGetSymbolAddress((void**)&clo, d_ctx_lo);
    cudaGetSymbolAddress((void**)&hh0, d_h_hi0);
    cudaGetSymbolAddress((void**)&hl0, d_h_lo0);
    cudaGetSymbolAddress((void**)&hh1, d_h_hi1);
    cudaGetSymbolAddress((void**)&hl1, d_h_lo1);
    cudaGetSymbolAddress((void**)&inh, d_in_hi);
    cudaGetSymbolAddress((void**)&inl, d_in_lo);
    cudaGetSymbolAddress((void**)&w3h, d_W3T_hi);
    cudaGetSymbolAddress((void**)&w3l, d_W3T_lo);
    cudaGetSymbolAddress((void**)&ghh, d_GhT_hi);
    cudaGetSymbolAddress((void**)&ghl, d_GhT_lo);
    cudaGetSymbolAddress((void**)&wih, d_WiT_hi);
    cudaGetSymbolAddress((void**)&wil, d_WiT_lo);

    cudaFuncSetAttribute(k_hmma, cudaFuncAttributeMaxDynamicSharedMemorySize, HSMEM);

    // streams/events created once in the (uncaptured) correctness call,
    // reused by the capture call. No device memory involved.
    static cudaStream_t s2 = [] {
        cudaStream_t s; cudaStreamCreateWithFlags(&s, cudaStreamNonBlocking); return s;
    }();
    static cudaEvent_t evFork = [] {
        cudaEvent_t e; cudaEventCreateWithFlags(&e, cudaEventDisableTiming); return e;
    }();
    static cudaEvent_t evJoin = [] {
        cudaEvent_t e; cudaEventCreateWithFlags(&e, cudaEventDisableTiming); return e;
    }();

    // layer-invariant precompute (main stream)
    k_invms<<<Bb, 256>>>(mask, invms);
    k_meanp<<<dim3(NCH, Bb), 256>>>(ih, mask, pnum);
    k_meanf<<<Bb, 256>>>(pnum, invms, gh);
    k_meanp<<<dim3(NCH, Bb), 256>>>(ic, mask, pnum);
    k_meanf<<<Bb, 256>>>(pnum, invms, gc);
    k_w3t<<<(H7 * H3 + 255) / 256, 256>>>(Wc, Wh, w3h, w3l);
    k_wt<<<(Hh * Hh + 255) / 256, 256>>>(Gh, Hh, Hh, ghh, ghl);
    k_wt<<<(H7 * Hh + 255) / 256, 256>>>(Wi, Hh, H7, wih, wil);
    k_split<<<(BSR * Hh + 255) / 256, 256>>>(ih, hh0, hl0, BSR * Hh);
    k_split<<<(BSR * Hh + 255) / 256, 256>>>(inputs, inh, inl, BSR * Hh);
    k_hmma<<<dim3(H7 / 128, BSR / 128), 256, HSMEM>>>(
        BSR, H7, Hh, inh, inl, wih, wil, bi, proj);

    float* hbufs[2] = { hb0, hb1 };
    float* cbufs[2] = { cb0, cb1 };
    __nv_bfloat16* hhis[2] = { hh0, hh1 };
    __nv_bfloat16* hlos[2] = { hl0, hl1 };

    for (int l = 0; l < LL; l++) {
        const float* hid = (l == 0) ? ih : hbufs[l & 1];
        const float* cel = (l == 0) ? ic : cbufs[l & 1];
        const __nv_bfloat16* hhi = hhis[l & 1];
        const __nv_bfloat16* hlo = hlos[l & 1];
        float* hout = (l == LL - 1) ? out : hbufs[(l + 1) & 1];
        float* cout = cbufs[(l + 1) & 1];

        // fork: z-branch (ctx + z-GEMM) depends only on hidden from prev update
        cudaEventRecord(evFork, 0);
        cudaStreamWaitEvent(s2, evFork, 0);
        k_ctx_bf<<<(BSR * (H3 / 8) + 255) / 256, 256, 0, s2>>>(hhi, hlo, chi, clo);
        k_hmma<<<dim3(H7 / 128, BSR / 128), 256, HSMEM, s2>>>(
            BSR, H7, H3, chi, clo, w3h, w3l, (const float*)nullptr, zb);
        cudaEventRecord(evJoin, s2);

        // ---- global state chain (main stream, concurrent with z-branch) ----
        k_meanp<<<dim3(NCH, Bb), 256>>>(hid, mask, pnum);
        k_meanf<<<Bb, 256>>>(pnum, invms, havg);
        k_smallgemm<<<(Bb * H3 + 255) / 256, 256>>>(Bb, H3, Hh, gh, Gi, gb, pi);
        k_smallgemm<<<(Bb * 2 * Hh + 255) / 256, 256>>>(Bb, 2 * Hh, Hh, havg, Ga,
                                                        (const float*)nullptr, pa);
        k_igog<<<Bb, 256>>>(pi, pa, lns, lnb, ig, og);
        k_hmma<<<dim3(Hh / 128, BSR / 128), 256, HSMEM>>>(
            BSR, Hh, Hh, hhi, hlo, ghh, ghl, (const float*)nullptr, ph);
        k_hg<<<BSR, 256>>>(ph, pi, mask, lns, lnb, ph);
        k_gcp<<<dim3(NCH, Bb), 256>>>(ph, cel, pnum, pden);
        k_gcf<<<Bb, 256>>>(pnum, pden, ig, og, gc, gh);
        k_smallgemm<<<(Bb * H7 + 255) / 256, 256>>>(Bb, H7, Hh, gh, Wg,
                                                    (const float*)nullptr, gWg);

        // join: update needs z (s2) + gWg/gc (main)
        cudaStreamWaitEvent(0, evJoin, 0);
        k_update<<<BSR, 256>>>(zb, proj, gWg, gc, mask, lns, lnb, cel, hout, cout,
                               hhis[(l + 1) & 1], hlos[(l + 1) & 1]);
    }
}

// round 8
// speedup vs baseline: 1.8572x; 1.1256x over previous
#include <cuda_runtime.h>
#include <cuda_bf16.h>
#include <cstdint>
#include <cstddef>

// Problem constants
#define Bb 8
#define Ss 1024
#define Hh 256
#define LL 7
#define BSR (Bb*Ss)        // 8192 rows
#define H7 (7*Hh)          // 1792
#define H3 (3*Hh)          // 768
#define NCH 64
#define SCH (Ss/NCH)       // 16

// ---------------- scratch (device globals; no allocations allowed) ----------
__device__ float d_hbuf0[BSR*Hh];
__device__ float d_hbuf1[BSR*Hh];
__device__ float d_cbuf0[BSR*Hh];
__device__ float d_cbuf1[BSR*Hh];
__device__ float d_proj[(size_t)BSR*H7];
__device__ float d_zbuf[(size_t)BSR*H7];
__device__ float d_ph[BSR*Hh];
__device__ float d_pi[Bb*H3];
__device__ float d_pa[Bb*2*Hh];
__device__ float d_igb[Bb*Hh];
__device__ float d_ogb[Bb*Hh];
__device__ float d_gh[Bb*Hh];
__device__ float d_gcv[Bb*Hh];
__device__ float d_havg[Bb*Hh];
__device__ float d_gWg[Bb*H7];
__device__ float d_pnum[Bb*NCH*Hh];
__device__ float d_pden[Bb*NCH*Hh];
__device__ float d_invms[Bb];
// split-bf16 activations / weights (16B aligned for uint4 / cp.async)
__device__ __align__(16) __nv_bfloat16 d_ctx_hi[(size_t)BSR*H3];
__device__ __align__(16) __nv_bfloat16 d_ctx_lo[(size_t)BSR*H3];
__device__ __align__(16) __nv_bfloat16 d_h_hi0[BSR*Hh];
__device__ __align__(16) __nv_bfloat16 d_h_lo0[BSR*Hh];
__device__ __align__(16) __nv_bfloat16 d_h_hi1[BSR*Hh];
__device__ __align__(16) __nv_bfloat16 d_h_lo1[BSR*Hh];
__device__ __align__(16) __nv_bfloat16 d_in_hi[BSR*Hh];
__device__ __align__(16) __nv_bfloat16 d_in_lo[BSR*Hh];
__device__ __align__(16) __nv_bfloat16 d_W3T_hi[H7*H3];
__device__ __align__(16) __nv_bfloat16 d_W3T_lo[H7*H3];
__device__ __align__(16) __nv_bfloat16 d_GhT_hi[Hh*Hh];
__device__ __align__(16) __nv_bfloat16 d_GhT_lo[Hh*Hh];
__device__ __align__(16) __nv_bfloat16 d_WiT_hi[H7*Hh];
__device__ __align__(16) __nv_bfloat16 d_WiT_lo[H7*Hh];

// ---------------- PTX helpers -----------------------------------------------
__device__ __forceinline__ uint32_t smem_u32(const void* p) {
    uint32_t a;
    asm("{ .reg .u64 t; cvta.to.shared.u64 t, %1; cvt.u32.u64 %0, t; }"
        : "=r"(a) : "l"(p));
    return a;
}
__device__ __forceinline__ void cpasync16(uint32_t dst, const void* src) {
    asm volatile("cp.async.cg.shared.global [%0], [%1], 16;" :: "r"(dst), "l"(src));
}
#define CP_COMMIT() asm volatile("cp.async.commit_group;" ::: "memory")
#define CP_WAIT1()  asm volatile("cp.async.wait_group 1;" ::: "memory")
#define CP_WAIT0()  asm volatile("cp.async.wait_group 0;" ::: "memory")

__device__ __forceinline__ void mma16816(float* c, const uint32_t* a, const uint32_t* b) {
    asm volatile(
        "mma.sync.aligned.m16n8k16.row.col.f32.bf16.bf16.f32 "
        "{%0,%1,%2,%3}, {%4,%5,%6,%7}, {%8,%9}, {%0,%1,%2,%3};"
        : "+f"(c[0]), "+f"(c[1]), "+f"(c[2]), "+f"(c[3])
        : "r"(a[0]), "r"(a[1]), "r"(a[2]), "r"(a[3]), "r"(b[0]), "r"(b[1]));
}

// ---------------- bf16x3 HMMA GEMM (2 CTAs/SM for latency hiding) ------------
#define KB 32
#define SA 40                      // padded smem row stride (halves)
#define MTILE (128*SA)
#define STAGE (4*MTILE)            // Ahi, Alo, Bhi, Blo
#define HSMEM (2*STAGE*2)          // 81920 bytes

__global__ void __launch_bounds__(256, 2) k_hmma(
    int M, int N, int K,
    const __nv_bfloat16* __restrict__ Ahi, const __nv_bfloat16* __restrict__ Alo,
    const __nv_bfloat16* __restrict__ Bhi, const __nv_bfloat16* __restrict__ Blo,
    const float* __restrict__ bias, float* __restrict__ C)
{
    extern __shared__ __nv_bfloat16 sm[];
    int tid = threadIdx.x, wid = tid >> 5, lane = tid & 31;
    int gID = lane >> 2, tg = lane & 3;
    int warp_m = wid >> 2, warp_n = wid & 3;
    int arow0 = blockIdx.y * 128, bcol0 = blockIdx.x * 128;

    const __nv_bfloat16* srcs[4] = {
        Ahi + (size_t)arow0 * K, Alo + (size_t)arow0 * K,
        Bhi + (size_t)bcol0 * K, Blo + (size_t)bcol0 * K };

    float acc[4][4][4];
    #pragma unroll
    for (int mi = 0; mi < 4; mi++)
        #pragma unroll
        for (int ni = 0; ni < 4; ni++)
            #pragma unroll
            for (int q = 0; q < 4; q++) acc[mi][ni][q] = 0.f;

    uint32_t smbase = smem_u32(sm);
    int niter = K / KB;

    // prologue: stage 0
    #pragma unroll
    for (int t = 0; t < 4; t++) {
        const __nv_bfloat16* src = srcs[t];
        uint32_t dst = smbase + (0 * STAGE + t * MTILE) * 2;
        #pragma unroll
        for (int s = 0; s < 2; s++) {
            int slot = tid + s * 256;
            int row = slot >> 2, cg = (slot & 3) * 8;
            cpasync16(dst + (row * SA + cg) * 2, src + (size_t)row * K + cg);
        }
    }
    CP_COMMIT();

    for (int it = 0; it < niter; it++) {
        if (it + 1 < niter) {
            int st = (it + 1) & 1;
            int k0 = (it + 1) * KB;
            #pragma unroll
            for (int t = 0; t < 4; t++) {
                const __nv_bfloat16* src = srcs[t] + k0;
                uint32_t dst = smbase + (st * STAGE + t * MTILE) * 2;
                #pragma unroll
                for (int s = 0; s < 2; s++) {
                    int slot = tid + s * 256;
                    int row = slot >> 2, cg = (slot & 3) * 8;
                    cpasync16(dst + (row * SA + cg) * 2, src + (size_t)row * K + cg);
                }
            }
            CP_COMMIT();
            CP_WAIT1();
        } else {
            CP_WAIT0();
        }
        __syncthreads();

        const __nv_bfloat16* As_h = sm + (it & 1) * STAGE;
        const __nv_bfloat16* As_l = As_h + MTILE;
        const __nv_bfloat16* Bs_h = As_h + 2 * MTILE;
        const __nv_bfloat16* Bs_l = As_h + 3 * MTILE;

        #pragma unroll
        for (int kk = 0; kk < KB; kk += 16) {
            uint32_t bh[4][2], bl[4][2];
            #pragma unroll
            for (int ni = 0; ni < 4; ni++) {
                int n = warp_n * 32 + ni * 8 + gID;
                const __nv_bfloat16* ph_ = Bs_h + n * SA + kk + tg * 2;
                const __nv_bfloat16* pl_ = Bs_l + n * SA + kk + tg * 2;
                bh[ni][0] = *(const uint32_t*)ph_;
                bh[ni][1] = *(const uint32_t*)(ph_ + 8);
                bl[ni][0] = *(const uint32_t*)pl_;
                bl[ni][1] = *(const uint32_t*)(pl_ + 8);
            }
            #pragma unroll
            for (int mi = 0; mi < 4; mi++) {
                int r0 = warp_m * 64 + mi * 16 + gID;
                const __nv_bfloat16* ah_ = As_h + r0 * SA + kk + tg * 2;
                const __nv_bfloat16* al_ = As_l + r0 * SA + kk + tg * 2;
                uint32_t ah[4], al[4];
                ah[0] = *(const uint32_t*)ah_;
                ah[1] = *(const uint32_t*)(ah_ + 8 * SA);
                ah[2] = *(const uint32_t*)(ah_ + 8);
                ah[3] = *(const uint32_t*)(ah_ + 8 * SA + 8);
                al[0] = *(const uint32_t*)al_;
                al[1] = *(const uint32_t*)(al_ + 8 * SA);
                al[2] = *(const uint32_t*)(al_ + 8);
                al[3] = *(const uint32_t*)(al_ + 8 * SA + 8);
                #pragma unroll
                for (int ni = 0; ni < 4; ni++) {
                    mma16816(acc[mi][ni], ah, bh[ni]);
                    mma16816(acc[mi][ni], ah, bl[ni]);
                    mma16816(acc[mi][ni], al, bh[ni]);
                }
            }
        }
        __syncthreads();
    }

    // epilogue
    #pragma unroll
    for (int mi = 0; mi < 4; mi++) {
        #pragma unroll
        for (int ni = 0; ni < 4; ni++) {
            int r = arow0 + warp_m * 64 + mi * 16 + gID;
            int c = bcol0 + warp_n * 32 + ni * 8 + tg * 2;
            float b0 = bias ? bias[c] : 0.f;
            float b1 = bias ? bias[c + 1] : 0.f;
            float2 v0 = make_float2(acc[mi][ni][0] + b0, acc[mi][ni][1] + b1);
            float2 v1 = make_float2(acc[mi][ni][2] + b0, acc[mi][ni][3] + b1);
            *(float2*)(C + (size_t)r * N + c) = v0;
            *(float2*)(C + (size_t)(r + 8) * N + c) = v1;
        }
    }
}

// ---------------- helpers ----------------------------------------------------
__device__ __forceinline__ float2 blockSum2(float a, float b, float* sh) {
    #pragma unroll
    for (int o = 16; o > 0; o >>= 1) {
        a += __shfl_down_sync(0xffffffffu, a, o);
        b += __shfl_down_sync(0xffffffffu, b, o);
    }
    int w = threadIdx.x >> 5, l = threadIdx.x & 31;
    if (l == 0) { sh[w] = a; sh[8 + w] = b; }
    __syncthreads();
    if (threadIdx.x == 0) {
        float sa = 0.f, sb2 = 0.f;
        #pragma unroll
        for (int i = 0; i < 8; i++) { sa += sh[i]; sb2 += sh[8 + i]; }
        sh[16] = sa; sh[17] = sb2;
    }
    __syncthreads();
    float2 r = make_float2(sh[16], sh[17]);
    __syncthreads();
    return r;
}
__device__ __forceinline__ float sigmoidf_(float x) { return 1.f / (1.f + expf(-x)); }
__device__ __forceinline__ void splitbf(float v, __nv_bfloat16& hi, __nv_bfloat16& lo) {
    hi = __float2bfloat16(v);
    lo = __float2bfloat16(v - __bfloat162float(hi));
}

// ---------------- split / transpose kernels ----------------------------------
__global__ void k_split(const float* __restrict__ x, __nv_bfloat16* __restrict__ hi,
                        __nv_bfloat16* __restrict__ lo, int n)
{
    int i = blockIdx.x * blockDim.x + threadIdx.x;
    if (i >= n) return;
    splitbf(x[i], hi[i], lo[i]);
}

__global__ void k_w3t(const float* __restrict__ Wc, const float* __restrict__ Wh,
                      __nv_bfloat16* __restrict__ hi, __nv_bfloat16* __restrict__ lo)
{
    int i = blockIdx.x * blockDim.x + threadIdx.x;   // [H7 x H3]
    if (i >= H7 * H3) return;
    int n = i / H3, k = i % H3;
    float v = (k < Hh) ? Wc[(size_t)k * H7 + n]
            : (k < 2 * Hh) ? Wh[(size_t)(k - Hh) * H7 + n]
            : Wc[(size_t)(k - Hh) * H7 + n];
    splitbf(v, hi[i], lo[i]);
}

__global__ void k_wt(const float* __restrict__ W, int K, int N,
                     __nv_bfloat16* __restrict__ hi, __nv_bfloat16* __restrict__ lo)
{
    int i = blockIdx.x * blockDim.x + threadIdx.x;   // [N x K]
    if (i >= N * K) return;
    int n = i / K, k = i % K;
    splitbf(W[(size_t)k * N + n], hi[i], lo[i]);
}

// ---------------- tiny GEMM for M=8 rows -------------------------------------
__global__ void k_smallgemm(int M, int N, int K,
                            const float* __restrict__ A, const float* __restrict__ W,
                            const float* __restrict__ bias, float* __restrict__ C)
{
    int idx = blockIdx.x * blockDim.x + threadIdx.x;
    if (idx >= M * N) return;
    int m = idx / N, n = idx % N;
    float acc = bias ? bias[n] : 0.f;
    const float* a = A + (size_t)m * K;
    for (int k = 0; k < K; k++) acc += a[k] * W[(size_t)k * N + n];
    C[idx] = acc;
}

// ---------------- small kernels ----------------------------------------------
__global__ void k_invms(const float* __restrict__ mask, float* __restrict__ invms)
{
    __shared__ float sh[8];
    int b = blockIdx.x, t = threadIdx.x;
    float a = 0.f;
    for (int s = t; s < Ss; s += 256) a += mask[b * Ss + s];
    #pragma unroll
    for (int o = 16; o > 0; o >>= 1) a += __shfl_down_sync(0xffffffffu, a, o);
    if ((t & 31) == 0) sh[t >> 5] = a;
    __syncthreads();
    if (t == 0) {
        float s2 = 0.f;
        #pragma unroll
        for (int i = 0; i < 8; i++) s2 += sh[i];
        invms[b] = 1.f / s2;
    }
}

__global__ void k_meanp(const float* __restrict__ x, const float* __restrict__ mask,
                        float* __restrict__ pnum)
{
    int ch = blockIdx.x, b = blockIdx.y, h = threadIdx.x;
    float acc = 0.f;
    int s0 = ch * SCH;
    #pragma unroll
    for (int i = 0; i < SCH; i++) {
        int s = s0 + i;
        acc += x[((size_t)(b * Ss + s)) * Hh + h] * mask[b * Ss + s];
    }
    pnum[(b * NCH + ch) * Hh + h] = acc;
}

__global__ void k_meanf(const float* __restrict__ pnum, const float* __restrict__ invms,
                        float* __restrict__ out)
{
    int b = blockIdx.x, h = threadIdx.x;
    float a = 0.f;
    #pragma unroll
    for (int c = 0; c < NCH; c++) a += pnum[(b * NCH + c) * Hh + h];
    out[b * Hh + h] = a * invms[b];
}

__global__ void k_igog(const float* __restrict__ pi, const float* __restrict__ pa,
                       const float* __restrict__ lns, const float* __restrict__ lnb,
                       float* __restrict__ ig, float* __restrict__ og)
{
    __shared__ float sh[18];
    int b = blockIdx.x, h = threadIdx.x;
    float v = pi[b * H3 + h] + pa[b * 2 * Hh + h];
    float2 ssum = blockSum2(v, v * v, sh);
    float m = ssum.x * (1.f / 256.f);
    float var = (ssum.y - 256.f * m * m) * (1.f / 255.f);
    float zn = lns[h] * (v - m) * rsqrtf(var + 1e-6f) + lnb[h];
    ig[b * Hh + h] = sigmoidf_(zn);
    v = pi[b * H3 + 2 * Hh + h] + pa[b * 2 * Hh + Hh + h];
    ssum = blockSum2(v, v * v, sh);
    m = ssum.x * (1.f / 256.f);
    var = (ssum.y - 256.f * m * m) * (1.f / 255.f);
    zn = lns[2 * Hh + h] * (v - m) * rsqrtf(var + 1e-6f) + lnb[2 * Hh + h];
    og[b * Hh + h] = sigmoidf_(zn);
}

__global__ void k_hg(const float* __restrict__ ph, const float* __restrict__ pi,
                     const float* __restrict__ mask,
                     const float* __restrict__ lns, const float* __restrict__ lnb,
                     float* __restrict__ hg)
{
    __shared__ float sh[18];
    int bs = blockIdx.x; int b = bs >> 10;
    int h = threadIdx.x;
    float v = ph[(size_t)bs * Hh + h] + pi[b * H3 + Hh + h];
    float2 ssum = blockSum2(v, v * v, sh);
    float m = ssum.x * (1.f / 256.f);
    float var = (ssum.y - 256.f * m * m) * (1.f / 255.f);
    float zn = lns[Hh + h] * (v - m) * rsqrtf(var + 1e-6f) + lnb[Hh + h];
    hg[(size_t)bs * Hh + h] = sigmoidf_(zn) + (mask[bs] * 1e25f - 1e25f);
}

__global__ void k_gcp(const float* __restrict__ hg, const float* __restrict__ cell,
                      float* __restrict__ pnum, float* __restrict__ pden)
{
    int ch = blockIdx.x, b = blockIdx.y, h = threadIdx.x;
    float num = 0.f, den = 0.f;
    int s0 = ch * SCH;
    #pragma unroll
    for (int i = 0; i < SCH; i++) {
        size_t idx = ((size_t)(b * Ss + s0 + i)) * Hh + h;
        float e = expf(hg[idx]);
        num += e * cell[idx];
        den += e;
    }
    pnum[(b * NCH + ch) * Hh + h] = num;
    pden[(b * NCH + ch) * Hh + h] = den;
}

__global__ void k_gcf(const float* __restrict__ pnum, const float* __restrict__ pden,
                      const float* __restrict__ ig, const float* __restrict__ og,
                      float* __restrict__ gc, float* __restrict__ gh)
{
    int b = blockIdx.x, h = threadIdx.x;
    float num = 0.f, den = 0.f;
    #pragma unroll
    for (int c = 0; c < NCH; c++) {
        num += pnum[(b * NCH + c) * Hh + h];
        den += pden[(b * NCH + c) * Hh + h];
    }
    float ei = expf(ig[b * Hh + h]);
    float g = (gc[b * Hh + h] * ei + num) / (ei + den);
    gc[b * Hh + h] = g;
    gh[b * Hh + h] = og[b * Hh + h] * tanhf(g);
}

// build split-bf16 ctx = [h_l, h, h_r] directly from split-bf16 hidden
__global__ void k_ctx_bf(const __nv_bfloat16* __restrict__ hhi,
                         const __nv_bfloat16* __restrict__ hlo,
                         __nv_bfloat16* __restrict__ chi,
                         __nv_bfloat16* __restrict__ clo)
{
    int i = blockIdx.x * blockDim.x + threadIdx.x;  // 8-elem chunk
    if (i >= BSR * (H3 / 8)) return;
    int bs = i / (H3 / 8);
    int j = (i % (H3 / 8)) * 8;
    int s = bs & (Ss - 1);
    uint4 vh = make_uint4(0, 0, 0, 0), vl = make_uint4(0, 0, 0, 0);
    long off = -1;
    if (j < Hh)           { if (s > 0)      off = ((long)bs - 1) * Hh + j; }
    else if (j < 2 * Hh)  {                 off = (long)bs * Hh + (j - Hh); }
    else                  { if (s < Ss - 1) off = ((long)bs + 1) * Hh + (j - 2 * Hh); }
    if (off >= 0) {
        vh = *(const uint4*)(hhi + off);
        vl = *(const uint4*)(hlo + off);
    }
    *(uint4*)(chi + (size_t)bs * H3 + j) = vh;
    *(uint4*)(clo + (size_t)bs * H3 + j) = vl;
}

// one-pass LN for all 7 groups: 2 barriers instead of 21
__global__ __launch_bounds__(256) void k_update(
    const float* __restrict__ z, const float* __restrict__ proj,
    const float* __restrict__ gWg, const float* __restrict__ gc,
    const float* __restrict__ mask,
    const float* __restrict__ lns, const float* __restrict__ lnb,
    const float* __restrict__ c_old,
    float* __restrict__ h_new, float* __restrict__ c_new,
    __nv_bfloat16* __restrict__ hhi, __nv_bfloat16* __restrict__ hlo)
{
    __shared__ float wsum[8][14];
    __shared__ float fin[14];
    int bs = blockIdx.x; int b = bs >> 10; int s = bs & (Ss - 1);
    int h = threadIdx.x;
    int w = h >> 5, lane = h & 31;
    size_t rz = (size_t)bs * H7;
    float v[7];
    #pragma unroll
    for (int k = 0; k < 7; k++)
        v[k] = z[rz + k * Hh + h] + proj[rz + k * Hh + h] + gWg[b * H7 + k * Hh + h];

    float p[14];
    #pragma unroll
    for (int k = 0; k < 7; k++) { p[2 * k] = v[k]; p[2 * k + 1] = v[k] * v[k]; }
    #pragma unroll
    for (int o = 16; o > 0; o >>= 1)
        #pragma unroll
        for (int j = 0; j < 14; j++)
            p[j] += __shfl_down_sync(0xffffffffu, p[j], o);
    if (lane == 0)
        #pragma unroll
        for (int j = 0; j < 14; j++) wsum[w][j] = p[j];
    __syncthreads();
    if (h < 14) {
        float a = 0.f;
        #pragma unroll
        for (int i = 0; i < 8; i++) a += wsum[i][h];
        fin[h] = a;
    }
    __syncthreads();

    float zn[7];
    #pragma unroll
    for (int k = 0; k < 7; k++) {
        float m = fin[2 * k] * (1.f / 256.f);
        float var = (fin[2 * k + 1] - 256.f * m * m) * (1.f / 255.f);
        zn[k] = lns[(3 + k) * Hh + h] * (v[k] - m) * rsqrtf(var + 1e-6f) + lnb[(3 + k) * Hh + h];
    }
    float e[6], den = 0.f;
    #pragma unroll
    for (int k = 0; k < 6; k++) {
        e[k] = expf(sigmoidf_(zn[k]));
        den += e[k];
    }
    float inv = 1.f / den;
    float mem = tanhf(zn[6]);
    size_t idx = (size_t)bs * Hh + h;
    float c  = c_old[idx];
    float cl = (s > 0)      ? c_old[idx - Hh] : 0.f;
    float cr = (s < Ss - 1) ? c_old[idx + Hh] : 0.f;
    float cn = (e[1] * cl + e[2] * cr + e[3] * c + e[0] * mem + e[4] * gc[b * Hh + h]) * inv;
    float mk = mask[bs];
    float hv = e[5] * inv * tanhf(cn) * mk;
    h_new[idx] = hv;
    c_new[idx] = cn * mk;
    splitbf(hv, hhi[idx], hlo[idx]);
}

// ---------------- orchestration ----------------------------------------------
extern "C" void kernel_launch(void* const* d_in, const int* in_sizes, int n_in,
                              void* d_out, int out_size)
{
    (void)in_sizes; (void)n_in; (void)out_size;
    const float* inputs = (const float*)d_in[0];
    const float* mask   = (const float*)d_in[1];
    const float* ih     = (const float*)d_in[2];
    const float* ic     = (const float*)d_in[3];
    const float* Wc     = (const float*)d_in[4];
    const float* Wh     = (const float*)d_in[5];
    const float* Wi     = (const float*)d_in[6];
    const float* bi     = (const float*)d_in[7];
    const float* Wg     = (const float*)d_in[8];
    const float* Gi     = (const float*)d_in[9];
    const float* gb     = (const float*)d_in[10];
    const float* Gh     = (const float*)d_in[11];
    const float* Ga     = (const float*)d_in[12];
    const float* lns    = (const float*)d_in[13];
    const float* lnb    = (const float*)d_in[14];
    float* out = (float*)d_out;

    float *hb0, *hb1, *cb0, *cb1, *proj, *zb, *ph;
    float *pi, *pa, *ig, *og, *gh, *gc, *havg, *gWg, *pnum, *pden, *invms;
    __nv_bfloat16 *chi, *clo, *hh0, *hl0, *hh1, *hl1, *inh, *inl;
    __nv_bfloat16 *w3h, *w3l, *ghh, *ghl, *wih, *wil;
    cudaGetSymbolAddress((void**)&hb0,  d_hbuf0);
    cudaGetSymbolAddress((void**)&hb1,  d_hbuf1);
    cudaGetSymbolAddress((void**)&cb0,  d_cbuf0);
    cudaGetSymbolAddress((void**)&cb1,  d_cbuf1);
    cudaGetSymbolAddress((void**)&proj, d_proj);
    cudaGetSymbolAddress((void**)&zb,   d_zbuf);
    cudaGetSymbolAddress((void**)&ph,   d_ph);
    cudaGetSymbolAddress((void**)&pi,   d_pi);
    cudaGetSymbolAddress((void**)&pa,   d_pa);
    cudaGetSymbolAddress((void**)&ig,   d_igb);
    cudaGetSymbolAddress((void**)&og,   d_ogb);
    cudaGetSymbolAddress((void**)&gh,   d_gh);
    cudaGetSymbolAddress((void**)&gc,   d_gcv);
    cudaGetSymbolAddress((void**)&havg, d_havg);
    cudaGetSymbolAddress((void**)&gWg,  d_gWg);
    cudaGetSymbolAddress((void**)&pnum, d_pnum);
    cudaGetSymbolAddress((void**)&pden, d_pden);
    cudaGetSymbolAddress((void**)&invms, d_invms);
    cudaGetSymbolAddress((void**)&chi, d_ctx_hi);
    cudaGetSymbolAddress((void**)&clo, d_ctx_lo);
    cudaGetSymbolAddress((void**)&hh0, d_h_hi0);
    cudaGetSymbolAddress((void**)&hl0, d_h_lo0);
    cudaGetSymbolAddress((void**)&hh1, d_h_hi1);
    cudaGetSymbolAddress((void**)&hl1, d_h_lo1);
    cudaGetSymbolAddress((void**)&inh, d_in_hi);
    cudaGetSymbolAddress((void**)&inl, d_in_lo);
    cudaGetSymbolAddress((void**)&w3h, d_W3T_hi);
    cudaGetSymbolAddress((void**)&w3l, d_W3T_lo);
    cudaGetSymbolAddress((void**)&ghh, d_GhT_hi);
    cudaGetSymbolAddress((void**)&ghl, d_GhT_lo);
    cudaGetSymbolAddress((void**)&wih, d_WiT_hi);
    cudaGetSymbolAddress((void**)&wil, d_WiT_lo);

    cudaFuncSetAttribute(k_hmma, cudaFuncAttributeMaxDynamicSharedMemorySize, HSMEM);

    // streams/events created once in the (uncaptured) correctness call,
    // reused by the capture call. No device memory involved.
    static cudaStream_t s2 = [] {
        cudaStream_t s; cudaStreamCreateWithFlags(&s, cudaStreamNonBlocking); return s;
    }();
    static cudaEvent_t evFork = [] {
        cudaEvent_t e; cudaEventCreateWithFlags(&e, cudaEventDisableTiming); return e;
    }();
    static cudaEvent_t evJoin = [] {
        cudaEvent_t e; cudaEventCreateWithFlags(&e, cudaEventDisableTiming); return e;
    }();

    // layer-invariant precompute (main stream)
    k_invms<<<Bb, 256>>>(mask, invms);
    k_meanp<<<dim3(NCH, Bb), 256>>>(ih, mask, pnum);
    k_meanf<<<Bb, 256>>>(pnum, invms, gh);
    k_meanp<<<dim3(NCH, Bb), 256>>>(ic, mask, pnum);
    k_meanf<<<Bb, 256>>>(pnum, invms, gc);
    k_w3t<<<(H7 * H3 + 255) / 256, 256>>>(Wc, Wh, w3h, w3l);
    k_wt<<<(Hh * Hh + 255) / 256, 256>>>(Gh, Hh, Hh, ghh, ghl);
    k_wt<<<(H7 * Hh + 255) / 256, 256>>>(Wi, Hh, H7, wih, wil);
    k_split<<<(BSR * Hh + 255) / 256, 256>>>(ih, hh0, hl0, BSR * Hh);
    k_split<<<(BSR * Hh + 255) / 256, 256>>>(inputs, inh, inl, BSR * Hh);
    k_hmma<<<dim3(H7 / 128, BSR / 128), 256, HSMEM>>>(
        BSR, H7, Hh, inh, inl, wih, wil, bi, proj);

    float* hbufs[2] = { hb0, hb1 };
    float* cbufs[2] = { cb0, cb1 };
    __nv_bfloat16* hhis[2] = { hh0, hh1 };
    __nv_bfloat16* hlos[2] = { hl0, hl1 };

    for (int l = 0; l < LL; l++) {
        const float* hid = (l == 0) ? ih : hbufs[l & 1];
        const float* cel = (l == 0) ? ic : cbufs[l & 1];
        const __nv_bfloat16* hhi = hhis[l & 1];
        const __nv_bfloat16* hlo = hlos[l & 1];
        float* hout = (l == LL - 1) ? out : hbufs[(l + 1) & 1];
        float* cout = cbufs[(l + 1) & 1];

        // fork: z-branch (ctx + z-GEMM) depends only on hidden from prev update
        cudaEventRecord(evFork, 0);
        cudaStreamWaitEvent(s2, evFork, 0);
        k_ctx_bf<<<(BSR * (H3 / 8) + 255) / 256, 256, 0, s2>>>(hhi, hlo, chi, clo);
        k_hmma<<<dim3(H7 / 128, BSR / 128), 256, HSMEM, s2>>>(
            BSR, H7, H3, chi, clo, w3h, w3l, (const float*)nullptr, zb);
        cudaEventRecord(evJoin, s2);

        // ---- global state chain (main stream, concurrent with z-branch) ----
        k_meanp<<<dim3(NCH, Bb), 256>>>(hid, mask, pnum);
        k_meanf<<<Bb, 256>>>(pnum, invms, havg);
        k_smallgemm<<<(Bb * H3 + 255) / 256, 256>>>(Bb, H3, Hh, gh, Gi, gb, pi);
        k_smallgemm<<<(Bb * 2 * Hh + 255) / 256, 256>>>(Bb, 2 * Hh, Hh, havg, Ga,
                                                        (const float*)nullptr, pa);
        k_igog<<<Bb, 256>>>(pi, pa, lns, lnb, ig, og);
        k_hmma<<<dim3(Hh / 128, BSR / 128), 256, HSMEM>>>(
            BSR, Hh, Hh, hhi, hlo, ghh, ghl, (const float*)nullptr, ph);
        k_hg<<<BSR, 256>>>(ph, pi, mask, lns, lnb, ph);
        k_gcp<<<dim3(NCH, Bb), 256>>>(ph, cel, pnum, pden);
        k_gcf<<<Bb, 256>>>(pnum, pden, ig, og, gc, gh);
        k_smallgemm<<<(Bb * H7 + 255) / 256, 256>>>(Bb, H7, Hh, gh, Wg,
                                                    (const float*)nullptr, gWg);

        // join: update needs z (s2) + gWg/gc (main)
        cudaStreamWaitEvent(0, evJoin, 0);
        k_update<<<BSR, 256>>>(zb, proj, gWg, gc, mask, lns, lnb, cel, hout, cout,
                               hhis[(l + 1) & 1], hlos[(l + 1) & 1]);
    }
}

// round 9
// speedup vs baseline: 1.9220x; 1.0349x over previous
#include <cuda_runtime.h>
#include <cuda_bf16.h>
#include <cstdint>
#include <cstddef>

// Problem constants
#define Bb 8
#define Ss 1024
#define Hh 256
#define LL 7
#define BSR (Bb*Ss)        // 8192 rows
#define H7 (7*Hh)          // 1792
#define H3 (3*Hh)          // 768
#define NCH 64
#define SCH (Ss/NCH)       // 16

// ---------------- scratch (device globals; no allocations allowed) ----------
__device__ float d_hbuf0[BSR*Hh];
__device__ float d_hbuf1[BSR*Hh];
__device__ float d_cbuf0[BSR*Hh];
__device__ float d_cbuf1[BSR*Hh];
__device__ float d_proj[(size_t)BSR*H7];
__device__ float d_zbuf[(size_t)BSR*H7];
__device__ float d_ph[BSR*Hh];
__device__ float d_pi[Bb*H3];
__device__ float d_pa[Bb*2*Hh];
__device__ float d_igb[Bb*Hh];
__device__ float d_ogb[Bb*Hh];
__device__ float d_gh[Bb*Hh];
__device__ float d_gcv[Bb*Hh];
__device__ float d_havg[Bb*Hh];
__device__ float d_gWg[Bb*H7];
__device__ float d_pnum[Bb*NCH*Hh];
__device__ float d_pden[Bb*NCH*Hh];
__device__ float d_invms[Bb];
// split-bf16 activations / weights (16B aligned for uint4 / cp.async)
__device__ __align__(16) __nv_bfloat16 d_ctx_hi[(size_t)BSR*H3];
__device__ __align__(16) __nv_bfloat16 d_ctx_lo[(size_t)BSR*H3];
__device__ __align__(16) __nv_bfloat16 d_h_hi0[BSR*Hh];
__device__ __align__(16) __nv_bfloat16 d_h_lo0[BSR*Hh];
__device__ __align__(16) __nv_bfloat16 d_h_hi1[BSR*Hh];
__device__ __align__(16) __nv_bfloat16 d_h_lo1[BSR*Hh];
__device__ __align__(16) __nv_bfloat16 d_in_hi[BSR*Hh];
__device__ __align__(16) __nv_bfloat16 d_in_lo[BSR*Hh];
__device__ __align__(16) __nv_bfloat16 d_W3T_hi[H7*H3];
__device__ __align__(16) __nv_bfloat16 d_W3T_lo[H7*H3];
__device__ __align__(16) __nv_bfloat16 d_GhT_hi[Hh*Hh];
__device__ __align__(16) __nv_bfloat16 d_GhT_lo[Hh*Hh];
__device__ __align__(16) __nv_bfloat16 d_WiT_hi[H7*Hh];
__device__ __align__(16) __nv_bfloat16 d_WiT_lo[H7*Hh];

// ---------------- PTX helpers -----------------------------------------------
__device__ __forceinline__ uint32_t smem_u32(const void* p) {
    uint32_t a;
    asm("{ .reg .u64 t; cvta.to.shared.u64 t, %1; cvt.u32.u64 %0, t; }"
        : "=r"(a) : "l"(p));
    return a;
}
__device__ __forceinline__ void cpasync16(uint32_t dst, const void* src) {
    asm volatile("cp.async.cg.shared.global [%0], [%1], 16;" :: "r"(dst), "l"(src));
}
#define CP_COMMIT() asm volatile("cp.async.commit_group;" ::: "memory")
#define CP_WAIT1()  asm volatile("cp.async.wait_group 1;" ::: "memory")
#define CP_WAIT0()  asm volatile("cp.async.wait_group 0;" ::: "memory")

__device__ __forceinline__ void mma16816(float* c, const uint32_t* a, const uint32_t* b) {
    asm volatile(
        "mma.sync.aligned.m16n8k16.row.col.f32.bf16.bf16.f32 "
        "{%0,%1,%2,%3}, {%4,%5,%6,%7}, {%8,%9}, {%0,%1,%2,%3};"
        : "+f"(c[0]), "+f"(c[1]), "+f"(c[2]), "+f"(c[3])
        : "r"(a[0]), "r"(a[1]), "r"(a[2]), "r"(a[3]), "r"(b[0]), "r"(b[1]));
}

// ---------------- bf16x3 HMMA GEMM (2 CTAs/SM for latency hiding) ------------
#define KB 32
#define SA 40                      // padded smem row stride (halves)
#define MTILE (128*SA)
#define STAGE (4*MTILE)            // Ahi, Alo, Bhi, Blo
#define HSMEM (2*STAGE*2)          // 81920 bytes

__global__ void __launch_bounds__(256, 2) k_hmma(
    int M, int N, int K,
    const __nv_bfloat16* __restrict__ Ahi, const __nv_bfloat16* __restrict__ Alo,
    const __nv_bfloat16* __restrict__ Bhi, const __nv_bfloat16* __restrict__ Blo,
    const float* __restrict__ bias, float* __restrict__ C)
{
    extern __shared__ __nv_bfloat16 sm[];
    int tid = threadIdx.x, wid = tid >> 5, lane = tid & 31;
    int gID = lane >> 2, tg = lane & 3;
    int warp_m = wid >> 2, warp_n = wid & 3;
    int arow0 = blockIdx.y * 128, bcol0 = blockIdx.x * 128;

    const __nv_bfloat16* srcs[4] = {
        Ahi + (size_t)arow0 * K, Alo + (size_t)arow0 * K,
        Bhi + (size_t)bcol0 * K, Blo + (size_t)bcol0 * K };

    float acc[4][4][4];
    #pragma unroll
    for (int mi = 0; mi < 4; mi++)
        #pragma unroll
        for (int ni = 0; ni < 4; ni++)
            #pragma unroll
            for (int q = 0; q < 4; q++) acc[mi][ni][q] = 0.f;

    uint32_t smbase = smem_u32(sm);
    int niter = K / KB;

    // prologue: stage 0
    #pragma unroll
    for (int t = 0; t < 4; t++) {
        const __nv_bfloat16* src = srcs[t];
        uint32_t dst = smbase + (0 * STAGE + t * MTILE) * 2;
        #pragma unroll
        for (int s = 0; s < 2; s++) {
            int slot = tid + s * 256;
            int row = slot >> 2, cg = (slot & 3) * 8;
            cpasync16(dst + (row * SA + cg) * 2, src + (size_t)row * K + cg);
        }
    }
    CP_COMMIT();

    for (int it = 0; it < niter; it++) {
        if (it + 1 < niter) {
            int st = (it + 1) & 1;
            int k0 = (it + 1) * KB;
            #pragma unroll
            for (int t = 0; t < 4; t++) {
                const __nv_bfloat16* src = srcs[t] + k0;
                uint32_t dst = smbase + (st * STAGE + t * MTILE) * 2;
                #pragma unroll
                for (int s = 0; s < 2; s++) {
                    int slot = tid + s * 256;
                    int row = slot >> 2, cg = (slot & 3) * 8;
                    cpasync16(dst + (row * SA + cg) * 2, src + (size_t)row * K + cg);
                }
            }
            CP_COMMIT();
            CP_WAIT1();
        } else {
            CP_WAIT0();
        }
        __syncthreads();

        const __nv_bfloat16* As_h = sm + (it & 1) * STAGE;
        const __nv_bfloat16* As_l = As_h + MTILE;
        const __nv_bfloat16* Bs_h = As_h + 2 * MTILE;
        const __nv_bfloat16* Bs_l = As_h + 3 * MTILE;

        #pragma unroll
        for (int kk = 0; kk < KB; kk += 16) {
            uint32_t bh[4][2], bl[4][2];
            #pragma unroll
            for (int ni = 0; ni < 4; ni++) {
                int n = warp_n * 32 + ni * 8 + gID;
                const __nv_bfloat16* ph_ = Bs_h + n * SA + kk + tg * 2;
                const __nv_bfloat16* pl_ = Bs_l + n * SA + kk + tg * 2;
                bh[ni][0] = *(const uint32_t*)ph_;
                bh[ni][1] = *(const uint32_t*)(ph_ + 8);
                bl[ni][0] = *(const uint32_t*)pl_;
                bl[ni][1] = *(const uint32_t*)(pl_ + 8);
            }
            #pragma unroll
            for (int mi = 0; mi < 4; mi++) {
                int r0 = warp_m * 64 + mi * 16 + gID;
                const __nv_bfloat16* ah_ = As_h + r0 * SA + kk + tg * 2;
                const __nv_bfloat16* al_ = As_l + r0 * SA + kk + tg * 2;
                uint32_t ah[4], al[4];
                ah[0] = *(const uint32_t*)ah_;
                ah[1] = *(const uint32_t*)(ah_ + 8 * SA);
                ah[2] = *(const uint32_t*)(ah_ + 8);
                ah[3] = *(const uint32_t*)(ah_ + 8 * SA + 8);
                al[0] = *(const uint32_t*)al_;
                al[1] = *(const uint32_t*)(al_ + 8 * SA);
                al[2] = *(const uint32_t*)(al_ + 8);
                al[3] = *(const uint32_t*)(al_ + 8 * SA + 8);
                #pragma unroll
                for (int ni = 0; ni < 4; ni++) {
                    mma16816(acc[mi][ni], ah, bh[ni]);
                    mma16816(acc[mi][ni], ah, bl[ni]);
                    mma16816(acc[mi][ni], al, bh[ni]);
                }
            }
        }
        __syncthreads();
    }

    // epilogue
    #pragma unroll
    for (int mi = 0; mi < 4; mi++) {
        #pragma unroll
        for (int ni = 0; ni < 4; ni++) {
            int r = arow0 + warp_m * 64 + mi * 16 + gID;
            int c = bcol0 + warp_n * 32 + ni * 8 + tg * 2;
            float b0 = bias ? bias[c] : 0.f;
            float b1 = bias ? bias[c + 1] : 0.f;
            float2 v0 = make_float2(acc[mi][ni][0] + b0, acc[mi][ni][1] + b1);
            float2 v1 = make_float2(acc[mi][ni][2] + b0, acc[mi][ni][3] + b1);
            *(float2*)(C + (size_t)r * N + c) = v0;
            *(float2*)(C + (size_t)(r + 8) * N + c) = v1;
        }
    }
}

// ---------------- helpers ----------------------------------------------------
__device__ __forceinline__ float2 blockSum2(float a, float b, float* sh) {
    #pragma unroll
    for (int o = 16; o > 0; o >>= 1) {
        a += __shfl_down_sync(0xffffffffu, a, o);
        b += __shfl_down_sync(0xffffffffu, b, o);
    }
    int w = threadIdx.x >> 5, l = threadIdx.x & 31;
    if (l == 0) { sh[w] = a; sh[8 + w] = b; }
    __syncthreads();
    if (threadIdx.x == 0) {
        float sa = 0.f, sb2 = 0.f;
        #pragma unroll
        for (int i = 0; i < 8; i++) { sa += sh[i]; sb2 += sh[8 + i]; }
        sh[16] = sa; sh[17] = sb2;
    }
    __syncthreads();
    float2 r = make_float2(sh[16], sh[17]);
    __syncthreads();
    return r;
}
__device__ __forceinline__ float sigmoidf_(float x) { return 1.f / (1.f + expf(-x)); }
__device__ __forceinline__ void splitbf(float v, __nv_bfloat16& hi, __nv_bfloat16& lo) {
    hi = __float2bfloat16(v);
    lo = __float2bfloat16(v - __bfloat162float(hi));
}

// ---------------- split / transpose kernels ----------------------------------
__global__ void k_split(const float* __restrict__ x, __nv_bfloat16* __restrict__ hi,
                        __nv_bfloat16* __restrict__ lo, int n)
{
    int i = blockIdx.x * blockDim.x + threadIdx.x;
    if (i >= n) return;
    splitbf(x[i], hi[i], lo[i]);
}

__global__ void k_w3t(const float* __restrict__ Wc, const float* __restrict__ Wh,
                      __nv_bfloat16* __restrict__ hi, __nv_bfloat16* __restrict__ lo)
{
    int i = blockIdx.x * blockDim.x + threadIdx.x;   // [H7 x H3]
    if (i >= H7 * H3) return;
    int n = i / H3, k = i % H3;
    float v = (k < Hh) ? Wc[(size_t)k * H7 + n]
            : (k < 2 * Hh) ? Wh[(size_t)(k - Hh) * H7 + n]
            : Wc[(size_t)(k - Hh) * H7 + n];
    splitbf(v, hi[i], lo[i]);
}

__global__ void k_wt(const float* __restrict__ W, int K, int N,
                     __nv_bfloat16* __restrict__ hi, __nv_bfloat16* __restrict__ lo)
{
    int i = blockIdx.x * blockDim.x + threadIdx.x;   // [N x K]
    if (i >= N * K) return;
    int n = i / K, k = i % K;
    splitbf(W[(size_t)k * N + n], hi[i], lo[i]);
}

// ---------------- tiny GEMM for M=8 rows -------------------------------------
__global__ void k_smallgemm(int M, int N, int K,
                            const float* __restrict__ A, const float* __restrict__ W,
                            const float* __restrict__ bias, float* __restrict__ C)
{
    int idx = blockIdx.x * blockDim.x + threadIdx.x;
    if (idx >= M * N) return;
    int m = idx / N, n = idx % N;
    float acc = bias ? bias[n] : 0.f;
    const float* a = A + (size_t)m * K;
    for (int k = 0; k < K; k++) acc += a[k] * W[(size_t)k * N + n];
    C[idx] = acc;
}

// ---------------- small kernels ----------------------------------------------
__global__ void k_invms(const float* __restrict__ mask, float* __restrict__ invms)
{
    __shared__ float sh[8];
    int b = blockIdx.x, t = threadIdx.x;
    float a = 0.f;
    for (int s = t; s < Ss; s += 256) a += mask[b * Ss + s];
    #pragma unroll
    for (int o = 16; o > 0; o >>= 1) a += __shfl_down_sync(0xffffffffu, a, o);
    if ((t & 31) == 0) sh[t >> 5] = a;
    __syncthreads();
    if (t == 0) {
        float s2 = 0.f;
        #pragma unroll
        for (int i = 0; i < 8; i++) s2 += sh[i];
        invms[b] = 1.f / s2;
    }
}

__global__ void k_meanp(const float* __restrict__ x, const float* __restrict__ mask,
                        float* __restrict__ pnum)
{
    int ch = blockIdx.x, b = blockIdx.y, h = threadIdx.x;
    float acc = 0.f;
    int s0 = ch * SCH;
    #pragma unroll
    for (int i = 0; i < SCH; i++) {
        int s = s0 + i;
        acc += x[((size_t)(b * Ss + s)) * Hh + h] * mask[b * Ss + s];
    }
    pnum[(b * NCH + ch) * Hh + h] = acc;
}

__global__ void k_meanf(const float* __restrict__ pnum, const float* __restrict__ invms,
                        float* __restrict__ out)
{
    int b = blockIdx.x, h = threadIdx.x;
    float a = 0.f;
    #pragma unroll
    for (int c = 0; c < NCH; c++) a += pnum[(b * NCH + c) * Hh + h];
    out[b * Hh + h] = a * invms[b];
}

__global__ void k_igog(const float* __restrict__ pi, const float* __restrict__ pa,
                       const float* __restrict__ lns, const float* __restrict__ lnb,
                       float* __restrict__ ig, float* __restrict__ og)
{
    __shared__ float sh[18];
    int b = blockIdx.x, h = threadIdx.x;
    float v = pi[b * H3 + h] + pa[b * 2 * Hh + h];
    float2 ssum = blockSum2(v, v * v, sh);
    float m = ssum.x * (1.f / 256.f);
    float var = (ssum.y - 256.f * m * m) * (1.f / 255.f);
    float zn = lns[h] * (v - m) * rsqrtf(var + 1e-6f) + lnb[h];
    ig[b * Hh + h] = sigmoidf_(zn);
    v = pi[b * H3 + 2 * Hh + h] + pa[b * 2 * Hh + Hh + h];
    ssum = blockSum2(v, v * v, sh);
    m = ssum.x * (1.f / 256.f);
    var = (ssum.y - 256.f * m * m) * (1.f / 255.f);
    zn = lns[2 * Hh + h] * (v - m) * rsqrtf(var + 1e-6f) + lnb[2 * Hh + h];
    og[b * Hh + h] = sigmoidf_(zn);
}

// fused hg + gcp: per (chunk, batch) block, LN+sigmoid+mask+exp each of the 16
// rows (batched 32-wide reduction, 2 barriers), then softmax partial sums.
__global__ __launch_bounds__(256) void k_hgcp(
    const float* __restrict__ ph, const float* __restrict__ pi,
    const float* __restrict__ mask,
    const float* __restrict__ lns, const float* __restrict__ lnb,
    const float* __restrict__ cell,
    float* __restrict__ pnum, float* __restrict__ pden)
{
    __shared__ float wsum[8][32];
    __shared__ float fin[32];
    int ch = blockIdx.x, b = blockIdx.y, h = threadIdx.x;
    int w = h >> 5, lane = h & 31;
    int s0 = ch * SCH;
    float piv = pi[b * H3 + Hh + h];
    float v[SCH];
    #pragma unroll
    for (int i = 0; i < SCH; i++)
        v[i] = ph[((size_t)(b * Ss + s0 + i)) * Hh + h] + piv;

    float p[2 * SCH];
    #pragma unroll
    for (int i = 0; i < SCH; i++) { p[2 * i] = v[i]; p[2 * i + 1] = v[i] * v[i]; }
    #pragma unroll
    for (int o = 16; o > 0; o >>= 1)
        #pragma unroll
        for (int j = 0; j < 2 * SCH; j++)
            p[j] += __shfl_down_sync(0xffffffffu, p[j], o);
    if (lane == 0)
        #pragma unroll
        for (int j = 0; j < 2 * SCH; j++) wsum[w][j] = p[j];
    __syncthreads();
    if (h < 2 * SCH) {
        float a = 0.f;
        #pragma unroll
        for (int i = 0; i < 8; i++) a += wsum[i][h];
        fin[h] = a;
    }
    __syncthreads();

    float lnsv = lns[Hh + h], lnbv = lnb[Hh + h];
    float num = 0.f, den = 0.f;
    #pragma unroll
    for (int i = 0; i < SCH; i++) {
        float m = fin[2 * i] * (1.f / 256.f);
        float var = (fin[2 * i + 1] - 256.f * m * m) * (1.f / 255.f);
        float zn = lnsv * (v[i] - m) * rsqrtf(var + 1e-6f) + lnbv;
        float mk = mask[b * Ss + s0 + i];
        float e = expf(sigmoidf_(zn) + (mk * 1e25f - 1e25f));
        size_t idx = ((size_t)(b * Ss + s0 + i)) * Hh + h;
        num += e * cell[idx];
        den += e;
    }
    pnum[(b * NCH + ch) * Hh + h] = num;
    pden[(b * NCH + ch) * Hh + h] = den;
}

__global__ void k_gcf(const float* __restrict__ pnum, const float* __restrict__ pden,
                      const float* __restrict__ ig, const float* __restrict__ og,
                      float* __restrict__ gc, float* __restrict__ gh)
{
    int b = blockIdx.x, h = threadIdx.x;
    float num = 0.f, den = 0.f;
    #pragma unroll
    for (int c = 0; c < NCH; c++) {
        num += pnum[(b * NCH + c) * Hh + h];
        den += pden[(b * NCH + c) * Hh + h];
    }
    float ei = expf(ig[b * Hh + h]);
    float g = (gc[b * Hh + h] * ei + num) / (ei + den);
    gc[b * Hh + h] = g;
    gh[b * Hh + h] = og[b * Hh + h] * tanhf(g);
}

// build split-bf16 ctx = [h_l, h, h_r] directly from split-bf16 hidden
__global__ void k_ctx_bf(const __nv_bfloat16* __restrict__ hhi,
                         const __nv_bfloat16* __restrict__ hlo,
                         __nv_bfloat16* __restrict__ chi,
                         __nv_bfloat16* __restrict__ clo)
{
    int i = blockIdx.x * blockDim.x + threadIdx.x;  // 8-elem chunk
    if (i >= BSR * (H3 / 8)) return;
    int bs = i / (H3 / 8);
    int j = (i % (H3 / 8)) * 8;
    int s = bs & (Ss - 1);
    uint4 vh = make_uint4(0, 0, 0, 0), vl = make_uint4(0, 0, 0, 0);
    long off = -1;
    if (j < Hh)           { if (s > 0)      off = ((long)bs - 1) * Hh + j; }
    else if (j < 2 * Hh)  {                 off = (long)bs * Hh + (j - Hh); }
    else                  { if (s < Ss - 1) off = ((long)bs + 1) * Hh + (j - 2 * Hh); }
    if (off >= 0) {
        vh = *(const uint4*)(hhi + off);
        vl = *(const uint4*)(hlo + off);
    }
    *(uint4*)(chi + (size_t)bs * H3 + j) = vh;
    *(uint4*)(clo + (size_t)bs * H3 + j) = vl;
}

// one-pass LN for all 7 groups: 2 barriers instead of 21
__global__ __launch_bounds__(256) void k_update(
    const float* __restrict__ z, const float* __restrict__ proj,
    const float* __restrict__ gWg, const float* __restrict__ gc,
    const float* __restrict__ mask,
    const float* __restrict__ lns, const float* __restrict__ lnb,
    const float* __restrict__ c_old,
    float* __restrict__ h_new, float* __restrict__ c_new,
    __nv_bfloat16* __restrict__ hhi, __nv_bfloat16* __restrict__ hlo)
{
    __shared__ float wsum[8][14];
    __shared__ float fin[14];
    int bs = blockIdx.x; int b = bs >> 10; int s = bs & (Ss - 1);
    int h = threadIdx.x;
    int w = h >> 5, lane = h & 31;
    size_t rz = (size_t)bs * H7;
    float v[7];
    #pragma unroll
    for (int k = 0; k < 7; k++)
        v[k] = z[rz + k * Hh + h] + proj[rz + k * Hh + h] + gWg[b * H7 + k * Hh + h];

    float p[14];
    #pragma unroll
    for (int k = 0; k < 7; k++) { p[2 * k] = v[k]; p[2 * k + 1] = v[k] * v[k]; }
    #pragma unroll
    for (int o = 16; o > 0; o >>= 1)
        #pragma unroll
        for (int j = 0; j < 14; j++)
            p[j] += __shfl_down_sync(0xffffffffu, p[j], o);
    if (lane == 0)
        #pragma unroll
        for (int j = 0; j < 14; j++) wsum[w][j] = p[j];
    __syncthreads();
    if (h < 14) {
        float a = 0.f;
        #pragma unroll
        for (int i = 0; i < 8; i++) a += wsum[i][h];
        fin[h] = a;
    }
    __syncthreads();

    float zn[7];
    #pragma unroll
    for (int k = 0; k < 7; k++) {
        float m = fin[2 * k] * (1.f / 256.f);
        float var = (fin[2 * k + 1] - 256.f * m * m) * (1.f / 255.f);
        zn[k] = lns[(3 + k) * Hh + h] * (v[k] - m) * rsqrtf(var + 1e-6f) + lnb[(3 + k) * Hh + h];
    }
    float e[6], den = 0.f;
    #pragma unroll
    for (int k = 0; k < 6; k++) {
        e[k] = expf(sigmoidf_(zn[k]));
        den += e[k];
    }
    float inv = 1.f / den;
    float mem = tanhf(zn[6]);
    size_t idx = (size_t)bs * Hh + h;
    float c  = c_old[idx];
    float cl = (s > 0)      ? c_old[idx - Hh] : 0.f;
    float cr = (s < Ss - 1) ? c_old[idx + Hh] : 0.f;
    float cn = (e[1] * cl + e[2] * cr + e[3] * c + e[0] * mem + e[4] * gc[b * Hh + h]) * inv;
    float mk = mask[bs];
    float hv = e[5] * inv * tanhf(cn) * mk;
    h_new[idx] = hv;
    c_new[idx] = cn * mk;
    splitbf(hv, hhi[idx], hlo[idx]);
}

// ---------------- orchestration ----------------------------------------------
extern "C" void kernel_launch(void* const* d_in, const int* in_sizes, int n_in,
                              void* d_out, int out_size)
{
    (void)in_sizes; (void)n_in; (void)out_size;
    const float* inputs = (const float*)d_in[0];
    const float* mask   = (const float*)d_in[1];
    const float* ih     = (const float*)d_in[2];
    const float* ic     = (const float*)d_in[3];
    const float* Wc     = (const float*)d_in[4];
    const float* Wh     = (const float*)d_in[5];
    const float* Wi     = (const float*)d_in[6];
    const float* bi     = (const float*)d_in[7];
    const float* Wg     = (const float*)d_in[8];
    const float* Gi     = (const float*)d_in[9];
    const float* gb     = (const float*)d_in[10];
    const float* Gh     = (const float*)d_in[11];
    const float* Ga     = (const float*)d_in[12];
    const float* lns    = (const float*)d_in[13];
    const float* lnb    = (const float*)d_in[14];
    float* out = (float*)d_out;

    float *hb0, *hb1, *cb0, *cb1, *proj, *zb, *ph;
    float *pi, *pa, *ig, *og, *gh, *gc, *havg, *gWg, *pnum, *pden, *invms;
    __nv_bfloat16 *chi, *clo, *hh0, *hl0, *hh1, *hl1, *inh, *inl;
    __nv_bfloat16 *w3h, *w3l, *ghh, *ghl, *wih, *wil;
    cudaGetSymbolAddress((void**)&hb0,  d_hbuf0);
    cudaGetSymbolAddress((void**)&hb1,  d_hbuf1);
    cudaGetSymbolAddress((void**)&cb0,  d_cbuf0);
    cudaGetSymbolAddress((void**)&cb1,  d_cbuf1);
    cudaGetSymbolAddress((void**)&proj, d_proj);
    cudaGetSymbolAddress((void**)&zb,   d_zbuf);
    cudaGetSymbolAddress((void**)&ph,   d_ph);
    cudaGetSymbolAddress((void**)&pi,   d_pi);
    cudaGetSymbolAddress((void**)&pa,   d_pa);
    cudaGetSymbolAddress((void**)&ig,   d_igb);
    cudaGetSymbolAddress((void**)&og,   d_ogb);
    cudaGetSymbolAddress((void**)&gh,   d_gh);
    cudaGetSymbolAddress((void**)&gc,   d_gcv);
    cudaGetSymbolAddress((void**)&havg, d_havg);
    cudaGetSymbolAddress((void**)&gWg,  d_gWg);
    cudaGetSymbolAddress((void**)&pnum, d_pnum);
    cudaGetSymbolAddress((void**)&pden, d_pden);
    cudaGetSymbolAddress((void**)&invms, d_invms);
    cudaGetSymbolAddress((void**)&chi, d_ctx_hi);
    cudaGetSymbolAddress((void**)&clo, d_ctx_lo);
    cudaGetSymbolAddress((void**)&hh0, d_h_hi0);
    cudaGetSymbolAddress((void**)&hl0, d_h_lo0);
    cudaGetSymbolAddress((void**)&hh1, d_h_hi1);
    cudaGetSymbolAddress((void**)&hl1, d_h_lo1);
    cudaGetSymbolAddress((void**)&inh, d_in_hi);
    cudaGetSymbolAddress((void**)&inl, d_in_lo);
    cudaGetSymbolAddress((void**)&w3h, d_W3T_hi);
    cudaGetSymbolAddress((void**)&w3l, d_W3T_lo);
    cudaGetSymbolAddress((void**)&ghh, d_GhT_hi);
    cudaGetSymbolAddress((void**)&ghl, d_GhT_lo);
    cudaGetSymbolAddress((void**)&wih, d_WiT_hi);
    cudaGetSymbolAddress((void**)&wil, d_WiT_lo);

    cudaFuncSetAttribute(k_hmma, cudaFuncAttributeMaxDynamicSharedMemorySize, HSMEM);

    // streams/events created once in the (uncaptured) correctness call,
    // reused by the capture call. No device memory involved.
    static cudaStream_t s2 = [] {
        cudaStream_t s; cudaStreamCreateWithFlags(&s, cudaStreamNonBlocking); return s;
    }();
    static cudaStream_t s3 = [] {
        cudaStream_t s; cudaStreamCreateWithFlags(&s, cudaStreamNonBlocking); return s;
    }();
    static cudaEvent_t evFork = [] {
        cudaEvent_t e; cudaEventCreateWithFlags(&e, cudaEventDisableTiming); return e;
    }();
    static cudaEvent_t evJoin = [] {
        cudaEvent_t e; cudaEventCreateWithFlags(&e, cudaEventDisableTiming); return e;
    }();
    static cudaEvent_t evPh = [] {
        cudaEvent_t e; cudaEventCreateWithFlags(&e, cudaEventDisableTiming); return e;
    }();

    // layer-invariant precompute (main stream)
    k_invms<<<Bb, 256>>>(mask, invms);
    k_meanp<<<dim3(NCH, Bb), 256>>>(ih, mask, pnum);
    k_meanf<<<Bb, 256>>>(pnum, invms, gh);
    k_meanp<<<dim3(NCH, Bb), 256>>>(ic, mask, pnum);
    k_meanf<<<Bb, 256>>>(pnum, invms, gc);
    k_w3t<<<(H7 * H3 + 255) / 256, 256>>>(Wc, Wh, w3h, w3l);
    k_wt<<<(Hh * Hh + 255) / 256, 256>>>(Gh, Hh, Hh, ghh, ghl);
    k_wt<<<(H7 * Hh + 255) / 256, 256>>>(Wi, Hh, H7, wih, wil);
    k_split<<<(BSR * Hh + 255) / 256, 256>>>(ih, hh0, hl0, BSR * Hh);
    k_split<<<(BSR * Hh + 255) / 256, 256>>>(inputs, inh, inl, BSR * Hh);
    k_hmma<<<dim3(H7 / 128, BSR / 128), 256, HSMEM>>>(
        BSR, H7, Hh, inh, inl, wih, wil, bi, proj);

    float* hbufs[2] = { hb0, hb1 };
    float* cbufs[2] = { cb0, cb1 };
    __nv_bfloat16* hhis[2] = { hh0, hh1 };
    __nv_bfloat16* hlos[2] = { hl0, hl1 };

    for (int l = 0; l < LL; l++) {
        const float* hid = (l == 0) ? ih : hbufs[l & 1];
        const float* cel = (l == 0) ? ic : cbufs[l & 1];
        const __nv_bfloat16* hhi = hhis[l & 1];
        const __nv_bfloat16* hlo = hlos[l & 1];
        float* hout = (l == LL - 1) ? out : hbufs[(l + 1) & 1];
        float* cout = cbufs[(l + 1) & 1];

        // fork: both GEMM branches depend only on hidden from prev update
        cudaEventRecord(evFork, 0);
        // s2: z-branch (ctx + z-GEMM)
        cudaStreamWaitEvent(s2, evFork, 0);
        k_ctx_bf<<<(BSR * (H3 / 8) + 255) / 256, 256, 0, s2>>>(hhi, hlo, chi, clo);
        k_hmma<<<dim3(H7 / 128, BSR / 128), 256, HSMEM, s2>>>(
            BSR, H7, H3, chi, clo, w3h, w3l, (const float*)nullptr, zb);
        cudaEventRecord(evJoin, s2);
        // s3: ph-branch (hidden @ Gh)
        cudaStreamWaitEvent(s3, evFork, 0);
        k_hmma<<<dim3(Hh / 128, BSR / 128), 256, HSMEM, s3>>>(
            BSR, Hh, Hh, hhi, hlo, ghh, ghl, (const float*)nullptr, ph);
        cudaEventRecord(evPh, s3);

        // ---- global state chain (main stream, concurrent with both) ----
        k_meanp<<<dim3(NCH, Bb), 256>>>(hid, mask, pnum);
        k_meanf<<<Bb, 256>>>(pnum, invms, havg);
        k_smallgemm<<<(Bb * H3 + 255) / 256, 256>>>(Bb, H3, Hh, gh, Gi, gb, pi);
        k_smallgemm<<<(Bb * 2 * Hh + 255) / 256, 256>>>(Bb, 2 * Hh, Hh, havg, Ga,
                                                        (const float*)nullptr, pa);
        k_igog<<<Bb, 256>>>(pi, pa, lns, lnb, ig, og);
        cudaStreamWaitEvent(0, evPh, 0);
        k_hgcp<<<dim3(NCH, Bb), 256>>>(ph, pi, mask, lns, lnb, cel, pnum, pden);
        k_gcf<<<Bb, 256>>>(pnum, pden, ig, og, gc, gh);
        k_smallgemm<<<(Bb * H7 + 255) / 256, 256>>>(Bb, H7, Hh, gh, Wg,
                                                    (const float*)nullptr, gWg);

        // join: update needs z (s2) + gWg/gc (main)
        cudaStreamWaitEvent(0, evJoin, 0);
        k_update<<<BSR, 256>>>(zb, proj, gWg, gc, mask, lns, lnb, cel, hout, cout,
                               hhis[(l + 1) & 1], hlos[(l + 1) & 1]);
    }
}

// round 10
// speedup vs baseline: 1.9305x; 1.0045x over previous
#include <cuda_runtime.h>
#include <cuda_bf16.h>
#include <cstdint>
#include <cstddef>

// Problem constants
#define Bb 8
#define Ss 1024
#define Hh 256
#define LL 7
#define BSR (Bb*Ss)        // 8192 rows
#define H7 (7*Hh)          // 1792
#define H3 (3*Hh)          // 768
#define NCH 64
#define SCH (Ss/NCH)       // 16

// ---------------- scratch (device globals; no allocations allowed) ----------
__device__ float d_hbuf0[BSR*Hh];
__device__ float d_hbuf1[BSR*Hh];
__device__ float d_cbuf0[BSR*Hh];
__device__ float d_cbuf1[BSR*Hh];
__device__ float d_proj[(size_t)BSR*H7];
__device__ float d_zbuf[(size_t)BSR*H7];
__device__ float d_ph[BSR*Hh];
__device__ float d_pi[Bb*H3];
__device__ float d_pa[Bb*2*Hh];
__device__ float d_igb[Bb*Hh];
__device__ float d_ogb[Bb*Hh];
__device__ float d_gh[Bb*Hh];
__device__ float d_gcv[Bb*Hh];
__device__ float d_havg[Bb*Hh];
__device__ float d_gWg[Bb*H7];
__device__ float d_pnum[Bb*NCH*Hh];
__device__ float d_pden[Bb*NCH*Hh];
__device__ float d_invms[Bb];
// split-bf16 activations / weights (16B aligned for uint4 / cp.async)
__device__ __align__(16) __nv_bfloat16 d_ctx_hi[(size_t)BSR*H3];
__device__ __align__(16) __nv_bfloat16 d_ctx_lo[(size_t)BSR*H3];
__device__ __align__(16) __nv_bfloat16 d_h_hi0[BSR*Hh];
__device__ __align__(16) __nv_bfloat16 d_h_lo0[BSR*Hh];
__device__ __align__(16) __nv_bfloat16 d_h_hi1[BSR*Hh];
__device__ __align__(16) __nv_bfloat16 d_h_lo1[BSR*Hh];
__device__ __align__(16) __nv_bfloat16 d_in_hi[BSR*Hh];
__device__ __align__(16) __nv_bfloat16 d_in_lo[BSR*Hh];
__device__ __align__(16) __nv_bfloat16 d_W3T_hi[H7*H3];
__device__ __align__(16) __nv_bfloat16 d_W3T_lo[H7*H3];
__device__ __align__(16) __nv_bfloat16 d_GhT_hi[Hh*Hh];
__device__ __align__(16) __nv_bfloat16 d_GhT_lo[Hh*Hh];
__device__ __align__(16) __nv_bfloat16 d_WiT_hi[H7*Hh];
__device__ __align__(16) __nv_bfloat16 d_WiT_lo[H7*Hh];

// ---------------- PTX helpers -----------------------------------------------
__device__ __forceinline__ uint32_t smem_u32(const void* p) {
    uint32_t a;
    asm("{ .reg .u64 t; cvta.to.shared.u64 t, %1; cvt.u32.u64 %0, t; }"
        : "=r"(a) : "l"(p));
    return a;
}
__device__ __forceinline__ void cpasync16(uint32_t dst, const void* src) {
    asm volatile("cp.async.cg.shared.global [%0], [%1], 16;" :: "r"(dst), "l"(src));
}
#define CP_COMMIT() asm volatile("cp.async.commit_group;" ::: "memory")
#define CP_WAIT1()  asm volatile("cp.async.wait_group 1;" ::: "memory")
#define CP_WAIT0()  asm volatile("cp.async.wait_group 0;" ::: "memory")

__device__ __forceinline__ void mma16816(float* c, const uint32_t* a, const uint32_t* b) {
    asm volatile(
        "mma.sync.aligned.m16n8k16.row.col.f32.bf16.bf16.f32 "
        "{%0,%1,%2,%3}, {%4,%5,%6,%7}, {%8,%9}, {%0,%1,%2,%3};"
        : "+f"(c[0]), "+f"(c[1]), "+f"(c[2]), "+f"(c[3])
        : "r"(a[0]), "r"(a[1]), "r"(a[2]), "r"(a[3]), "r"(b[0]), "r"(b[1]));
}

// ---------------- bf16x3 HMMA GEMM (2 CTAs/SM for latency hiding) ------------
#define KB 32
#define SA 40                      // padded smem row stride (halves)
#define MTILE (128*SA)
#define STAGE (4*MTILE)            // Ahi, Alo, Bhi, Blo
#define HSMEM (2*STAGE*2)          // 81920 bytes

__global__ void __launch_bounds__(256, 2) k_hmma(
    int M, int N, int K,
    const __nv_bfloat16* __restrict__ Ahi, const __nv_bfloat16* __restrict__ Alo,
    const __nv_bfloat16* __restrict__ Bhi, const __nv_bfloat16* __restrict__ Blo,
    const float* __restrict__ bias, const float* __restrict__ add,
    float* __restrict__ C)
{
    extern __shared__ __nv_bfloat16 sm[];
    int tid = threadIdx.x, wid = tid >> 5, lane = tid & 31;
    int gID = lane >> 2, tg = lane & 3;
    int warp_m = wid >> 2, warp_n = wid & 3;
    int arow0 = blockIdx.y * 128, bcol0 = blockIdx.x * 128;

    const __nv_bfloat16* srcs[4] = {
        Ahi + (size_t)arow0 * K, Alo + (size_t)arow0 * K,
        Bhi + (size_t)bcol0 * K, Blo + (size_t)bcol0 * K };

    float acc[4][4][4];
    #pragma unroll
    for (int mi = 0; mi < 4; mi++)
        #pragma unroll
        for (int ni = 0; ni < 4; ni++)
            #pragma unroll
            for (int q = 0; q < 4; q++) acc[mi][ni][q] = 0.f;

    uint32_t smbase = smem_u32(sm);
    int niter = K / KB;

    // prologue: stage 0
    #pragma unroll
    for (int t = 0; t < 4; t++) {
        const __nv_bfloat16* src = srcs[t];
        uint32_t dst = smbase + (0 * STAGE + t * MTILE) * 2;
        #pragma unroll
        for (int s = 0; s < 2; s++) {
            int slot = tid + s * 256;
            int row = slot >> 2, cg = (slot & 3) * 8;
            cpasync16(dst + (row * SA + cg) * 2, src + (size_t)row * K + cg);
        }
    }
    CP_COMMIT();

    for (int it = 0; it < niter; it++) {
        if (it + 1 < niter) {
            int st = (it + 1) & 1;
            int k0 = (it + 1) * KB;
            #pragma unroll
            for (int t = 0; t < 4; t++) {
                const __nv_bfloat16* src = srcs[t] + k0;
                uint32_t dst = smbase + (st * STAGE + t * MTILE) * 2;
                #pragma unroll
                for (int s = 0; s < 2; s++) {
                    int slot = tid + s * 256;
                    int row = slot >> 2, cg = (slot & 3) * 8;
                    cpasync16(dst + (row * SA + cg) * 2, src + (size_t)row * K + cg);
                }
            }
            CP_COMMIT();
            CP_WAIT1();
        } else {
            CP_WAIT0();
        }
        __syncthreads();

        const __nv_bfloat16* As_h = sm + (it & 1) * STAGE;
        const __nv_bfloat16* As_l = As_h + MTILE;
        const __nv_bfloat16* Bs_h = As_h + 2 * MTILE;
        const __nv_bfloat16* Bs_l = As_h + 3 * MTILE;

        #pragma unroll
        for (int kk = 0; kk < KB; kk += 16) {
            uint32_t bh[4][2], bl[4][2];
            #pragma unroll
            for (int ni = 0; ni < 4; ni++) {
                int n = warp_n * 32 + ni * 8 + gID;
                const __nv_bfloat16* ph_ = Bs_h + n * SA + kk + tg * 2;
                const __nv_bfloat16* pl_ = Bs_l + n * SA + kk + tg * 2;
                bh[ni][0] = *(const uint32_t*)ph_;
                bh[ni][1] = *(const uint32_t*)(ph_ + 8);
                bl[ni][0] = *(const uint32_t*)pl_;
                bl[ni][1] = *(const uint32_t*)(pl_ + 8);
            }
            #pragma unroll
            for (int mi = 0; mi < 4; mi++) {
                int r0 = warp_m * 64 + mi * 16 + gID;
                const __nv_bfloat16* ah_ = As_h + r0 * SA + kk + tg * 2;
                const __nv_bfloat16* al_ = As_l + r0 * SA + kk + tg * 2;
                uint32_t ah[4], al[4];
                ah[0] = *(const uint32_t*)ah_;
                ah[1] = *(const uint32_t*)(ah_ + 8 * SA);
                ah[2] = *(const uint32_t*)(ah_ + 8);
                ah[3] = *(const uint32_t*)(ah_ + 8 * SA + 8);
                al[0] = *(const uint32_t*)al_;
                al[1] = *(const uint32_t*)(al_ + 8 * SA);
                al[2] = *(const uint32_t*)(al_ + 8);
                al[3] = *(const uint32_t*)(al_ + 8 * SA + 8);
                #pragma unroll
                for (int ni = 0; ni < 4; ni++) {
                    mma16816(acc[mi][ni], ah, bh[ni]);
                    mma16816(acc[mi][ni], ah, bl[ni]);
                    mma16816(acc[mi][ni], al, bh[ni]);
                }
            }
        }
        __syncthreads();
    }

    // epilogue: C = acc (+bias[c]) (+add[r,c])
    #pragma unroll
    for (int mi = 0; mi < 4; mi++) {
        #pragma unroll
        for (int ni = 0; ni < 4; ni++) {
            int r = arow0 + warp_m * 64 + mi * 16 + gID;
            int c = bcol0 + warp_n * 32 + ni * 8 + tg * 2;
            float b0 = bias ? bias[c] : 0.f;
            float b1 = bias ? bias[c + 1] : 0.f;
            float2 v0 = make_float2(acc[mi][ni][0] + b0, acc[mi][ni][1] + b1);
            float2 v1 = make_float2(acc[mi][ni][2] + b0, acc[mi][ni][3] + b1);
            if (add) {
                float2 a0 = *(const float2*)(add + (size_t)r * N + c);
                float2 a1 = *(const float2*)(add + (size_t)(r + 8) * N + c);
                v0.x += a0.x; v0.y += a0.y;
                v1.x += a1.x; v1.y += a1.y;
            }
            *(float2*)(C + (size_t)r * N + c) = v0;
            *(float2*)(C + (size_t)(r + 8) * N + c) = v1;
        }
    }
}

// ---------------- helpers ----------------------------------------------------
__device__ __forceinline__ float2 blockSum2(float a, float b, float* sh) {
    #pragma unroll
    for (int o = 16; o > 0; o >>= 1) {
        a += __shfl_down_sync(0xffffffffu, a, o);
        b += __shfl_down_sync(0xffffffffu, b, o);
    }
    int w = threadIdx.x >> 5, l = threadIdx.x & 31;
    if (l == 0) { sh[w] = a; sh[8 + w] = b; }
    __syncthreads();
    if (threadIdx.x == 0) {
        float sa = 0.f, sb2 = 0.f;
        #pragma unroll
        for (int i = 0; i < 8; i++) { sa += sh[i]; sb2 += sh[8 + i]; }
        sh[16] = sa; sh[17] = sb2;
    }
    __syncthreads();
    float2 r = make_float2(sh[16], sh[17]);
    __syncthreads();
    return r;
}
__device__ __forceinline__ float sigmoidf_(float x) { return 1.f / (1.f + expf(-x)); }
__device__ __forceinline__ void splitbf(float v, __nv_bfloat16& hi, __nv_bfloat16& lo) {
    hi = __float2bfloat16(v);
    lo = __float2bfloat16(v - __bfloat162float(hi));
}

// ---------------- split / transpose kernels ----------------------------------
__global__ void k_split(const float* __restrict__ x, __nv_bfloat16* __restrict__ hi,
                        __nv_bfloat16* __restrict__ lo, int n)
{
    int i = blockIdx.x * blockDim.x + threadIdx.x;
    if (i >= n) return;
    splitbf(x[i], hi[i], lo[i]);
}

__global__ void k_w3t(const float* __restrict__ Wc, const float* __restrict__ Wh,
                      __nv_bfloat16* __restrict__ hi, __nv_bfloat16* __restrict__ lo)
{
    int i = blockIdx.x * blockDim.x + threadIdx.x;   // [H7 x H3]
    if (i >= H7 * H3) return;
    int n = i / H3, k = i % H3;
    float v = (k < Hh) ? Wc[(size_t)k * H7 + n]
            : (k < 2 * Hh) ? Wh[(size_t)(k - Hh) * H7 + n]
            : Wc[(size_t)(k - Hh) * H7 + n];
    splitbf(v, hi[i], lo[i]);
}

__global__ void k_wt(const float* __restrict__ W, int K, int N,
                     __nv_bfloat16* __restrict__ hi, __nv_bfloat16* __restrict__ lo)
{
    int i = blockIdx.x * blockDim.x + threadIdx.x;   // [N x K]
    if (i >= N * K) return;
    int n = i / K, k = i % K;
    splitbf(W[(size_t)k * N + n], hi[i], lo[i]);
}

// ---------------- tiny GEMM for M=8 rows -------------------------------------
__global__ void k_smallgemm(int M, int N, int K,
                            const float* __restrict__ A, const float* __restrict__ W,
                            const float* __restrict__ bias, float* __restrict__ C)
{
    int idx = blockIdx.x * blockDim.x + threadIdx.x;
    if (idx >= M * N) return;
    int m = idx / N, n = idx % N;
    float acc = bias ? bias[n] : 0.f;
    const float* a = A + (size_t)m * K;
    for (int k = 0; k < K; k++) acc += a[k] * W[(size_t)k * N + n];
    C[idx] = acc;
}

// ---------------- small kernels ----------------------------------------------
__global__ void k_invms(const float* __restrict__ mask, float* __restrict__ invms)
{
    __shared__ float sh[8];
    int b = blockIdx.x, t = threadIdx.x;
    float a = 0.f;
    for (int s = t; s < Ss; s += 256) a += mask[b * Ss + s];
    #pragma unroll
    for (int o = 16; o > 0; o >>= 1) a += __shfl_down_sync(0xffffffffu, a, o);
    if ((t & 31) == 0) sh[t >> 5] = a;
    __syncthreads();
    if (t == 0) {
        float s2 = 0.f;
        #pragma unroll
        for (int i = 0; i < 8; i++) s2 += sh[i];
        invms[b] = 1.f / s2;
    }
}

__global__ void k_meanp(const float* __restrict__ x, const float* __restrict__ mask,
                        float* __restrict__ pnum)
{
    int ch = blockIdx.x, b = blockIdx.y, h = threadIdx.x;
    float acc = 0.f;
    int s0 = ch * SCH;
    #pragma unroll
    for (int i = 0; i < SCH; i++) {
        int s = s0 + i;
        acc += x[((size_t)(b * Ss + s)) * Hh + h] * mask[b * Ss + s];
    }
    pnum[(b * NCH + ch) * Hh + h] = acc;
}

__global__ void k_meanf(const float* __restrict__ pnum, const float* __restrict__ invms,
                        float* __restrict__ out)
{
    int b = blockIdx.x, h = threadIdx.x;
    float a = 0.f;
    #pragma unroll
    for (int c = 0; c < NCH; c++) a += pnum[(b * NCH + c) * Hh + h];
    out[b * Hh + h] = a * invms[b];
}

__global__ void k_igog(const float* __restrict__ pi, const float* __restrict__ pa,
                       const float* __restrict__ lns, const float* __restrict__ lnb,
                       float* __restrict__ ig, float* __restrict__ og)
{
    __shared__ float sh[18];
    int b = blockIdx.x, h = threadIdx.x;
    float v = pi[b * H3 + h] + pa[b * 2 * Hh + h];
    float2 ssum = blockSum2(v, v * v, sh);
    float m = ssum.x * (1.f / 256.f);
    float var = (ssum.y - 256.f * m * m) * (1.f / 255.f);
    float zn = lns[h] * (v - m) * rsqrtf(var + 1e-6f) + lnb[h];
    ig[b * Hh + h] = sigmoidf_(zn);
    v = pi[b * H3 + 2 * Hh + h] + pa[b * 2 * Hh + Hh + h];
    ssum = blockSum2(v, v * v, sh);
    m = ssum.x * (1.f / 256.f);
    var = (ssum.y - 256.f * m * m) * (1.f / 255.f);
    zn = lns[2 * Hh + h] * (v - m) * rsqrtf(var + 1e-6f) + lnb[2 * Hh + h];
    og[b * Hh + h] = sigmoidf_(zn);
}

// fused hg + gcp: per (chunk, batch) block, LN+sigmoid+mask+exp each of the 16
// rows (batched 32-wide reduction, 2 barriers), then softmax partial sums.
__global__ __launch_bounds__(256) void k_hgcp(
    const float* __restrict__ ph, const float* __restrict__ pi,
    const float* __restrict__ mask,
    const float* __restrict__ lns, const float* __restrict__ lnb,
    const float* __restrict__ cell,
    float* __restrict__ pnum, float* __restrict__ pden)
{
    __shared__ float wsum[8][32];
    __shared__ float fin[32];
    int ch = blockIdx.x, b = blockIdx.y, h = threadIdx.x;
    int w = h >> 5, lane = h & 31;
    int s0 = ch * SCH;
    float piv = pi[b * H3 + Hh + h];
    float v[SCH];
    #pragma unroll
    for (int i = 0; i < SCH; i++)
        v[i] = ph[((size_t)(b * Ss + s0 + i)) * Hh + h] + piv;

    float p[2 * SCH];
    #pragma unroll
    for (int i = 0; i < SCH; i++) { p[2 * i] = v[i]; p[2 * i + 1] = v[i] * v[i]; }
    #pragma unroll
    for (int o = 16; o > 0; o >>= 1)
        #pragma unroll
        for (int j = 0; j < 2 * SCH; j++)
            p[j] += __shfl_down_sync(0xffffffffu, p[j], o);
    if (lane == 0)
        #pragma unroll
        for (int j = 0; j < 2 * SCH; j++) wsum[w][j] = p[j];
    __syncthreads();
    if (h < 2 * SCH) {
        float a = 0.f;
        #pragma unroll
        for (int i = 0; i < 8; i++) a += wsum[i][h];
        fin[h] = a;
    }
    __syncthreads();

    float lnsv = lns[Hh + h], lnbv = lnb[Hh + h];
    float num = 0.f, den = 0.f;
    #pragma unroll
    for (int i = 0; i < SCH; i++) {
        float m = fin[2 * i] * (1.f / 256.f);
        float var = (fin[2 * i + 1] - 256.f * m * m) * (1.f / 255.f);
        float zn = lnsv * (v[i] - m) * rsqrtf(var + 1e-6f) + lnbv;
        float mk = mask[b * Ss + s0 + i];
        float e = expf(sigmoidf_(zn) + (mk * 1e25f - 1e25f));
        size_t idx = ((size_t)(b * Ss + s0 + i)) * Hh + h;
        num += e * cell[idx];
        den += e;
    }
    pnum[(b * NCH + ch) * Hh + h] = num;
    pden[(b * NCH + ch) * Hh + h] = den;
}

__global__ void k_gcf(const float* __restrict__ pnum, const float* __restrict__ pden,
                      const float* __restrict__ ig, const float* __restrict__ og,
                      float* __restrict__ gc, float* __restrict__ gh)
{
    int b = blockIdx.x, h = threadIdx.x;
    float num = 0.f, den = 0.f;
    #pragma unroll
    for (int c = 0; c < NCH; c++) {
        num += pnum[(b * NCH + c) * Hh + h];
        den += pden[(b * NCH + c) * Hh + h];
    }
    float ei = expf(ig[b * Hh + h]);
    float g = (gc[b * Hh + h] * ei + num) / (ei + den);
    gc[b * Hh + h] = g;
    gh[b * Hh + h] = og[b * Hh + h] * tanhf(g);
}

// build split-bf16 ctx = [h_l, h, h_r] directly from split-bf16 hidden
__global__ void k_ctx_bf(const __nv_bfloat16* __restrict__ hhi,
                         const __nv_bfloat16* __restrict__ hlo,
                         __nv_bfloat16* __restrict__ chi,
                         __nv_bfloat16* __restrict__ clo)
{
    int i = blockIdx.x * blockDim.x + threadIdx.x;  // 8-elem chunk
    if (i >= BSR * (H3 / 8)) return;
    int bs = i / (H3 / 8);
    int j = (i % (H3 / 8)) * 8;
    int s = bs & (Ss - 1);
    uint4 vh = make_uint4(0, 0, 0, 0), vl = make_uint4(0, 0, 0, 0);
    long off = -1;
    if (j < Hh)           { if (s > 0)      off = ((long)bs - 1) * Hh + j; }
    else if (j < 2 * Hh)  {                 off = (long)bs * Hh + (j - Hh); }
    else                  { if (s < Ss - 1) off = ((long)bs + 1) * Hh + (j - 2 * Hh); }
    if (off >= 0) {
        vh = *(const uint4*)(hhi + off);
        vl = *(const uint4*)(hlo + off);
    }
    *(uint4*)(chi + (size_t)bs * H3 + j) = vh;
    *(uint4*)(clo + (size_t)bs * H3 + j) = vl;
}

// one-pass LN for all 7 groups: 2 barriers instead of 21
// z already contains proj (fused in z-GEMM epilogue)
__global__ __launch_bounds__(256) void k_update(
    const float* __restrict__ z,
    const float* __restrict__ gWg, const float* __restrict__ gc,
    const float* __restrict__ mask,
    const float* __restrict__ lns, const float* __restrict__ lnb,
    const float* __restrict__ c_old,
    float* __restrict__ h_new, float* __restrict__ c_new,
    __nv_bfloat16* __restrict__ hhi, __nv_bfloat16* __restrict__ hlo)
{
    __shared__ float wsum[8][14];
    __shared__ float fin[14];
    int bs = blockIdx.x; int b = bs >> 10; int s = bs & (Ss - 1);
    int h = threadIdx.x;
    int w = h >> 5, lane = h & 31;
    size_t rz = (size_t)bs * H7;
    float v[7];
    #pragma unroll
    for (int k = 0; k < 7; k++)
        v[k] = z[rz + k * Hh + h] + gWg[b * H7 + k * Hh + h];

    float p[14];
    #pragma unroll
    for (int k = 0; k < 7; k++) { p[2 * k] = v[k]; p[2 * k + 1] = v[k] * v[k]; }
    #pragma unroll
    for (int o = 16; o > 0; o >>= 1)
        #pragma unroll
        for (int j = 0; j < 14; j++)
            p[j] += __shfl_down_sync(0xffffffffu, p[j], o);
    if (lane == 0)
        #pragma unroll
        for (int j = 0; j < 14; j++) wsum[w][j] = p[j];
    __syncthreads();
    if (h < 14) {
        float a = 0.f;
        #pragma unroll
        for (int i = 0; i < 8; i++) a += wsum[i][h];
        fin[h] = a;
    }
    __syncthreads();

    float zn[7];
    #pragma unroll
    for (int k = 0; k < 7; k++) {
        float m = fin[2 * k] * (1.f / 256.f);
        float var = (fin[2 * k + 1] - 256.f * m * m) * (1.f / 255.f);
        zn[k] = lns[(3 + k) * Hh + h] * (v[k] - m) * rsqrtf(var + 1e-6f) + lnb[(3 + k) * Hh + h];
    }
    float e[6], den = 0.f;
    #pragma unroll
    for (int k = 0; k < 6; k++) {
        e[k] = expf(sigmoidf_(zn[k]));
        den += e[k];
    }
    float inv = 1.f / den;
    float mem = tanhf(zn[6]);
    size_t idx = (size_t)bs * Hh + h;
    float c  = c_old[idx];
    float cl = (s > 0)      ? c_old[idx - Hh] : 0.f;
    float cr = (s < Ss - 1) ? c_old[idx + Hh] : 0.f;
    float cn = (e[1] * cl + e[2] * cr + e[3] * c + e[0] * mem + e[4] * gc[b * Hh + h]) * inv;
    float mk = mask[bs];
    float hv = e[5] * inv * tanhf(cn) * mk;
    h_new[idx] = hv;
    c_new[idx] = cn * mk;
    splitbf(hv, hhi[idx], hlo[idx]);
}

// ---------------- orchestration ----------------------------------------------
extern "C" void kernel_launch(void* const* d_in, const int* in_sizes, int n_in,
                              void* d_out, int out_size)
{
    (void)in_sizes; (void)n_in; (void)out_size;
    const float* inputs = (const float*)d_in[0];
    const float* mask   = (const float*)d_in[1];
    const float* ih     = (const float*)d_in[2];
    const float* ic     = (const float*)d_in[3];
    const float* Wc     = (const float*)d_in[4];
    const float* Wh     = (const float*)d_in[5];
    const float* Wi     = (const float*)d_in[6];
    const float* bi     = (const float*)d_in[7];
    const float* Wg     = (const float*)d_in[8];
    const float* Gi     = (const float*)d_in[9];
    const float* gb     = (const float*)d_in[10];
    const float* Gh     = (const float*)d_in[11];
    const float* Ga     = (const float*)d_in[12];
    const float* lns    = (const float*)d_in[13];
    const float* lnb    = (const float*)d_in[14];
    float* out = (float*)d_out;

    float *hb0, *hb1, *cb0, *cb1, *proj, *zb, *ph;
    float *pi, *pa, *ig, *og, *gh, *gc, *havg, *gWg, *pnum, *pden, *invms;
    __nv_bfloat16 *chi, *clo, *hh0, *hl0, *hh1, *hl1, *inh, *inl;
    __nv_bfloat16 *w3h, *w3l, *ghh, *ghl, *wih, *wil;
    cudaGetSymbolAddress((void**)&hb0,  d_hbuf0);
    cudaGetSymbolAddress((void**)&hb1,  d_hbuf1);
    cudaGetSymbolAddress((void**)&cb0,  d_cbuf0);
    cudaGetSymbolAddress((void**)&cb1,  d_cbuf1);
    cudaGetSymbolAddress((void**)&proj, d_proj);
    cudaGetSymbolAddress((void**)&zb,   d_zbuf);
    cudaGetSymbolAddress((void**)&ph,   d_ph);
    cudaGetSymbolAddress((void**)&pi,   d_pi);
    cudaGetSymbolAddress((void**)&pa,   d_pa);
    cudaGetSymbolAddress((void**)&ig,   d_igb);
    cudaGetSymbolAddress((void**)&og,   d_ogb);
    cudaGetSymbolAddress((void**)&gh,   d_gh);
    cudaGetSymbolAddress((void**)&gc,   d_gcv);
    cudaGetSymbolAddress((void**)&havg, d_havg);
    cudaGetSymbolAddress((void**)&gWg,  d_gWg);
    cudaGetSymbolAddress((void**)&pnum, d_pnum);
    cudaGetSymbolAddress((void**)&pden, d_pden);
    cudaGetSymbolAddress((void**)&invms, d_invms);
    cudaGetSymbolAddress((void**)&chi, d_ctx_hi);
    cudaGetSymbolAddress((void**)&clo, d_ctx_lo);
    cudaGetSymbolAddress((void**)&hh0, d_h_hi0);
    cudaGetSymbolAddress((void**)&hl0, d_h_lo0);
    cudaGetSymbolAddress((void**)&hh1, d_h_hi1);
    cudaGetSymbolAddress((void**)&hl1, d_h_lo1);
    cudaGetSymbolAddress((void**)&inh, d_in_hi);
    cudaGetSymbolAddress((void**)&inl, d_in_lo);
    cudaGetSymbolAddress((void**)&w3h, d_W3T_hi);
    cudaGetSymbolAddress((void**)&w3l, d_W3T_lo);
    cudaGetSymbolAddress((void**)&ghh, d_GhT_hi);
    cudaGetSymbolAddress((void**)&ghl, d_GhT_lo);
    cudaGetSymbolAddress((void**)&wih, d_WiT_hi);
    cudaGetSymbolAddress((void**)&wil, d_WiT_lo);

    cudaFuncSetAttribute(k_hmma, cudaFuncAttributeMaxDynamicSharedMemorySize, HSMEM);

    // streams/events created once in the (uncaptured) correctness call,
    // reused by the capture call. No device memory involved.
    static cudaStream_t s2 = [] {
        cudaStream_t s; cudaStreamCreateWithFlags(&s, cudaStreamNonBlocking); return s;
    }();
    static cudaStream_t s3 = [] {
        cudaStream_t s; cudaStreamCreateWithFlags(&s, cudaStreamNonBlocking); return s;
    }();
    static cudaEvent_t evFork = [] {
        cudaEvent_t e; cudaEventCreateWithFlags(&e, cudaEventDisableTiming); return e;
    }();
    static cudaEvent_t evJoin = [] {
        cudaEvent_t e; cudaEventCreateWithFlags(&e, cudaEventDisableTiming); return e;
    }();
    static cudaEvent_t evPh = [] {
        cudaEvent_t e; cudaEventCreateWithFlags(&e, cudaEventDisableTiming); return e;
    }();

    // layer-invariant precompute (main stream)
    k_invms<<<Bb, 256>>>(mask, invms);
    k_meanp<<<dim3(NCH, Bb), 256>>>(ih, mask, pnum);
    k_meanf<<<Bb, 256>>>(pnum, invms, gh);
    k_meanp<<<dim3(NCH, Bb), 256>>>(ic, mask, pnum);
    k_meanf<<<Bb, 256>>>(pnum, invms, gc);
    k_w3t<<<(H7 * H3 + 255) / 256, 256>>>(Wc, Wh, w3h, w3l);
    k_wt<<<(Hh * Hh + 255) / 256, 256>>>(Gh, Hh, Hh, ghh, ghl);
    k_wt<<<(H7 * Hh + 255) / 256, 256>>>(Wi, Hh, H7, wih, wil);
    k_split<<<(BSR * Hh + 255) / 256, 256>>>(ih, hh0, hl0, BSR * Hh);
    k_split<<<(BSR * Hh + 255) / 256, 256>>>(inputs, inh, inl, BSR * Hh);
    k_hmma<<<dim3(H7 / 128, BSR / 128), 256, HSMEM>>>(
        BSR, H7, Hh, inh, inl, wih, wil, bi, (const float*)nullptr, proj);

    float* hbufs[2] = { hb0, hb1 };
    float* cbufs[2] = { cb0, cb1 };
    __nv_bfloat16* hhis[2] = { hh0, hh1 };
    __nv_bfloat16* hlos[2] = { hl0, hl1 };

    for (int l = 0; l < LL; l++) {
        const float* hid = (l == 0) ? ih : hbufs[l & 1];
        const float* cel = (l == 0) ? ic : cbufs[l & 1];
        const __nv_bfloat16* hhi = hhis[l & 1];
        const __nv_bfloat16* hlo = hlos[l & 1];
        float* hout = (l == LL - 1) ? out : hbufs[(l + 1) & 1];
        float* cout = cbufs[(l + 1) & 1];

        // fork: both GEMM branches depend only on hidden from prev update
        cudaEventRecord(evFork, 0);
        // s2: z-branch (ctx + z-GEMM, proj fused into epilogue)
        cudaStreamWaitEvent(s2, evFork, 0);
        k_ctx_bf<<<(BSR * (H3 / 8) + 255) / 256, 256, 0, s2>>>(hhi, hlo, chi, clo);
        k_hmma<<<dim3(H7 / 128, BSR / 128), 256, HSMEM, s2>>>(
            BSR, H7, H3, chi, clo, w3h, w3l, (const float*)nullptr, proj, zb);
        cudaEventRecord(evJoin, s2);
        // s3: ph-branch (hidden @ Gh)
        cudaStreamWaitEvent(s3, evFork, 0);
        k_hmma<<<dim3(Hh / 128, BSR / 128), 256, HSMEM, s3>>>(
            BSR, Hh, Hh, hhi, hlo, ghh, ghl,
            (const float*)nullptr, (const float*)nullptr, ph);
        cudaEventRecord(evPh, s3);

        // ---- global state chain (main stream, concurrent with both) ----
        k_meanp<<<dim3(NCH, Bb), 256>>>(hid, mask, pnum);
        k_meanf<<<Bb, 256>>>(pnum, invms, havg);
        k_smallgemm<<<(Bb * H3 + 255) / 256, 256>>>(Bb, H3, Hh, gh, Gi, gb, pi);
        k_smallgemm<<<(Bb * 2 * Hh + 255) / 256, 256>>>(Bb, 2 * Hh, Hh, havg, Ga,
                                                        (const float*)nullptr, pa);
        k_igog<<<Bb, 256>>>(pi, pa, lns, lnb, ig, og);
        cudaStreamWaitEvent(0, evPh, 0);
        k_hgcp<<<dim3(NCH, Bb), 256>>>(ph, pi, mask, lns, lnb, cel, pnum, pden);
        k_gcf<<<Bb, 256>>>(pnum, pden, ig, og, gc, gh);
        k_smallgemm<<<(Bb * H7 + 255) / 256, 256>>>(Bb, H7, Hh, gh, Wg,
                                                    (const float*)nullptr, gWg);

        // join: update needs z (s2) + gWg/gc (main)
        cudaStreamWaitEvent(0, evJoin, 0);
        k_update<<<BSR, 256>>>(zb, gWg, gc, mask, lns, lnb, cel, hout, cout,
                               hhis[(l + 1) & 1], hlos[(l + 1) & 1]);
    }
}

// round 12
// speedup vs baseline: 2.2285x; 1.1543x over previous
#include <cuda_runtime.h>
#include <cuda_fp16.h>
#include <cstdint>
#include <cstddef>

// Problem constants
#define Bb 8
#define Ss 1024
#define Hh 256
#define LL 7
#define BSR (Bb*Ss)        // 8192 rows
#define H7 (7*Hh)          // 1792
#define H3 (3*Hh)          // 768
#define NCH 64
#define SCH (Ss/NCH)       // 16

// ---------------- scratch (device globals; no allocations allowed) ----------
__device__ float d_hbuf0[BSR*Hh];
__device__ float d_hbuf1[BSR*Hh];
__device__ float d_cbuf0[BSR*Hh];
__device__ float d_cbuf1[BSR*Hh];
__device__ float d_proj[(size_t)BSR*H7];
__device__ float d_zbuf[(size_t)BSR*H7];
__device__ float d_ph[BSR*Hh];
__device__ float d_pi[Bb*H3];
__device__ float d_pa[Bb*2*Hh];
__device__ float d_igb[Bb*Hh];
__device__ float d_ogb[Bb*Hh];
__device__ float d_gh[Bb*Hh];
__device__ float d_gcv[Bb*Hh];
__device__ float d_havg[Bb*Hh];
__device__ float d_gWg[Bb*H7];
__device__ float d_pnum[Bb*NCH*Hh];
__device__ float d_pden[Bb*NCH*Hh];
__device__ float d_invms[Bb];
// fp16 split activations (hi+lo) / fp16 single-rounded weights (16B aligned)
__device__ __align__(16) __half d_ctx_hi[(size_t)BSR*H3];
__device__ __align__(16) __half d_ctx_lo[(size_t)BSR*H3];
__device__ __align__(16) __half d_h_hi0[BSR*Hh];
__device__ __align__(16) __half d_h_lo0[BSR*Hh];
__device__ __align__(16) __half d_h_hi1[BSR*Hh];
__device__ __align__(16) __half d_h_lo1[BSR*Hh];
__device__ __align__(16) __half d_in_hi[BSR*Hh];
__device__ __align__(16) __half d_in_lo[BSR*Hh];
__device__ __align__(16) __half d_W3T[H7*H3];
__device__ __align__(16) __half d_GhT[Hh*Hh];
__device__ __align__(16) __half d_WiT[H7*Hh];

// ---------------- PTX helpers -----------------------------------------------
__device__ __forceinline__ uint32_t smem_u32(const void* p) {
    uint32_t a;
    asm("{ .reg .u64 t; cvta.to.shared.u64 t, %1; cvt.u32.u64 %0, t; }"
        : "=r"(a) : "l"(p));
    return a;
}
__device__ __forceinline__ void cpasync16(uint32_t dst, const void* src) {
    asm volatile("cp.async.cg.shared.global [%0], [%1], 16;" :: "r"(dst), "l"(src));
}
#define CP_COMMIT() asm volatile("cp.async.commit_group;" ::: "memory")
#define CP_WAIT1()  asm volatile("cp.async.wait_group 1;" ::: "memory")
#define CP_WAIT0()  asm volatile("cp.async.wait_group 0;" ::: "memory")

__device__ __forceinline__ void mma16816(float* c, const uint32_t* a, const uint32_t* b) {
    asm volatile(
        "mma.sync.aligned.m16n8k16.row.col.f32.f16.f16.f32 "
        "{%0,%1,%2,%3}, {%4,%5,%6,%7}, {%8,%9}, {%0,%1,%2,%3};"
        : "+f"(c[0]), "+f"(c[1]), "+f"(c[2]), "+f"(c[3])
        : "r"(a[0]), "r"(a[1]), "r"(a[2]), "r"(a[3]), "r"(b[0]), "r"(b[1]));
}

// ---------------- fp16x2 HMMA GEMM (A split hi/lo, B single fp16) ------------
// C[M,N] = (Ahi+Alo)[M,K] @ B^T, B stored [N,K] K-major fp16.
#define KB 32
#define SA 40                      // padded smem row stride (halves)
#define MTILE (128*SA)
#define STAGE (3*MTILE)            // Ahi, Alo, B
#define HSMEM (2*STAGE*2)          // 61440 bytes

__global__ void __launch_bounds__(256, 2) k_hmma(
    int M, int N, int K,
    const __half* __restrict__ Ahi, const __half* __restrict__ Alo,
    const __half* __restrict__ B,
    const float* __restrict__ bias, const float* __restrict__ add,
    float* __restrict__ C)
{
    extern __shared__ __half sm[];
    int tid = threadIdx.x, wid = tid >> 5, lane = tid & 31;
    int gID = lane >> 2, tg = lane & 3;
    int warp_m = wid >> 2, warp_n = wid & 3;
    int arow0 = blockIdx.y * 128, bcol0 = blockIdx.x * 128;

    const __half* srcs[3] = {
        Ahi + (size_t)arow0 * K, Alo + (size_t)arow0 * K,
        B + (size_t)bcol0 * K };

    float acc[4][4][4];
    #pragma unroll
    for (int mi = 0; mi < 4; mi++)
        #pragma unroll
        for (int ni = 0; ni < 4; ni++)
            #pragma unroll
            for (int q = 0; q < 4; q++) acc[mi][ni][q] = 0.f;

    uint32_t smbase = smem_u32(sm);
    int niter = K / KB;

    // prologue: stage 0
    #pragma unroll
    for (int t = 0; t < 3; t++) {
        const __half* src = srcs[t];
        uint32_t dst = smbase + (0 * STAGE + t * MTILE) * 2;
        #pragma unroll
        for (int s = 0; s < 2; s++) {
            int slot = tid + s * 256;
            int row = slot >> 2, cg = (slot & 3) * 8;
            cpasync16(dst + (row * SA + cg) * 2, src + (size_t)row * K + cg);
        }
    }
    CP_COMMIT();

    for (int it = 0; it < niter; it++) {
        if (it + 1 < niter) {
            int st = (it + 1) & 1;
            int k0 = (it + 1) * KB;
            #pragma unroll
            for (int t = 0; t < 3; t++) {
                const __half* src = srcs[t] + k0;
                uint32_t dst = smbase + (st * STAGE + t * MTILE) * 2;
                #pragma unroll
                for (int s = 0; s < 2; s++) {
                    int slot = tid + s * 256;
                    int row = slot >> 2, cg = (slot & 3) * 8;
                    cpasync16(dst + (row * SA + cg) * 2, src + (size_t)row * K + cg);
                }
            }
            CP_COMMIT();
            CP_WAIT1();
        } else {
            CP_WAIT0();
        }
        __syncthreads();

        const __half* As_h = sm + (it & 1) * STAGE;
        const __half* As_l = As_h + MTILE;
        const __half* Bs   = As_h + 2 * MTILE;

        #pragma unroll
        for (int kk = 0; kk < KB; kk += 16) {
            uint32_t bf[4][2];
            #pragma unroll
            for (int ni = 0; ni < 4; ni++) {
                int n = warp_n * 32 + ni * 8 + gID;
                const __half* pb = Bs + n * SA + kk + tg * 2;
                bf[ni][0] = *(const uint32_t*)pb;
                bf[ni][1] = *(const uint32_t*)(pb + 8);
            }
            #pragma unroll
            for (int mi = 0; mi < 4; mi++) {
                int r0 = warp_m * 64 + mi * 16 + gID;
                const __half* ah_ = As_h + r0 * SA + kk + tg * 2;
                const __half* al_ = As_l + r0 * SA + kk + tg * 2;
                uint32_t ah[4], al[4];
                ah[0] = *(const uint32_t*)ah_;
                ah[1] = *(const uint32_t*)(ah_ + 8 * SA);
                ah[2] = *(const uint32_t*)(ah_ + 8);
                ah[3] = *(const uint32_t*)(ah_ + 8 * SA + 8);
                al[0] = *(const uint32_t*)al_;
                al[1] = *(const uint32_t*)(al_ + 8 * SA);
                al[2] = *(const uint32_t*)(al_ + 8);
                al[3] = *(const uint32_t*)(al_ + 8 * SA + 8);
                #pragma unroll
                for (int ni = 0; ni < 4; ni++) {
                    mma16816(acc[mi][ni], ah, bf[ni]);
                    mma16816(acc[mi][ni], al, bf[ni]);
                }
            }
        }
        __syncthreads();
    }

    // epilogue: C = acc (+bias[c]) (+add[r,c])
    #pragma unroll
    for (int mi = 0; mi < 4; mi++) {
        #pragma unroll
        for (int ni = 0; ni < 4; ni++) {
            int r = arow0 + warp_m * 64 + mi * 16 + gID;
            int c = bcol0 + warp_n * 32 + ni * 8 + tg * 2;
            float b0 = bias ? bias[c] : 0.f;
            float b1 = bias ? bias[c + 1] : 0.f;
            float2 v0 = make_float2(acc[mi][ni][0] + b0, acc[mi][ni][1] + b1);
            float2 v1 = make_float2(acc[mi][ni][2] + b0, acc[mi][ni][3] + b1);
            if (add) {
                float2 a0 = *(const float2*)(add + (size_t)r * N + c);
                float2 a1 = *(const float2*)(add + (size_t)(r + 8) * N + c);
                v0.x += a0.x; v0.y += a0.y;
                v1.x += a1.x; v1.y += a1.y;
            }
            *(float2*)(C + (size_t)r * N + c) = v0;
            *(float2*)(C + (size_t)(r + 8) * N + c) = v1;
        }
    }
}

// ---------------- helpers ----------------------------------------------------
__device__ __forceinline__ float2 blockSum2(float a, float b, float* sh) {
    #pragma unroll
    for (int o = 16; o > 0; o >>= 1) {
        a += __shfl_down_sync(0xffffffffu, a, o);
        b += __shfl_down_sync(0xffffffffu, b, o);
    }
    int w = threadIdx.x >> 5, l = threadIdx.x & 31;
    if (l == 0) { sh[w] = a; sh[8 + w] = b; }
    __syncthreads();
    if (threadIdx.x == 0) {
        float sa = 0.f, sb2 = 0.f;
        #pragma unroll
        for (int i = 0; i < 8; i++) { sa += sh[i]; sb2 += sh[8 + i]; }
        sh[16] = sa; sh[17] = sb2;
    }
    __syncthreads();
    float2 r = make_float2(sh[16], sh[17]);
    __syncthreads();
    return r;
}
__device__ __forceinline__ float sigmoidf_(float x) { return 1.f / (1.f + expf(-x)); }
__device__ __forceinline__ void splith(float v, __half& hi, __half& lo) {
    hi = __float2half(v);
    lo = __float2half(v - __half2float(hi));
}

// ---------------- split / transpose kernels ----------------------------------
__global__ void k_split(const float* __restrict__ x, __half* __restrict__ hi,
                        __half* __restrict__ lo, int n)
{
    int i = blockIdx.x * blockDim.x + threadIdx.x;
    if (i >= n) return;
    splith(x[i], hi[i], lo[i]);
}

__global__ void k_w3t(const float* __restrict__ Wc, const float* __restrict__ Wh,
                      __half* __restrict__ w)
{
    int i = blockIdx.x * blockDim.x + threadIdx.x;   // [H7 x H3]
    if (i >= H7 * H3) return;
    int n = i / H3, k = i % H3;
    float v = (k < Hh) ? Wc[(size_t)k * H7 + n]
            : (k < 2 * Hh) ? Wh[(size_t)(k - Hh) * H7 + n]
            : Wc[(size_t)(k - Hh) * H7 + n];
    w[i] = __float2half(v);
}

__global__ void k_wt(const float* __restrict__ W, int K, int N,
                     __half* __restrict__ w)
{
    int i = blockIdx.x * blockDim.x + threadIdx.x;   // [N x K]
    if (i >= N * K) return;
    int n = i / K, k = i % K;
    w[i] = __float2half(W[(size_t)k * N + n]);
}

// ---------------- tiny GEMM for M=8 rows -------------------------------------
__global__ void k_smallgemm(int M, int N, int K,
                            const float* __restrict__ A, const float* __restrict__ W,
                            const float* __restrict__ bias, float* __restrict__ C)
{
    int idx = blockIdx.x * blockDim.x + threadIdx.x;
    if (idx >= M * N) return;
    int m = idx / N, n = idx % N;
    float acc = bias ? bias[n] : 0.f;
    const float* a = A + (size_t)m * K;
    for (int k = 0; k < K; k++) acc += a[k] * W[(size_t)k * N + n];
    C[idx] = acc;
}

// ---------------- small kernels ----------------------------------------------
__global__ void k_invms(const float* __restrict__ mask, float* __restrict__ invms)
{
    __shared__ float sh[8];
    int b = blockIdx.x, t = threadIdx.x;
    float a = 0.f;
    for (int s = t; s < Ss; s += 256) a += mask[b * Ss + s];
    #pragma unroll
    for (int o = 16; o > 0; o >>= 1) a += __shfl_down_sync(0xffffffffu, a, o);
    if ((t & 31) == 0) sh[t >> 5] = a;
    __syncthreads();
    if (t == 0) {
        float s2 = 0.f;
        #pragma unroll
        for (int i = 0; i < 8; i++) s2 += sh[i];
        invms[b] = 1.f / s2;
    }
}

__global__ void k_meanp(const float* __restrict__ x, const float* __restrict__ mask,
                        float* __restrict__ pnum)
{
    int ch = blockIdx.x, b = blockIdx.y, h = threadIdx.x;
    float acc = 0.f;
    int s0 = ch * SCH;
    #pragma unroll
    for (int i = 0; i < SCH; i++) {
        int s = s0 + i;
        acc += x[((size_t)(b * Ss + s)) * Hh + h] * mask[b * Ss + s];
    }
    pnum[(b * NCH + ch) * Hh + h] = acc;
}

__global__ void k_meanf(const float* __restrict__ pnum, const float* __restrict__ invms,
                        float* __restrict__ out)
{
    int b = blockIdx.x, h = threadIdx.x;
    float a = 0.f;
    #pragma unroll
    for (int c = 0; c < NCH; c++) a += pnum[(b * NCH + c) * Hh + h];
    out[b * Hh + h] = a * invms[b];
}

__global__ void k_igog(const float* __restrict__ pi, const float* __restrict__ pa,
                       const float* __restrict__ lns, const float* __restrict__ lnb,
                       float* __restrict__ ig, float* __restrict__ og)
{
    __shared__ float sh[18];
    int b = blockIdx.x, h = threadIdx.x;
    float v = pi[b * H3 + h] + pa[b * 2 * Hh + h];
    float2 ssum = blockSum2(v, v * v, sh);
    float m = ssum.x * (1.f / 256.f);
    float var = (ssum.y - 256.f * m * m) * (1.f / 255.f);
    float zn = lns[h] * (v - m) * rsqrtf(var + 1e-6f) + lnb[h];
    ig[b * Hh + h] = sigmoidf_(zn);
    v = pi[b * H3 + 2 * Hh + h] + pa[b * 2 * Hh + Hh + h];
    ssum = blockSum2(v, v * v, sh);
    m = ssum.x * (1.f / 256.f);
    var = (ssum.y - 256.f * m * m) * (1.f / 255.f);
    zn = lns[2 * Hh + h] * (v - m) * rsqrtf(var + 1e-6f) + lnb[2 * Hh + h];
    og[b * Hh + h] = sigmoidf_(zn);
}

// fused hg + gcp
__global__ __launch_bounds__(256) void k_hgcp(
    const float* __restrict__ ph, const float* __restrict__ pi,
    const float* __restrict__ mask,
    const float* __restrict__ lns, const float* __restrict__ lnb,
    const float* __restrict__ cell,
    float* __restrict__ pnum, float* __restrict__ pden)
{
    __shared__ float wsum[8][32];
    __shared__ float fin[32];
    int ch = blockIdx.x, b = blockIdx.y, h = threadIdx.x;
    int w = h >> 5, lane = h & 31;
    int s0 = ch * SCH;
    float piv = pi[b * H3 + Hh + h];
    float v[SCH];
    #pragma unroll
    for (int i = 0; i < SCH; i++)
        v[i] = ph[((size_t)(b * Ss + s0 + i)) * Hh + h] + piv;

    float p[2 * SCH];
    #pragma unroll
    for (int i = 0; i < SCH; i++) { p[2 * i] = v[i]; p[2 * i + 1] = v[i] * v[i]; }
    #pragma unroll
    for (int o = 16; o > 0; o >>= 1)
        #pragma unroll
        for (int j = 0; j < 2 * SCH; j++)
            p[j] += __shfl_down_sync(0xffffffffu, p[j], o);
    if (lane == 0)
        #pragma unroll
        for (int j = 0; j < 2 * SCH; j++) wsum[w][j] = p[j];
    __syncthreads();
    if (h < 2 * SCH) {
        float a = 0.f;
        #pragma unroll
        for (int i = 0; i < 8; i++) a += wsum[i][h];
        fin[h] = a;
    }
    __syncthreads();

    float lnsv = lns[Hh + h], lnbv = lnb[Hh + h];
    float num = 0.f, den = 0.f;
    #pragma unroll
    for (int i = 0; i < SCH; i++) {
        float m = fin[2 * i] * (1.f / 256.f);
        float var = (fin[2 * i + 1] - 256.f * m * m) * (1.f / 255.f);
        float zn = lnsv * (v[i] - m) * rsqrtf(var + 1e-6f) + lnbv;
        float mk = mask[b * Ss + s0 + i];
        float e = expf(sigmoidf_(zn) + (mk * 1e25f - 1e25f));
        size_t idx = ((size_t)(b * Ss + s0 + i)) * Hh + h;
        num += e * cell[idx];
        den += e;
    }
    pnum[(b * NCH + ch) * Hh + h] = num;
    pden[(b * NCH + ch) * Hh + h] = den;
}

__global__ void k_gcf(const float* __restrict__ pnum, const float* __restrict__ pden,
                      const float* __restrict__ ig, const float* __restrict__ og,
                      float* __restrict__ gc, float* __restrict__ gh)
{
    int b = blockIdx.x, h = threadIdx.x;
    float num = 0.f, den = 0.f;
    #pragma unroll
    for (int c = 0; c < NCH; c++) {
        num += pnum[(b * NCH + c) * Hh + h];
        den += pden[(b * NCH + c) * Hh + h];
    }
    float ei = expf(ig[b * Hh + h]);
    float g = (gc[b * Hh + h] * ei + num) / (ei + den);
    gc[b * Hh + h] = g;
    gh[b * Hh + h] = og[b * Hh + h] * tanhf(g);
}

// build split-fp16 ctx = [h_l, h, h_r] from split-fp16 hidden
__global__ void k_ctx_bf(const __half* __restrict__ hhi,
                         const __half* __restrict__ hlo,
                         __half* __restrict__ chi,
                         __half* __restrict__ clo)
{
    int i = blockIdx.x * blockDim.x + threadIdx.x;  // 8-elem chunk
    if (i >= BSR * (H3 / 8)) return;
    int bs = i / (H3 / 8);
    int j = (i % (H3 / 8)) * 8;
    int s = bs & (Ss - 1);
    uint4 vh = make_uint4(0, 0, 0, 0), vl = make_uint4(0, 0, 0, 0);
    long off = -1;
    if (j < Hh)           { if (s > 0)      off = ((long)bs - 1) * Hh + j; }
    else if (j < 2 * Hh)  {                 off = (long)bs * Hh + (j - Hh); }
    else                  { if (s < Ss - 1) off = ((long)bs + 1) * Hh + (j - 2 * Hh); }
    if (off >= 0) {
        vh = *(const uint4*)(hhi + off);
        vl = *(const uint4*)(hlo + off);
    }
    *(uint4*)(chi + (size_t)bs * H3 + j) = vh;
    *(uint4*)(clo + (size_t)bs * H3 + j) = vl;
}

// one-pass LN for all 7 groups; z already contains proj
__global__ __launch_bounds__(256) void k_update(
    const float* __restrict__ z,
    const float* __restrict__ gWg, const float* __restrict__ gc,
    const float* __restrict__ mask,
    const float* __restrict__ lns, const float* __restrict__ lnb,
    const float* __restrict__ c_old,
    float* __restrict__ h_new, float* __restrict__ c_new,
    __half* __restrict__ hhi, __half* __restrict__ hlo)
{
    __shared__ float wsum[8][14];
    __shared__ float fin[14];
    int bs = blockIdx.x; int b = bs >> 10; int s = bs & (Ss - 1);
    int h = threadIdx.x;
    int w = h >> 5, lane = h & 31;
    size_t rz = (size_t)bs * H7;
    float v[7];
    #pragma unroll
    for (int k = 0; k < 7; k++)
        v[k] = z[rz + k * Hh + h] + gWg[b * H7 + k * Hh + h];

    float p[14];
    #pragma unroll
    for (int k = 0; k < 7; k++) { p[2 * k] = v[k]; p[2 * k + 1] = v[k] * v[k]; }
    #pragma unroll
    for (int o = 16; o > 0; o >>= 1)
        #pragma unroll
        for (int j = 0; j < 14; j++)
            p[j] += __shfl_down_sync(0xffffffffu, p[j], o);
    if (lane == 0)
        #pragma unroll
        for (int j = 0; j < 14; j++) wsum[w][j] = p[j];
    __syncthreads();
    if (h < 14) {
        float a = 0.f;
        #pragma unroll
        for (int i = 0; i < 8; i++) a += wsum[i][h];
        fin[h] = a;
    }
    __syncthreads();

    float zn[7];
    #pragma unroll
    for (int k = 0; k < 7; k++) {
        float m = fin[2 * k] * (1.f / 256.f);
        float var = (fin[2 * k + 1] - 256.f * m * m) * (1.f / 255.f);
        zn[k] = lns[(3 + k) * Hh + h] * (v[k] - m) * rsqrtf(var + 1e-6f) + lnb[(3 + k) * Hh + h];
    }
    float e[6], den = 0.f;
    #pragma unroll
    for (int k = 0; k < 6; k++) {
        e[k] = expf(sigmoidf_(zn[k]));
        den += e[k];
    }
    float inv = 1.f / den;
    float mem = tanhf(zn[6]);
    size_t idx = (size_t)bs * Hh + h;
    float c  = c_old[idx];
    float cl = (s > 0)      ? c_old[idx - Hh] : 0.f;
    float cr = (s < Ss - 1) ? c_old[idx + Hh] : 0.f;
    float cn = (e[1] * cl + e[2] * cr + e[3] * c + e[0] * mem + e[4] * gc[b * Hh + h]) * inv;
    float mk = mask[bs];
    float hv = e[5] * inv * tanhf(cn) * mk;
    h_new[idx] = hv;
    c_new[idx] = cn * mk;
    splith(hv, hhi[idx], hlo[idx]);
}

// ---------------- orchestration ----------------------------------------------
extern "C" void kernel_launch(void* const* d_in, const int* in_sizes, int n_in,
                              void* d_out, int out_size)
{
    (void)in_sizes; (void)n_in; (void)out_size;
    const float* inputs = (const float*)d_in[0];
    const float* mask   = (const float*)d_in[1];
    const float* ih     = (const float*)d_in[2];
    const float* ic     = (const float*)d_in[3];
    const float* Wc     = (const float*)d_in[4];
    const float* Wh     = (const float*)d_in[5];
    const float* Wi     = (const float*)d_in[6];
    const float* bi     = (const float*)d_in[7];
    const float* Wg     = (const float*)d_in[8];
    const float* Gi     = (const float*)d_in[9];
    const float* gb     = (const float*)d_in[10];
    const float* Gh     = (const float*)d_in[11];
    const float* Ga     = (const float*)d_in[12];
    const float* lns    = (const float*)d_in[13];
    const float* lnb    = (const float*)d_in[14];
    float* out = (float*)d_out;

    float *hb0, *hb1, *cb0, *cb1, *proj, *zb, *ph;
    float *pi, *pa, *ig, *og, *gh, *gc, *havg, *gWg, *pnum, *pden, *invms;
    __half *chi, *clo, *hh0, *hl0, *hh1, *hl1, *inh, *inl;
    __half *w3, *ght, *wit;
    cudaGetSymbolAddress((void**)&hb0,  d_hbuf0);
    cudaGetSymbolAddress((void**)&hb1,  d_hbuf1);
    cudaGetSymbolAddress((void**)&cb0,  d_cbuf0);
    cudaGetSymbolAddress((void**)&cb1,  d_cbuf1);
    cudaGetSymbolAddress((void**)&proj, d_proj);
    cudaGetSymbolAddress((void**)&zb,   d_zbuf);
    cudaGetSymbolAddress((void**)&ph,   d_ph);
    cudaGetSymbolAddress((void**)&pi,   d_pi);
    cudaGetSymbolAddress((void**)&pa,   d_pa);
    cudaGetSymbolAddress((void**)&ig,   d_igb);
    cudaGetSymbolAddress((void**)&og,   d_ogb);
    cudaGetSymbolAddress((void**)&gh,   d_gh);
    cudaGetSymbolAddress((void**)&gc,   d_gcv);
    cudaGetSymbolAddress((void**)&havg, d_havg);
    cudaGetSymbolAddress((void**)&gWg,  d_gWg);
    cudaGetSymbolAddress((void**)&pnum, d_pnum);
    cudaGetSymbolAddress((void**)&pden, d_pden);
    cudaGetSymbolAddress((void**)&invms, d_invms);
    cudaGetSymbolAddress((void**)&chi, d_ctx_hi);
    cudaGetSymbolAddress((void**)&clo, d_ctx_lo);
    cudaGetSymbolAddress((void**)&hh0, d_h_hi0);
    cudaGetSymbolAddress((void**)&hl0, d_h_lo0);
    cudaGetSymbolAddress((void**)&hh1, d_h_hi1);
    cudaGetSymbolAddress((void**)&hl1, d_h_lo1);
    cudaGetSymbolAddress((void**)&inh, d_in_hi);
    cudaGetSymbolAddress((void**)&inl, d_in_lo);
    cudaGetSymbolAddress((void**)&w3,  d_W3T);
    cudaGetSymbolAddress((void**)&ght, d_GhT);
    cudaGetSymbolAddress((void**)&wit, d_WiT);

    cudaFuncSetAttribute(k_hmma, cudaFuncAttributeMaxDynamicSharedMemorySize, HSMEM);

    static cudaStream_t s2 = [] {
        cudaStream_t s; cudaStreamCreateWithFlags(&s, cudaStreamNonBlocking); return s;
    }();
    static cudaStream_t s3 = [] {
        cudaStream_t s; cudaStreamCreateWithFlags(&s, cudaStreamNonBlocking); return s;
    }();
    static cudaEvent_t evFork = [] {
        cudaEvent_t e; cudaEventCreateWithFlags(&e, cudaEventDisableTiming); return e;
    }();
    static cudaEvent_t evJoin = [] {
        cudaEvent_t e; cudaEventCreateWithFlags(&e, cudaEventDisableTiming); return e;
    }();
    static cudaEvent_t evPh = [] {
        cudaEvent_t e; cudaEventCreateWithFlags(&e, cudaEventDisableTiming); return e;
    }();

    // layer-invariant precompute (main stream)
    k_invms<<<Bb, 256>>>(mask, invms);
    k_meanp<<<dim3(NCH, Bb), 256>>>(ih, mask, pnum);
    k_meanf<<<Bb, 256>>>(pnum, invms, gh);
    k_meanp<<<dim3(NCH, Bb), 256>>>(ic, mask, pnum);
    k_meanf<<<Bb, 256>>>(pnum, invms, gc);
    k_w3t<<<(H7 * H3 + 255) / 256, 256>>>(Wc, Wh, w3);
    k_wt<<<(Hh * Hh + 255) / 256, 256>>>(Gh, Hh, Hh, ght);
    k_wt<<<(H7 * Hh + 255) / 256, 256>>>(Wi, Hh, H7, wit);
    k_split<<<(BSR * Hh + 255) / 256, 256>>>(ih, hh0, hl0, BSR * Hh);
    k_split<<<(BSR * Hh + 255) / 256, 256>>>(inputs, inh, inl, BSR * Hh);
    k_hmma<<<dim3(H7 / 128, BSR / 128), 256, HSMEM>>>(
        BSR, H7, Hh, inh, inl, wit, bi, (const float*)nullptr, proj);

    float* hbufs[2] = { hb0, hb1 };
    float* cbufs[2] = { cb0, cb1 };
    __half* hhis[2] = { hh0, hh1 };
    __half* hlos[2] = { hl0, hl1 };

    for (int l = 0; l < LL; l++) {
        const float* hid = (l == 0) ? ih : hbufs[l & 1];
        const float* cel = (l == 0) ? ic : cbufs[l & 1];
        const __half* hhi = hhis[l & 1];
        const __half* hlo = hlos[l & 1];
        float* hout = (l == LL - 1) ? out : hbufs[(l + 1) & 1];
        float* cout = cbufs[(l + 1) & 1];

        // fork: both GEMM branches depend only on hidden from prev update
        cudaEventRecord(evFork, 0);
        // s2: z-branch (ctx + z-GEMM, proj fused into epilogue)
        cudaStreamWaitEvent(s2, evFork, 0);
        k_ctx_bf<<<(BSR * (H3 / 8) + 255) / 256, 256, 0, s2>>>(hhi, hlo, chi, clo);
        k_hmma<<<dim3(H7 / 128, BSR / 128), 256, HSMEM, s2>>>(
            BSR, H7, H3, chi, clo, w3, (const float*)nullptr, proj, zb);
        cudaEventRecord(evJoin, s2);
        // s3: ph-branch (hidden @ Gh)
        cudaStreamWaitEvent(s3, evFork, 0);
        k_hmma<<<dim3(Hh / 128, BSR / 128), 256, HSMEM, s3>>>(
            BSR, Hh, Hh, hhi, hlo, ght,
            (const float*)nullptr, (const float*)nullptr, ph);
        cudaEventRecord(evPh, s3);

        // ---- global state chain (main stream, concurrent with both) ----
        k_meanp<<<dim3(NCH, Bb), 256>>>(hid, mask, pnum);
        k_meanf<<<Bb, 256>>>(pnum, invms, havg);
        k_smallgemm<<<(Bb * H3 + 255) / 256, 256>>>(Bb, H3, Hh, gh, Gi, gb, pi);
        k_smallgemm<<<(Bb * 2 * Hh + 255) / 256, 256>>>(Bb, 2 * Hh, Hh, havg, Ga,
                                                        (const float*)nullptr, pa);
        k_igog<<<Bb, 256>>>(pi, pa, lns, lnb, ig, og);
        cudaStreamWaitEvent(0, evPh, 0);
        k_hgcp<<<dim3(NCH, Bb), 256>>>(ph, pi, mask, lns, lnb, cel, pnum, pden);
        k_gcf<<<Bb, 256>>>(pnum, pden, ig, og, gc, gh);
        k_smallgemm<<<(Bb * H7 + 255) / 256, 256>>>(Bb, H7, Hh, gh, Wg,
                                                    (const float*)nullptr, gWg);

        // join: update needs z (s2) + gWg/gc (main)
        cudaStreamWaitEvent(0, evJoin, 0);
        k_update<<<BSR, 256>>>(zb, gWg, gc, mask, lns, lnb, cel, hout, cout,
                               hhis[(l + 1) & 1], hlos[(l + 1) & 1]);
    }
}